// round 1
// baseline (speedup 1.0000x reference)
#include <cuda_runtime.h>
#include <cuda_bf16.h>
#include <math.h>

// ---------------- problem constants ----------------
#define DIM     384
#define HEADS   6
#define HDIM    64
#define POINTS  4
#define LEVELS  3
#define HID     96
#define BB      2
#define NMID    1728              // 12^3
#define NTOK    15768             // 73*NMID/8
#define NHIGH   13824             // 8*NMID  (level0 = 24^3)
#define NMIDEND 15552             // NHIGH + NMID
#define MROWS   (BB*NTOK)         // 31536

// ---------------- scratch (device globals; no allocation allowed) ----------------
__device__ float g_qn  [(size_t)MROWS*DIM];
__device__ float g_aq  [(size_t)MROWS*DIM];   // reused later as ffn-LN output
__device__ float g_af  [(size_t)MROWS*DIM];
__device__ float g_val [(size_t)MROWS*DIM];
__device__ float g_off [(size_t)MROWS*216];
__device__ float g_awl [(size_t)MROWS*72];
__device__ float g_dout[(size_t)MROWS*DIM];
__device__ float g_out1[(size_t)MROWS*DIM];
__device__ float g_x   [(size_t)MROWS*HID];
__device__ float g_xg  [(size_t)MROWS*HID];

// ---------------- helpers ----------------
__device__ __forceinline__ float2 block_sum2(float a, float b) {
    // 128 threads = 4 warps
    __shared__ float sa[4], sb[4];
    int lane = threadIdx.x & 31, w = threadIdx.x >> 5;
    #pragma unroll
    for (int o = 16; o > 0; o >>= 1) {
        a += __shfl_down_sync(0xffffffffu, a, o);
        b += __shfl_down_sync(0xffffffffu, b, o);
    }
    if (lane == 0) { sa[w] = a; sb[w] = b; }
    __syncthreads();
    float ra = sa[0] + sa[1] + sa[2] + sa[3];
    float rb = sb[0] + sb[1] + sb[2] + sb[3];
    __syncthreads();
    return make_float2(ra, rb);
}

// ---------------- K1: build q (+feat) and the fused LN chain ----------------
// qn = LN(q,qnorm); aq = LN(qn,ext_qnorm); af = LN(LN(q,fnorm),ext_fnorm)
__global__ void prep_kernel(const float* __restrict__ query, const float* __restrict__ feat,
                            const float* __restrict__ qw, const float* __restrict__ qb,
                            const float* __restrict__ fw, const float* __restrict__ fb,
                            const float* __restrict__ eqw, const float* __restrict__ eqb,
                            const float* __restrict__ efw, const float* __restrict__ efb,
                            float* __restrict__ qn_o, float* __restrict__ aq_o,
                            float* __restrict__ af_o)
{
    int row = blockIdx.x;                 // 0..MROWS-1
    int b = row / NTOK, t = row % NTOK;
    int tid = threadIdx.x;                // 128
    float x[3];
    float s = 0.f, ss = 0.f;
    #pragma unroll
    for (int i = 0; i < 3; i++) {
        int c = tid + i * 128;
        float v = query[(size_t)row * DIM + c];
        if (t >= NHIGH && t < NMIDEND)
            v += feat[((size_t)b * NMID + (t - NHIGH)) * DIM + c];
        x[i] = v; s += v; ss += v * v;
    }
    float2 r = block_sum2(s, ss);
    float m  = r.x * (1.f / DIM);
    float rs = rsqrtf(r.y * (1.f / DIM) - m * m + 1e-6f);

    float qv[3], fv[3];
    float s1 = 0.f, ss1 = 0.f, s2 = 0.f, ss2 = 0.f;
    #pragma unroll
    for (int i = 0; i < 3; i++) {
        int c = tid + i * 128;
        float xn = (x[i] - m) * rs;
        qv[i] = xn * qw[c] + qb[c];
        fv[i] = xn * fw[c] + fb[c];
        qn_o[(size_t)row * DIM + c] = qv[i];
        s1 += qv[i]; ss1 += qv[i] * qv[i];
        s2 += fv[i]; ss2 += fv[i] * fv[i];
    }
    float2 r1 = block_sum2(s1, ss1);
    float m1  = r1.x * (1.f / DIM);
    float rs1 = rsqrtf(r1.y * (1.f / DIM) - m1 * m1 + 1e-6f);
    float2 r2 = block_sum2(s2, ss2);
    float m2  = r2.x * (1.f / DIM);
    float rs2 = rsqrtf(r2.y * (1.f / DIM) - m2 * m2 + 1e-6f);
    #pragma unroll
    for (int i = 0; i < 3; i++) {
        int c = tid + i * 128;
        aq_o[(size_t)row * DIM + c] = (qv[i] - m1) * rs1 * eqw[c] + eqb[c];
        af_o[(size_t)row * DIM + c] = (fv[i] - m2) * rs2 * efw[c] + efb[c];
    }
}

// ---------------- generic LN ----------------
__global__ void ln_kernel(const float* __restrict__ xin, const float* __restrict__ w,
                          const float* __restrict__ bws, float* __restrict__ yo)
{
    int row = blockIdx.x;
    int tid = threadIdx.x;                // 128
    float x[3]; float s = 0.f, ss = 0.f;
    #pragma unroll
    for (int i = 0; i < 3; i++) {
        int c = tid + i * 128;
        x[i] = xin[(size_t)row * DIM + c];
        s += x[i]; ss += x[i] * x[i];
    }
    float2 r = block_sum2(s, ss);
    float m  = r.x * (1.f / DIM);
    float rs = rsqrtf(r.y * (1.f / DIM) - m * m + 1e-6f);
    #pragma unroll
    for (int i = 0; i < 3; i++) {
        int c = tid + i * 128;
        yo[(size_t)row * DIM + c] = (x[i] - m) * rs * w[c] + bws[c];
    }
}

// ---------------- tiled fp32 GEMM: C = A[M,K] @ W[K,N] + bias (+resid) ----------------
template<bool RESID>
__global__ void gemm_kernel(const float* __restrict__ A, const float* __restrict__ W,
                            const float* __restrict__ bias, const float* __restrict__ resid,
                            float* __restrict__ C, int M, int N, int K)
{
    constexpr int BM = 128, BN = 64, BK = 16, TM = 8, TN = 4;
    __shared__ float As[BK][BM];
    __shared__ float Bs[BK][BN];
    int tid = threadIdx.x;        // 256
    int tx = tid & 15;            // N dir (16 * TN = 64)
    int ty = tid >> 4;            // M dir (16 * TM = 128)
    int row0 = blockIdx.y * BM;
    int col0 = blockIdx.x * BN;
    float acc[TM][TN] = {};
    for (int k0 = 0; k0 < K; k0 += BK) {
        #pragma unroll
        for (int i = 0; i < 8; i++) {
            int idx = tid + i * 256;
            int m = idx >> 4, k = idx & 15;
            int gr = row0 + m;
            As[k][m] = (gr < M) ? A[(size_t)gr * K + (k0 + k)] : 0.f;
        }
        #pragma unroll
        for (int i = 0; i < 4; i++) {
            int idx = tid + i * 256;
            int k = idx >> 6, n = idx & 63;
            int gn = col0 + n;
            Bs[k][n] = (gn < N) ? W[(size_t)(k0 + k) * N + gn] : 0.f;
        }
        __syncthreads();
        #pragma unroll
        for (int k = 0; k < BK; k++) {
            float a[TM], bv[TN];
            #pragma unroll
            for (int i = 0; i < TM; i++) a[i] = As[k][ty * TM + i];
            #pragma unroll
            for (int j = 0; j < TN; j++) bv[j] = Bs[k][tx * TN + j];
            #pragma unroll
            for (int i = 0; i < TM; i++)
                #pragma unroll
                for (int j = 0; j < TN; j++)
                    acc[i][j] += a[i] * bv[j];
        }
        __syncthreads();
    }
    #pragma unroll
    for (int i = 0; i < TM; i++) {
        int r = row0 + ty * TM + i;
        if (r >= M) continue;
        #pragma unroll
        for (int j = 0; j < TN; j++) {
            int c = col0 + tx * TN + j;
            if (c >= N) continue;
            float v = acc[i][j] + bias[c];
            if (RESID) v += resid[(size_t)r * N + c];
            C[(size_t)r * N + c] = v;
        }
    }
}

// ---------------- deformable sampling (softmax fused) ----------------
// one warp per (b, q, h); lanes cover 64 head-dims (2 each)
__global__ void deform_kernel(const float* __restrict__ off, const float* __restrict__ awl,
                              const float* __restrict__ value, float* __restrict__ out)
{
    int gw   = (blockIdx.x * blockDim.x + threadIdx.x) >> 5;
    int lane = threadIdx.x & 31;
    if (gw >= MROWS * HEADS) return;
    int h  = gw % HEADS;
    int bq = gw / HEADS;              // b*NTOK + q
    int q  = bq % NTOK;
    int b  = bq / NTOK;

    // reference point from the query token's own level grid (order d,x,y)
    float rd, rx, ry;
    {
        int S, loc;
        if (q < NHIGH)        { S = 24; loc = q; }
        else if (q < NMIDEND) { S = 12; loc = q - NHIGH; }
        else                  { S = 6;  loc = q - NMIDEND; }
        int d = loc / (S * S), y = (loc / S) % S, x = loc % S;
        float inv = 1.f / (float)S;
        rd = (d + 0.5f) * inv; ry = (y + 0.5f) * inv; rx = (x + 0.5f) * inv;
    }

    // softmax over the 12 (level,point) logits for this head
    float aw[12];
    {
        const float* ap = awl + (size_t)bq * 72 + h * 12;
        float mx = -1e30f;
        #pragma unroll
        for (int j = 0; j < 12; j++) { aw[j] = ap[j]; mx = fmaxf(mx, aw[j]); }
        float se = 0.f;
        #pragma unroll
        for (int j = 0; j < 12; j++) { aw[j] = expf(aw[j] - mx); se += aw[j]; }
        float inv = 1.f / se;
        #pragma unroll
        for (int j = 0; j < 12; j++) aw[j] *= inv;
    }

    const int   Ls[3] = {24, 12, 6};
    const int   St[3] = {0, NHIGH, NMIDEND};
    const float* offp = off + (size_t)bq * 216 + h * 36;
    const float* vb   = value + (size_t)b * NTOK * DIM + h * HDIM + lane;

    float acc0 = 0.f, acc1 = 0.f;
    #pragma unroll
    for (int l = 0; l < 3; l++) {
        int S = Ls[l], st = St[l];
        #pragma unroll
        for (int p = 0; p < 4; p++) {
            const float* o = offp + (l * 4 + p) * 3;
            // loc = ref + off/(S,S,S); pixel = loc*S - 0.5 = ref*S + off - 0.5
            float pd = rd * S + o[0] - 0.5f;
            float px = rx * S + o[1] - 0.5f;
            float py = ry * S + o[2] - 0.5f;
            float fd = floorf(pd), fx = floorf(px), fy = floorf(py);
            int d0 = (int)fd, x0 = (int)fx, y0 = (int)fy;
            float wd = pd - fd, wx = px - fx, wy = py - fy;
            float a = aw[l * 4 + p];
            #pragma unroll
            for (int dd = 0; dd < 2; dd++) {
                int di = d0 + dd;
                if (di < 0 || di >= S) continue;
                float w_d = a * (dd ? wd : 1.f - wd);
                #pragma unroll
                for (int dy = 0; dy < 2; dy++) {
                    int yi = y0 + dy;
                    if (yi < 0 || yi >= S) continue;
                    float w_dy = w_d * (dy ? wy : 1.f - wy);
                    #pragma unroll
                    for (int dx = 0; dx < 2; dx++) {
                        int xi = x0 + dx;
                        if (xi < 0 || xi >= S) continue;
                        float w = w_dy * (dx ? wx : 1.f - wx);
                        size_t idx = (size_t)st + ((size_t)di * S + yi) * S + xi;
                        const float* vp = vb + idx * DIM;
                        acc0 += w * vp[0];
                        acc1 += w * vp[32];
                    }
                }
            }
        }
    }
    float* op = out + (size_t)bq * DIM + h * HDIM + lane;
    op[0]  = acc0;
    op[32] = acc1;
}

// ---------------- depthwise 3x3x3 conv per pyramid segment + exact GELU ----------------
__global__ void dwconv_gelu_kernel(const float* __restrict__ x, const float* __restrict__ w,
                                   const float* __restrict__ bias, float* __restrict__ y)
{
    int v = blockIdx.x % NTOK;
    int b = blockIdx.x / NTOK;
    int c = threadIdx.x;              // 96
    __shared__ float sw[27 * HID];
    for (int i = c; i < 27 * HID; i += HID) sw[i] = w[i];
    __syncthreads();

    int S, base;
    if (v < NHIGH)        { S = 24; base = 0; }
    else if (v < NMIDEND) { S = 12; base = NHIGH; }
    else                  { S = 6;  base = NMIDEND; }
    int loc = v - base;
    int d = loc / (S * S), yy = (loc / S) % S, xx = loc % S;

    const float* xb = x + ((size_t)b * NTOK + base) * HID;
    float acc = bias[c];
    #pragma unroll
    for (int kd = 0; kd < 3; kd++) {
        int di = d + kd - 1;
        if (di < 0 || di >= S) continue;
        #pragma unroll
        for (int kh = 0; kh < 3; kh++) {
            int yi = yy + kh - 1;
            if (yi < 0 || yi >= S) continue;
            #pragma unroll
            for (int kw = 0; kw < 3; kw++) {
                int xi = xx + kw - 1;
                if (xi < 0 || xi >= S) continue;
                acc += sw[((kd * 3 + kh) * 3 + kw) * HID + c] *
                       xb[((size_t)(di * S + yi) * S + xi) * HID + c];
            }
        }
    }
    float g = 0.5f * acc * (1.f + erff(acc * 0.70710678118654752f));
    y[((size_t)b * NTOK + v) * HID + c] = g;
}

// ---------------- launch ----------------
static float* sym_addr(const void* sym) {
    void* p = nullptr;
    cudaGetSymbolAddress(&p, sym);
    return (float*)p;
}

extern "C" void kernel_launch(void* const* d_in, const int* in_sizes, int n_in,
                              void* d_out, int out_size)
{
    const float* query = (const float*)d_in[0];
    const float* feat  = (const float*)d_in[2];
    // 24 weight arrays are the LAST 24 inputs (robust to whether D/H/W scalars appear)
    int wb = n_in - 24;
    const float* qnorm_w    = (const float*)d_in[wb + 0];
    const float* qnorm_b    = (const float*)d_in[wb + 1];
    const float* fnorm_w    = (const float*)d_in[wb + 2];
    const float* fnorm_b    = (const float*)d_in[wb + 3];
    const float* ext_qnorm_w= (const float*)d_in[wb + 4];
    const float* ext_qnorm_b= (const float*)d_in[wb + 5];
    const float* ext_fnorm_w= (const float*)d_in[wb + 6];
    const float* ext_fnorm_b= (const float*)d_in[wb + 7];
    const float* ffn_norm_w = (const float*)d_in[wb + 8];
    const float* ffn_norm_b = (const float*)d_in[wb + 9];
    const float* off_w      = (const float*)d_in[wb + 10];
    const float* off_b      = (const float*)d_in[wb + 11];
    const float* aw_w       = (const float*)d_in[wb + 12];
    const float* aw_b       = (const float*)d_in[wb + 13];
    const float* val_w      = (const float*)d_in[wb + 14];
    const float* val_b      = (const float*)d_in[wb + 15];
    const float* out_w      = (const float*)d_in[wb + 16];
    const float* out_b      = (const float*)d_in[wb + 17];
    const float* fc1_w      = (const float*)d_in[wb + 18];
    const float* fc1_b      = (const float*)d_in[wb + 19];
    const float* dw_w       = (const float*)d_in[wb + 20];
    const float* dw_b       = (const float*)d_in[wb + 21];
    const float* fc2_w      = (const float*)d_in[wb + 22];
    const float* fc2_b      = (const float*)d_in[wb + 23];

    float* qn   = sym_addr(g_qn);
    float* aq   = sym_addr(g_aq);
    float* af   = sym_addr(g_af);
    float* val  = sym_addr(g_val);
    float* off  = sym_addr(g_off);
    float* awl  = sym_addr(g_awl);
    float* dout = sym_addr(g_dout);
    float* out1 = sym_addr(g_out1);
    float* xf   = sym_addr(g_x);
    float* xg   = sym_addr(g_xg);
    float* outp = (float*)d_out;

    const int M = MROWS;
    dim3 gemm_blk(256);
    int gy = (M + 127) / 128;

    // 1) q build + LN chain
    prep_kernel<<<M, 128>>>(query, feat, qnorm_w, qnorm_b, fnorm_w, fnorm_b,
                            ext_qnorm_w, ext_qnorm_b, ext_fnorm_w, ext_fnorm_b,
                            qn, aq, af);
    // 2) value = af @ val_w + val_b
    gemm_kernel<false><<<dim3(6, gy), gemm_blk>>>(af, val_w, val_b, nullptr, val, M, 384, 384);
    // 3) offsets = aq @ off_w + off_b
    gemm_kernel<false><<<dim3(4, gy), gemm_blk>>>(aq, off_w, off_b, nullptr, off, M, 216, 384);
    // 4) attention logits = aq @ aw_w + aw_b
    gemm_kernel<false><<<dim3(2, gy), gemm_blk>>>(aq, aw_w, aw_b, nullptr, awl, M, 72, 384);
    // 5) deformable sampling (softmax fused)
    {
        int warps = MROWS * HEADS;
        int blocks = (warps + 7) / 8;
        deform_kernel<<<blocks, 256>>>(off, awl, val, dout);
    }
    // 6) out1 = qn + dout @ out_w + out_b
    gemm_kernel<true><<<dim3(6, gy), gemm_blk>>>(dout, out_w, out_b, qn, out1, M, 384, 384);
    // 7) t = LN(out1, ffn_norm)   (reuse aq buffer)
    ln_kernel<<<M, 128>>>(out1, ffn_norm_w, ffn_norm_b, aq);
    // 8) x = t @ fc1_w + fc1_b
    gemm_kernel<false><<<dim3(2, gy), gemm_blk>>>(aq, fc1_w, fc1_b, nullptr, xf, M, 96, 384);
    // 9) depthwise conv per segment + GELU
    dwconv_gelu_kernel<<<MROWS, HID>>>(xf, dw_w, dw_b, xg);
    // 10) out = out1 + xg @ fc2_w + fc2_b
    gemm_kernel<true><<<dim3(6, gy), gemm_blk>>>(xg, fc2_w, fc2_b, out1, outp, M, 384, 96);
}

// round 2
// speedup vs baseline: 1.3132x; 1.3132x over previous
#include <cuda_runtime.h>
#include <cuda_bf16.h>
#include <mma.h>
#include <math.h>

using namespace nvcuda;

// ---------------- problem constants ----------------
#define DIM     384
#define HEADS   6
#define HDIM    64
#define POINTS  4
#define LEVELS  3
#define HID     96
#define BB      2
#define NMID    1728              // 12^3
#define NTOK    15768             // 73*NMID/8
#define NHIGH   13824             // 8*NMID  (level0 = 24^3)
#define NMIDEND 15552             // NHIGH + NMID
#define MROWS   (BB*NTOK)         // 31536

// ---------------- scratch (device globals; no allocation allowed) ----------------
__device__ float g_qn  [(size_t)MROWS*DIM];
__device__ float g_aq  [(size_t)MROWS*DIM];   // reused later as ffn-LN output
__device__ float g_af  [(size_t)MROWS*DIM];
__device__ float g_val [(size_t)MROWS*DIM];
__device__ float g_off [(size_t)MROWS*216];
__device__ float g_awl [(size_t)MROWS*72];
__device__ float g_dout[(size_t)MROWS*DIM];
__device__ float g_out1[(size_t)MROWS*DIM];
__device__ float g_x   [(size_t)MROWS*HID];
__device__ float g_xg  [(size_t)MROWS*HID];

// ---------------- helpers ----------------
__device__ __forceinline__ float2 block_sum2(float a, float b) {
    __shared__ float sa[4], sb[4];
    int lane = threadIdx.x & 31, w = threadIdx.x >> 5;
    #pragma unroll
    for (int o = 16; o > 0; o >>= 1) {
        a += __shfl_down_sync(0xffffffffu, a, o);
        b += __shfl_down_sync(0xffffffffu, b, o);
    }
    if (lane == 0) { sa[w] = a; sb[w] = b; }
    __syncthreads();
    float ra = sa[0] + sa[1] + sa[2] + sa[3];
    float rb = sb[0] + sb[1] + sb[2] + sb[3];
    __syncthreads();
    return make_float2(ra, rb);
}

// ---------------- K1: build q (+feat) and the fused LN chain ----------------
__global__ void prep_kernel(const float* __restrict__ query, const float* __restrict__ feat,
                            const float* __restrict__ qw, const float* __restrict__ qb,
                            const float* __restrict__ fw, const float* __restrict__ fb,
                            const float* __restrict__ eqw, const float* __restrict__ eqb,
                            const float* __restrict__ efw, const float* __restrict__ efb,
                            float* __restrict__ qn_o, float* __restrict__ aq_o,
                            float* __restrict__ af_o)
{
    int row = blockIdx.x;
    int b = row / NTOK, t = row % NTOK;
    int tid = threadIdx.x;                // 128
    float x[3];
    float s = 0.f, ss = 0.f;
    #pragma unroll
    for (int i = 0; i < 3; i++) {
        int c = tid + i * 128;
        float v = query[(size_t)row * DIM + c];
        if (t >= NHIGH && t < NMIDEND)
            v += feat[((size_t)b * NMID + (t - NHIGH)) * DIM + c];
        x[i] = v; s += v; ss += v * v;
    }
    float2 r = block_sum2(s, ss);
    float m  = r.x * (1.f / DIM);
    float rs = rsqrtf(r.y * (1.f / DIM) - m * m + 1e-6f);

    float qv[3], fv[3];
    float s1 = 0.f, ss1 = 0.f, s2 = 0.f, ss2 = 0.f;
    #pragma unroll
    for (int i = 0; i < 3; i++) {
        int c = tid + i * 128;
        float xn = (x[i] - m) * rs;
        qv[i] = xn * qw[c] + qb[c];
        fv[i] = xn * fw[c] + fb[c];
        qn_o[(size_t)row * DIM + c] = qv[i];
        s1 += qv[i]; ss1 += qv[i] * qv[i];
        s2 += fv[i]; ss2 += fv[i] * fv[i];
    }
    float2 r1 = block_sum2(s1, ss1);
    float m1  = r1.x * (1.f / DIM);
    float rs1 = rsqrtf(r1.y * (1.f / DIM) - m1 * m1 + 1e-6f);
    float2 r2 = block_sum2(s2, ss2);
    float m2  = r2.x * (1.f / DIM);
    float rs2 = rsqrtf(r2.y * (1.f / DIM) - m2 * m2 + 1e-6f);
    #pragma unroll
    for (int i = 0; i < 3; i++) {
        int c = tid + i * 128;
        aq_o[(size_t)row * DIM + c] = (qv[i] - m1) * rs1 * eqw[c] + eqb[c];
        af_o[(size_t)row * DIM + c] = (fv[i] - m2) * rs2 * efw[c] + efb[c];
    }
}

// ---------------- generic LN ----------------
__global__ void ln_kernel(const float* __restrict__ xin, const float* __restrict__ w,
                          const float* __restrict__ bws, float* __restrict__ yo)
{
    int row = blockIdx.x;
    int tid = threadIdx.x;                // 128
    float x[3]; float s = 0.f, ss = 0.f;
    #pragma unroll
    for (int i = 0; i < 3; i++) {
        int c = tid + i * 128;
        x[i] = xin[(size_t)row * DIM + c];
        s += x[i]; ss += x[i] * x[i];
    }
    float2 r = block_sum2(s, ss);
    float m  = r.x * (1.f / DIM);
    float rs = rsqrtf(r.y * (1.f / DIM) - m * m + 1e-6f);
    #pragma unroll
    for (int i = 0; i < 3; i++) {
        int c = tid + i * 128;
        yo[(size_t)row * DIM + c] = (x[i] - m) * rs * w[c] + bws[c];
    }
}

// ---------------- tf32 tensor-core GEMM: C = A[M,K] @ W[K,N] + bias (+resid) ----
// block: 256 threads = 8 warps (4 M x 2 N), tile 128x64, BK=16
template<bool RESID>
__global__ void gemm_tf32_kernel(const float* __restrict__ A, const float* __restrict__ W,
                                 const float* __restrict__ bias, const float* __restrict__ resid,
                                 float* __restrict__ C, int M, int N, int K)
{
    constexpr int BM = 128, BN = 64, BK = 16;
    constexpr int AP = 24;   // A tile row pitch (floats), 96B = 6*16B
    constexpr int BP = 72;   // B tile row pitch, 288B
    constexpr int CP = 72;   // C staging pitch
    __shared__ __align__(16) float smem[BM * CP];   // 36 KB; reused for A|B then C
    float* As = smem;                // [BM][AP]  (3072 floats)
    float* Bs = smem + BM * AP;      // [BK][BP]  (1152 floats)
    float* Cs = smem;                // [BM][CP]

    int tid = threadIdx.x;
    int wid = tid >> 5;
    int wm = wid & 3;        // warp row  (4 x 32 rows)
    int wn = wid >> 2;       // warp col  (2 x 32 cols)
    int row0 = blockIdx.y * BM;
    int col0 = blockIdx.x * BN;

    wmma::fragment<wmma::accumulator, 16, 16, 8, float> acc[2][2];
    #pragma unroll
    for (int i = 0; i < 2; i++)
        #pragma unroll
        for (int j = 0; j < 2; j++)
            wmma::fill_fragment(acc[i][j], 0.f);

    for (int k0 = 0; k0 < K; k0 += BK) {
        // A tile: 128x16, float4 x2 per thread
        #pragma unroll
        for (int i = 0; i < 2; i++) {
            int idx = tid + i * 256;          // 0..511
            int m = idx >> 2, kq = (idx & 3) * 4;
            int gr = row0 + m;
            float4 v = make_float4(0.f, 0.f, 0.f, 0.f);
            if (gr < M) v = *(const float4*)&A[(size_t)gr * K + k0 + kq];
            float* dst = &As[m * AP + kq];
            dst[0] = v.x; dst[1] = v.y; dst[2] = v.z; dst[3] = v.w;
        }
        // B tile: 16x64, scalar x4 per thread
        #pragma unroll
        for (int i = 0; i < 4; i++) {
            int idx = tid + i * 256;          // 0..1023
            int kk = idx >> 6, n = idx & 63;
            int gn = col0 + n;
            Bs[kk * BP + n] = (gn < N) ? W[(size_t)(k0 + kk) * N + gn] : 0.f;
        }
        __syncthreads();
        #pragma unroll
        for (int ks = 0; ks < 2; ks++) {
            wmma::fragment<wmma::matrix_a, 16, 16, 8, wmma::precision::tf32, wmma::row_major> fa[2];
            wmma::fragment<wmma::matrix_b, 16, 16, 8, wmma::precision::tf32, wmma::row_major> fb[2];
            #pragma unroll
            for (int i = 0; i < 2; i++) {
                wmma::load_matrix_sync(fa[i], &As[(wm * 32 + i * 16) * AP + ks * 8], AP);
                #pragma unroll
                for (int t = 0; t < fa[i].num_elements; t++)
                    fa[i].x[t] = wmma::__float_to_tf32(fa[i].x[t]);
            }
            #pragma unroll
            for (int j = 0; j < 2; j++) {
                wmma::load_matrix_sync(fb[j], &Bs[(ks * 8) * BP + wn * 32 + j * 16], BP);
                #pragma unroll
                for (int t = 0; t < fb[j].num_elements; t++)
                    fb[j].x[t] = wmma::__float_to_tf32(fb[j].x[t]);
            }
            #pragma unroll
            for (int i = 0; i < 2; i++)
                #pragma unroll
                for (int j = 0; j < 2; j++)
                    wmma::mma_sync(acc[i][j], fa[i], fb[j], acc[i][j]);
        }
        __syncthreads();
    }

    // stage C in shared, then bias/resid epilogue
    #pragma unroll
    for (int i = 0; i < 2; i++)
        #pragma unroll
        for (int j = 0; j < 2; j++)
            wmma::store_matrix_sync(&Cs[(wm * 32 + i * 16) * CP + wn * 32 + j * 16],
                                    acc[i][j], CP, wmma::mem_row_major);
    __syncthreads();
    #pragma unroll
    for (int it = 0; it < (BM * BN) / 256; it++) {
        int idx = tid + it * 256;
        int r = idx >> 6, c = idx & 63;
        int gr = row0 + r, gc = col0 + c;
        if (gr < M && gc < N) {
            float v = Cs[r * CP + c] + bias[gc];
            if (RESID) v += resid[(size_t)gr * N + gc];
            C[(size_t)gr * N + gc] = v;
        }
    }
}

// ---------------- deformable sampling (softmax fused) ----------------
__global__ void deform_kernel(const float* __restrict__ off, const float* __restrict__ awl,
                              const float* __restrict__ value, float* __restrict__ out)
{
    int gw   = (blockIdx.x * blockDim.x + threadIdx.x) >> 5;
    int lane = threadIdx.x & 31;
    if (gw >= MROWS * HEADS) return;
    int h  = gw % HEADS;
    int bq = gw / HEADS;              // b*NTOK + q
    int q  = bq % NTOK;
    int b  = bq / NTOK;

    float rd, rx, ry;
    {
        int S, loc;
        if (q < NHIGH)        { S = 24; loc = q; }
        else if (q < NMIDEND) { S = 12; loc = q - NHIGH; }
        else                  { S = 6;  loc = q - NMIDEND; }
        int d = loc / (S * S), y = (loc / S) % S, x = loc % S;
        float inv = 1.f / (float)S;
        rd = (d + 0.5f) * inv; ry = (y + 0.5f) * inv; rx = (x + 0.5f) * inv;
    }

    float aw[12];
    {
        const float* ap = awl + (size_t)bq * 72 + h * 12;
        float mx = -1e30f;
        #pragma unroll
        for (int j = 0; j < 12; j++) { aw[j] = ap[j]; mx = fmaxf(mx, aw[j]); }
        float se = 0.f;
        #pragma unroll
        for (int j = 0; j < 12; j++) { aw[j] = expf(aw[j] - mx); se += aw[j]; }
        float inv = 1.f / se;
        #pragma unroll
        for (int j = 0; j < 12; j++) aw[j] *= inv;
    }

    const int   Ls[3] = {24, 12, 6};
    const int   St[3] = {0, NHIGH, NMIDEND};
    const float* offp = off + (size_t)bq * 216 + h * 36;
    const float* vb   = value + (size_t)b * NTOK * DIM + h * HDIM + lane;

    float acc0 = 0.f, acc1 = 0.f;
    #pragma unroll
    for (int l = 0; l < 3; l++) {
        int S = Ls[l], st = St[l];
        #pragma unroll
        for (int p = 0; p < 4; p++) {
            const float* o = offp + (l * 4 + p) * 3;
            float pd = rd * S + o[0] - 0.5f;
            float px = rx * S + o[1] - 0.5f;
            float py = ry * S + o[2] - 0.5f;
            float fd = floorf(pd), fx = floorf(px), fy = floorf(py);
            int d0 = (int)fd, x0 = (int)fx, y0 = (int)fy;
            float wd = pd - fd, wx = px - fx, wy = py - fy;
            float a = aw[l * 4 + p];
            #pragma unroll
            for (int dd = 0; dd < 2; dd++) {
                int di = d0 + dd;
                if (di < 0 || di >= S) continue;
                float w_d = a * (dd ? wd : 1.f - wd);
                #pragma unroll
                for (int dy = 0; dy < 2; dy++) {
                    int yi = y0 + dy;
                    if (yi < 0 || yi >= S) continue;
                    float w_dy = w_d * (dy ? wy : 1.f - wy);
                    #pragma unroll
                    for (int dx = 0; dx < 2; dx++) {
                        int xi = x0 + dx;
                        if (xi < 0 || xi >= S) continue;
                        float w = w_dy * (dx ? wx : 1.f - wx);
                        size_t idx = (size_t)st + ((size_t)di * S + yi) * S + xi;
                        const float* vp = vb + idx * DIM;
                        acc0 += w * vp[0];
                        acc1 += w * vp[32];
                    }
                }
            }
        }
    }
    float* op = out + (size_t)bq * DIM + h * HDIM + lane;
    op[0]  = acc0;
    op[32] = acc1;
}

// ---------------- depthwise 3x3x3 conv per pyramid segment + exact GELU ----------------
__global__ void dwconv_gelu_kernel(const float* __restrict__ x, const float* __restrict__ w,
                                   const float* __restrict__ bias, float* __restrict__ y)
{
    int v = blockIdx.x % NTOK;
    int b = blockIdx.x / NTOK;
    int c = threadIdx.x;              // 96
    __shared__ float sw[27 * HID];
    for (int i = c; i < 27 * HID; i += HID) sw[i] = w[i];
    __syncthreads();

    int S, base;
    if (v < NHIGH)        { S = 24; base = 0; }
    else if (v < NMIDEND) { S = 12; base = NHIGH; }
    else                  { S = 6;  base = NMIDEND; }
    int loc = v - base;
    int d = loc / (S * S), yy = (loc / S) % S, xx = loc % S;

    const float* xb = x + ((size_t)b * NTOK + base) * HID;
    float acc = bias[c];
    #pragma unroll
    for (int kd = 0; kd < 3; kd++) {
        int di = d + kd - 1;
        if (di < 0 || di >= S) continue;
        #pragma unroll
        for (int kh = 0; kh < 3; kh++) {
            int yi = yy + kh - 1;
            if (yi < 0 || yi >= S) continue;
            #pragma unroll
            for (int kw = 0; kw < 3; kw++) {
                int xi = xx + kw - 1;
                if (xi < 0 || xi >= S) continue;
                acc += sw[((kd * 3 + kh) * 3 + kw) * HID + c] *
                       xb[((size_t)(di * S + yi) * S + xi) * HID + c];
            }
        }
    }
    float g = 0.5f * acc * (1.f + erff(acc * 0.70710678118654752f));
    y[((size_t)b * NTOK + v) * HID + c] = g;
}

// ---------------- launch ----------------
static float* sym_addr(const void* sym) {
    void* p = nullptr;
    cudaGetSymbolAddress(&p, sym);
    return (float*)p;
}

extern "C" void kernel_launch(void* const* d_in, const int* in_sizes, int n_in,
                              void* d_out, int out_size)
{
    const float* query = (const float*)d_in[0];
    const float* feat  = (const float*)d_in[2];
    int wb = n_in - 24;
    const float* qnorm_w    = (const float*)d_in[wb + 0];
    const float* qnorm_b    = (const float*)d_in[wb + 1];
    const float* fnorm_w    = (const float*)d_in[wb + 2];
    const float* fnorm_b    = (const float*)d_in[wb + 3];
    const float* ext_qnorm_w= (const float*)d_in[wb + 4];
    const float* ext_qnorm_b= (const float*)d_in[wb + 5];
    const float* ext_fnorm_w= (const float*)d_in[wb + 6];
    const float* ext_fnorm_b= (const float*)d_in[wb + 7];
    const float* ffn_norm_w = (const float*)d_in[wb + 8];
    const float* ffn_norm_b = (const float*)d_in[wb + 9];
    const float* off_w      = (const float*)d_in[wb + 10];
    const float* off_b      = (const float*)d_in[wb + 11];
    const float* aw_w       = (const float*)d_in[wb + 12];
    const float* aw_b       = (const float*)d_in[wb + 13];
    const float* val_w      = (const float*)d_in[wb + 14];
    const float* val_b      = (const float*)d_in[wb + 15];
    const float* out_w      = (const float*)d_in[wb + 16];
    const float* out_b      = (const float*)d_in[wb + 17];
    const float* fc1_w      = (const float*)d_in[wb + 18];
    const float* fc1_b      = (const float*)d_in[wb + 19];
    const float* dw_w       = (const float*)d_in[wb + 20];
    const float* dw_b       = (const float*)d_in[wb + 21];
    const float* fc2_w      = (const float*)d_in[wb + 22];
    const float* fc2_b      = (const float*)d_in[wb + 23];

    float* qn   = sym_addr(g_qn);
    float* aq   = sym_addr(g_aq);
    float* af   = sym_addr(g_af);
    float* val  = sym_addr(g_val);
    float* off  = sym_addr(g_off);
    float* awl  = sym_addr(g_awl);
    float* dout = sym_addr(g_dout);
    float* out1 = sym_addr(g_out1);
    float* xf   = sym_addr(g_x);
    float* xg   = sym_addr(g_xg);
    float* outp = (float*)d_out;

    const int M = MROWS;
    dim3 gemm_blk(256);
    int gy = (M + 127) / 128;

    // 1) q build + LN chain
    prep_kernel<<<M, 128>>>(query, feat, qnorm_w, qnorm_b, fnorm_w, fnorm_b,
                            ext_qnorm_w, ext_qnorm_b, ext_fnorm_w, ext_fnorm_b,
                            qn, aq, af);
    // 2) value = af @ val_w + val_b
    gemm_tf32_kernel<false><<<dim3(6, gy), gemm_blk>>>(af, val_w, val_b, nullptr, val, M, 384, 384);
    // 3) offsets = aq @ off_w + off_b
    gemm_tf32_kernel<false><<<dim3(4, gy), gemm_blk>>>(aq, off_w, off_b, nullptr, off, M, 216, 384);
    // 4) attention logits = aq @ aw_w + aw_b
    gemm_tf32_kernel<false><<<dim3(2, gy), gemm_blk>>>(aq, aw_w, aw_b, nullptr, awl, M, 72, 384);
    // 5) deformable sampling (softmax fused)
    {
        int warps = MROWS * HEADS;
        int blocks = (warps + 7) / 8;
        deform_kernel<<<blocks, 256>>>(off, awl, val, dout);
    }
    // 6) out1 = qn + dout @ out_w + out_b
    gemm_tf32_kernel<true><<<dim3(6, gy), gemm_blk>>>(dout, out_w, out_b, qn, out1, M, 384, 384);
    // 7) t = LN(out1, ffn_norm)   (reuse aq buffer)
    ln_kernel<<<M, 128>>>(out1, ffn_norm_w, ffn_norm_b, aq);
    // 8) x = t @ fc1_w + fc1_b
    gemm_tf32_kernel<false><<<dim3(2, gy), gemm_blk>>>(aq, fc1_w, fc1_b, nullptr, xf, M, 96, 384);
    // 9) depthwise conv per segment + GELU
    dwconv_gelu_kernel<<<MROWS, HID>>>(xf, dw_w, dw_b, xg);
    // 10) out = out1 + xg @ fc2_w + fc2_b
    gemm_tf32_kernel<true><<<dim3(6, gy), gemm_blk>>>(xg, fc2_w, fc2_b, out1, outp, M, 384, 96);
}

// round 3
// speedup vs baseline: 1.8341x; 1.3966x over previous
#include <cuda_runtime.h>
#include <cuda_bf16.h>
#include <mma.h>
#include <math.h>

using namespace nvcuda;
typedef __nv_bfloat16 bf16;

// ---------------- problem constants ----------------
#define DIM     384
#define HEADS   6
#define HDIM    64
#define HID     96
#define BB      2
#define NMID    1728
#define NTOK    15768
#define NHIGH   13824
#define NMIDEND 15552
#define MROWS   (BB*NTOK)         // 31536

// weight arena offsets (bf16 elements)
#define WOFF_VAL  0
#define WOFF_OFF  147456
#define WOFF_AW   230400
#define WOFF_OUT  258048
#define WOFF_FC1  405504
#define WOFF_FC2  442368
#define WTOTAL    479232

// ---------------- scratch (device globals) ----------------
__device__ float g_qn  [(size_t)MROWS*DIM];
__device__ float g_out1[(size_t)MROWS*DIM];
__device__ float g_off [(size_t)MROWS*216];
__device__ float g_awl [(size_t)MROWS*72];
__device__ bf16  g_aq_b [(size_t)MROWS*DIM];   // reused as ffn-LN output
__device__ bf16  g_af_b [(size_t)MROWS*DIM];
__device__ bf16  g_val_b[(size_t)MROWS*DIM];
__device__ bf16  g_dout_b[(size_t)MROWS*DIM];
__device__ bf16  g_xf_b [(size_t)MROWS*HID];
__device__ bf16  g_xg_b [(size_t)MROWS*HID];
__device__ bf16  g_wb   [WTOTAL];

// ---------------- weight convert ----------------
__global__ void cvt_weights_kernel(const float* __restrict__ vw, const float* __restrict__ ow,
                                   const float* __restrict__ aww, const float* __restrict__ outw,
                                   const float* __restrict__ f1w, const float* __restrict__ f2w,
                                   bf16* __restrict__ dst)
{
    int i = blockIdx.x * blockDim.x + threadIdx.x;
    int stride = gridDim.x * blockDim.x;
    for (; i < WTOTAL; i += stride) {
        float v;
        if      (i < WOFF_OFF) v = vw [i - WOFF_VAL];
        else if (i < WOFF_AW ) v = ow [i - WOFF_OFF];
        else if (i < WOFF_OUT) v = aww[i - WOFF_AW];
        else if (i < WOFF_FC1) v = outw[i - WOFF_OUT];
        else if (i < WOFF_FC2) v = f1w[i - WOFF_FC1];
        else                   v = f2w[i - WOFF_FC2];
        dst[i] = __float2bfloat16(v);
    }
}

// ---------------- helpers ----------------
__device__ __forceinline__ float2 block_sum2(float a, float b) {
    __shared__ float sa[4], sb[4];
    int lane = threadIdx.x & 31, w = threadIdx.x >> 5;
    #pragma unroll
    for (int o = 16; o > 0; o >>= 1) {
        a += __shfl_down_sync(0xffffffffu, a, o);
        b += __shfl_down_sync(0xffffffffu, b, o);
    }
    if (lane == 0) { sa[w] = a; sb[w] = b; }
    __syncthreads();
    float ra = sa[0] + sa[1] + sa[2] + sa[3];
    float rb = sb[0] + sb[1] + sb[2] + sb[3];
    __syncthreads();
    return make_float2(ra, rb);
}

// ---------------- K1: build q (+feat), fused LN chain ----------------
__global__ void prep_kernel(const float* __restrict__ query, const float* __restrict__ feat,
                            const float* __restrict__ qw, const float* __restrict__ qb,
                            const float* __restrict__ fw, const float* __restrict__ fb,
                            const float* __restrict__ eqw, const float* __restrict__ eqb,
                            const float* __restrict__ efw, const float* __restrict__ efb,
                            float* __restrict__ qn_o, bf16* __restrict__ aq_o,
                            bf16* __restrict__ af_o)
{
    int row = blockIdx.x;
    int b = row / NTOK, t = row % NTOK;
    int tid = threadIdx.x;                // 128
    float x[3];
    float s = 0.f, ss = 0.f;
    #pragma unroll
    for (int i = 0; i < 3; i++) {
        int c = tid + i * 128;
        float v = query[(size_t)row * DIM + c];
        if (t >= NHIGH && t < NMIDEND)
            v += feat[((size_t)b * NMID + (t - NHIGH)) * DIM + c];
        x[i] = v; s += v; ss += v * v;
    }
    float2 r = block_sum2(s, ss);
    float m  = r.x * (1.f / DIM);
    float rs = rsqrtf(r.y * (1.f / DIM) - m * m + 1e-6f);

    float qv[3], fv[3];
    float s1 = 0.f, ss1 = 0.f, s2 = 0.f, ss2 = 0.f;
    #pragma unroll
    for (int i = 0; i < 3; i++) {
        int c = tid + i * 128;
        float xn = (x[i] - m) * rs;
        qv[i] = xn * qw[c] + qb[c];
        fv[i] = xn * fw[c] + fb[c];
        qn_o[(size_t)row * DIM + c] = qv[i];
        s1 += qv[i]; ss1 += qv[i] * qv[i];
        s2 += fv[i]; ss2 += fv[i] * fv[i];
    }
    float2 r1 = block_sum2(s1, ss1);
    float m1  = r1.x * (1.f / DIM);
    float rs1 = rsqrtf(r1.y * (1.f / DIM) - m1 * m1 + 1e-6f);
    float2 r2 = block_sum2(s2, ss2);
    float m2  = r2.x * (1.f / DIM);
    float rs2 = rsqrtf(r2.y * (1.f / DIM) - m2 * m2 + 1e-6f);
    #pragma unroll
    for (int i = 0; i < 3; i++) {
        int c = tid + i * 128;
        aq_o[(size_t)row * DIM + c] = __float2bfloat16((qv[i] - m1) * rs1 * eqw[c] + eqb[c]);
        af_o[(size_t)row * DIM + c] = __float2bfloat16((fv[i] - m2) * rs2 * efw[c] + efb[c]);
    }
}

// ---------------- generic LN (fp32 in -> bf16 out) ----------------
__global__ void ln_kernel(const float* __restrict__ xin, const float* __restrict__ w,
                          const float* __restrict__ bws, bf16* __restrict__ yo)
{
    int row = blockIdx.x;
    int tid = threadIdx.x;                // 128
    float x[3]; float s = 0.f, ss = 0.f;
    #pragma unroll
    for (int i = 0; i < 3; i++) {
        int c = tid + i * 128;
        x[i] = xin[(size_t)row * DIM + c];
        s += x[i]; ss += x[i] * x[i];
    }
    float2 r = block_sum2(s, ss);
    float m  = r.x * (1.f / DIM);
    float rs = rsqrtf(r.y * (1.f / DIM) - m * m + 1e-6f);
    #pragma unroll
    for (int i = 0; i < 3; i++) {
        int c = tid + i * 128;
        yo[(size_t)row * DIM + c] = __float2bfloat16((x[i] - m) * rs * w[c] + bws[c]);
    }
}

// ---------------- bf16 tensor-core GEMM, double-buffered ----------------
// C = A[M,K] @ W[K,N] + bias (+resid); 256 thr = 8 warps (4M x 2N), tile 128x64, BK=32
template<bool RESID, bool OUTBF>
__global__ void __launch_bounds__(256) gemm_bf16_kernel(
        const bf16* __restrict__ A, const bf16* __restrict__ W,
        const float* __restrict__ bias, const float* __restrict__ resid,
        void* __restrict__ Cout, int M, int N, int K)
{
    constexpr int BM = 128, BN = 64, BK = 32;
    constexpr int AP = 48, BP = 80, CP = 72;
    __shared__ __align__(16) char sraw[BM * CP * 4];              // 36864 B
    bf16* As = (bf16*)sraw;                                        // [2][BM*AP]
    bf16* Bs = (bf16*)(sraw + 2 * BM * AP * (int)sizeof(bf16));    // [2][BK*BP]
    float* Cs = (float*)sraw;

    int tid = threadIdx.x;
    int wid = tid >> 5, wm = wid & 3, wn = wid >> 2;
    int row0 = blockIdx.y * BM, col0 = blockIdx.x * BN;

    // load assignments: A = 512 vec8 (2/thr), B = 256 vec8 (1/thr)
    const int am0 = tid >> 2, akq = (tid & 3) * 8;
    const int bk  = tid >> 3, bn  = (tid & 7) * 8;
    const bool a0ok = (row0 + am0)      < M;
    const bool a1ok = (row0 + am0 + 64) < M;
    const bool bok  = (col0 + bn)       < N;
    const uint4 z4 = make_uint4(0, 0, 0, 0);

    uint4 ra0, ra1, rb;
    #define LDG_TILE(K0) do { \
        ra0 = a0ok ? *(const uint4*)&A[(size_t)(row0 + am0)      * K + (K0) + akq] : z4; \
        ra1 = a1ok ? *(const uint4*)&A[(size_t)(row0 + am0 + 64) * K + (K0) + akq] : z4; \
        rb  = bok  ? *(const uint4*)&W[(size_t)((K0) + bk) * N + col0 + bn]        : z4; \
    } while (0)
    #define STS_TILE(BUF) do { \
        *(uint4*)&As[(BUF) * BM * AP + am0 * AP + akq]        = ra0; \
        *(uint4*)&As[(BUF) * BM * AP + (am0 + 64) * AP + akq] = ra1; \
        *(uint4*)&Bs[(BUF) * BK * BP + bk * BP + bn]          = rb;  \
    } while (0)

    wmma::fragment<wmma::accumulator, 16, 16, 16, float> acc[2][2];
    #pragma unroll
    for (int i = 0; i < 2; i++)
        #pragma unroll
        for (int j = 0; j < 2; j++)
            wmma::fill_fragment(acc[i][j], 0.f);

    const int nk = K / BK;
    LDG_TILE(0);
    STS_TILE(0);
    __syncthreads();

    for (int t = 0; t < nk; t++) {
        if (t + 1 < nk) LDG_TILE((t + 1) * BK);
        const bf16* Ab = As + (t & 1) * BM * AP;
        const bf16* Bb = Bs + (t & 1) * BK * BP;
        #pragma unroll
        for (int ks = 0; ks < 2; ks++) {
            wmma::fragment<wmma::matrix_a, 16, 16, 16, bf16, wmma::row_major> fa[2];
            wmma::fragment<wmma::matrix_b, 16, 16, 16, bf16, wmma::row_major> fb[2];
            #pragma unroll
            for (int i = 0; i < 2; i++)
                wmma::load_matrix_sync(fa[i], &Ab[(wm * 32 + i * 16) * AP + ks * 16], AP);
            #pragma unroll
            for (int j = 0; j < 2; j++)
                wmma::load_matrix_sync(fb[j], &Bb[(ks * 16) * BP + wn * 32 + j * 16], BP);
            #pragma unroll
            for (int i = 0; i < 2; i++)
                #pragma unroll
                for (int j = 0; j < 2; j++)
                    wmma::mma_sync(acc[i][j], fa[i], fb[j], acc[i][j]);
        }
        if (t + 1 < nk) STS_TILE((t + 1) & 1);
        __syncthreads();
    }

    // epilogue via smem staging
    #pragma unroll
    for (int i = 0; i < 2; i++)
        #pragma unroll
        for (int j = 0; j < 2; j++)
            wmma::store_matrix_sync(&Cs[(wm * 32 + i * 16) * CP + wn * 32 + j * 16],
                                    acc[i][j], CP, wmma::mem_row_major);
    __syncthreads();
    #pragma unroll
    for (int it = 0; it < (BM * BN) / 256; it++) {
        int idx = tid + it * 256;
        int r = idx >> 6, c = idx & 63;
        int gr = row0 + r, gc = col0 + c;
        if (gr < M && gc < N) {
            float v = Cs[r * CP + c] + bias[gc];
            if (RESID) v += resid[(size_t)gr * N + gc];
            if (OUTBF) ((bf16*)Cout)[(size_t)gr * N + gc] = __float2bfloat16(v);
            else       ((float*)Cout)[(size_t)gr * N + gc] = v;
        }
    }
    #undef LDG_TILE
    #undef STS_TILE
}

// ---------------- deformable sampling (softmax fused, bf16 value) ----------------
__global__ void deform_kernel(const float* __restrict__ off, const float* __restrict__ awl,
                              const bf16* __restrict__ value, bf16* __restrict__ out)
{
    int gw   = (blockIdx.x * blockDim.x + threadIdx.x) >> 5;
    int lane = threadIdx.x & 31;
    if (gw >= MROWS * HEADS) return;
    int h  = gw % HEADS;
    int bq = gw / HEADS;
    int q  = bq % NTOK;
    int b  = bq / NTOK;

    float rd, rx, ry;
    {
        int S, loc;
        if (q < NHIGH)        { S = 24; loc = q; }
        else if (q < NMIDEND) { S = 12; loc = q - NHIGH; }
        else                  { S = 6;  loc = q - NMIDEND; }
        int d = loc / (S * S), y = (loc / S) % S, x = loc % S;
        float inv = 1.f / (float)S;
        rd = (d + 0.5f) * inv; ry = (y + 0.5f) * inv; rx = (x + 0.5f) * inv;
    }

    float aw[12];
    {
        const float* ap = awl + (size_t)bq * 72 + h * 12;
        float mx = -1e30f;
        #pragma unroll
        for (int j = 0; j < 12; j++) { aw[j] = ap[j]; mx = fmaxf(mx, aw[j]); }
        float se = 0.f;
        #pragma unroll
        for (int j = 0; j < 12; j++) { aw[j] = expf(aw[j] - mx); se += aw[j]; }
        float inv = 1.f / se;
        #pragma unroll
        for (int j = 0; j < 12; j++) aw[j] *= inv;
    }

    const int Ls[3] = {24, 12, 6};
    const int St[3] = {0, NHIGH, NMIDEND};
    const float* offp = off + (size_t)bq * 216 + h * 36;
    const bf16* vb    = value + (size_t)b * NTOK * DIM + h * HDIM + lane;

    float acc0 = 0.f, acc1 = 0.f;
    #pragma unroll
    for (int l = 0; l < 3; l++) {
        int S = Ls[l], st = St[l];
        #pragma unroll
        for (int p = 0; p < 4; p++) {
            const float* o = offp + (l * 4 + p) * 3;
            float pd = rd * S + o[0] - 0.5f;
            float px = rx * S + o[1] - 0.5f;
            float py = ry * S + o[2] - 0.5f;
            float fd = floorf(pd), fx = floorf(px), fy = floorf(py);
            int d0 = (int)fd, x0 = (int)fx, y0 = (int)fy;
            float wd = pd - fd, wx = px - fx, wy = py - fy;
            float a = aw[l * 4 + p];
            #pragma unroll
            for (int dd = 0; dd < 2; dd++) {
                int di = d0 + dd;
                if (di < 0 || di >= S) continue;
                float w_d = a * (dd ? wd : 1.f - wd);
                #pragma unroll
                for (int dy = 0; dy < 2; dy++) {
                    int yi = y0 + dy;
                    if (yi < 0 || yi >= S) continue;
                    float w_dy = w_d * (dy ? wy : 1.f - wy);
                    #pragma unroll
                    for (int dx = 0; dx < 2; dx++) {
                        int xi = x0 + dx;
                        if (xi < 0 || xi >= S) continue;
                        float w = w_dy * (dx ? wx : 1.f - wx);
                        size_t idx = (size_t)st + ((size_t)di * S + yi) * S + xi;
                        const bf16* vp = vb + idx * DIM;
                        acc0 += w * __bfloat162float(vp[0]);
                        acc1 += w * __bfloat162float(vp[32]);
                    }
                }
            }
        }
    }
    bf16* op = out + (size_t)bq * DIM + h * HDIM + lane;
    op[0]  = __float2bfloat16(acc0);
    op[32] = __float2bfloat16(acc1);
}

// ---------------- depthwise 3x3x3 conv per segment + exact GELU ----------------
__global__ void dwconv_gelu_kernel(const bf16* __restrict__ x, const float* __restrict__ w,
                                   const float* __restrict__ bias, bf16* __restrict__ y)
{
    int v = blockIdx.x % NTOK;
    int b = blockIdx.x / NTOK;
    int c = threadIdx.x;              // 96
    __shared__ float sw[27 * HID];
    for (int i = c; i < 27 * HID; i += HID) sw[i] = w[i];
    __syncthreads();

    int S, base;
    if (v < NHIGH)        { S = 24; base = 0; }
    else if (v < NMIDEND) { S = 12; base = NHIGH; }
    else                  { S = 6;  base = NMIDEND; }
    int loc = v - base;
    int d = loc / (S * S), yy = (loc / S) % S, xx = loc % S;

    const bf16* xb = x + ((size_t)b * NTOK + base) * HID;
    float acc = bias[c];
    #pragma unroll
    for (int kd = 0; kd < 3; kd++) {
        int di = d + kd - 1;
        if (di < 0 || di >= S) continue;
        #pragma unroll
        for (int kh = 0; kh < 3; kh++) {
            int yi = yy + kh - 1;
            if (yi < 0 || yi >= S) continue;
            #pragma unroll
            for (int kw = 0; kw < 3; kw++) {
                int xi = xx + kw - 1;
                if (xi < 0 || xi >= S) continue;
                acc += sw[((kd * 3 + kh) * 3 + kw) * HID + c] *
                       __bfloat162float(xb[((size_t)(di * S + yi) * S + xi) * HID + c]);
            }
        }
    }
    float g = 0.5f * acc * (1.f + erff(acc * 0.70710678118654752f));
    y[((size_t)b * NTOK + v) * HID + c] = __float2bfloat16(g);
}

// ---------------- launch ----------------
static void* sym_addr(const void* sym) {
    void* p = nullptr;
    cudaGetSymbolAddress(&p, sym);
    return p;
}

extern "C" void kernel_launch(void* const* d_in, const int* in_sizes, int n_in,
                              void* d_out, int out_size)
{
    const float* query = (const float*)d_in[0];
    const float* feat  = (const float*)d_in[2];
    int wb = n_in - 24;
    const float* qnorm_w    = (const float*)d_in[wb + 0];
    const float* qnorm_b    = (const float*)d_in[wb + 1];
    const float* fnorm_w    = (const float*)d_in[wb + 2];
    const float* fnorm_b    = (const float*)d_in[wb + 3];
    const float* ext_qnorm_w= (const float*)d_in[wb + 4];
    const float* ext_qnorm_b= (const float*)d_in[wb + 5];
    const float* ext_fnorm_w= (const float*)d_in[wb + 6];
    const float* ext_fnorm_b= (const float*)d_in[wb + 7];
    const float* ffn_norm_w = (const float*)d_in[wb + 8];
    const float* ffn_norm_b = (const float*)d_in[wb + 9];
    const float* off_w      = (const float*)d_in[wb + 10];
    const float* off_b      = (const float*)d_in[wb + 11];
    const float* aw_w       = (const float*)d_in[wb + 12];
    const float* aw_b       = (const float*)d_in[wb + 13];
    const float* val_w      = (const float*)d_in[wb + 14];
    const float* val_b      = (const float*)d_in[wb + 15];
    const float* out_w      = (const float*)d_in[wb + 16];
    const float* out_b      = (const float*)d_in[wb + 17];
    const float* fc1_w      = (const float*)d_in[wb + 18];
    const float* fc1_b      = (const float*)d_in[wb + 19];
    const float* dw_w       = (const float*)d_in[wb + 20];
    const float* dw_b       = (const float*)d_in[wb + 21];
    const float* fc2_w      = (const float*)d_in[wb + 22];
    const float* fc2_b      = (const float*)d_in[wb + 23];

    float* qn   = (float*)sym_addr(g_qn);
    float* out1 = (float*)sym_addr(g_out1);
    float* off  = (float*)sym_addr(g_off);
    float* awl  = (float*)sym_addr(g_awl);
    bf16* aqb   = (bf16*)sym_addr(g_aq_b);
    bf16* afb   = (bf16*)sym_addr(g_af_b);
    bf16* valb  = (bf16*)sym_addr(g_val_b);
    bf16* doutb = (bf16*)sym_addr(g_dout_b);
    bf16* xfb   = (bf16*)sym_addr(g_xf_b);
    bf16* xgb   = (bf16*)sym_addr(g_xg_b);
    bf16* wbf   = (bf16*)sym_addr(g_wb);
    float* outp = (float*)d_out;

    const int M = MROWS;
    int gy = (M + 127) / 128;

    // 0) weights -> bf16
    cvt_weights_kernel<<<468, 256>>>(val_w, off_w, aw_w, out_w, fc1_w, fc2_w, wbf);
    // 1) q build + LN chain (aq/af in bf16)
    prep_kernel<<<M, 128>>>(query, feat, qnorm_w, qnorm_b, fnorm_w, fnorm_b,
                            ext_qnorm_w, ext_qnorm_b, ext_fnorm_w, ext_fnorm_b,
                            qn, aqb, afb);
    // 2) value = af @ val_w + val_b   (bf16 out)
    gemm_bf16_kernel<false, true><<<dim3(6, gy), 256>>>(afb, wbf + WOFF_VAL, val_b, nullptr, valb, M, 384, 384);
    // 3) offsets = aq @ off_w + off_b  (fp32 out)
    gemm_bf16_kernel<false, false><<<dim3(4, gy), 256>>>(aqb, wbf + WOFF_OFF, off_b, nullptr, off, M, 216, 384);
    // 4) attention logits  (fp32 out)
    gemm_bf16_kernel<false, false><<<dim3(2, gy), 256>>>(aqb, wbf + WOFF_AW, aw_b, nullptr, awl, M, 72, 384);
    // 5) deformable sampling
    {
        int warps = MROWS * HEADS;
        int blocks = (warps + 7) / 8;
        deform_kernel<<<blocks, 256>>>(off, awl, valb, doutb);
    }
    // 6) out1 = qn + dout @ out_w + out_b (fp32)
    gemm_bf16_kernel<true, false><<<dim3(6, gy), 256>>>(doutb, wbf + WOFF_OUT, out_b, qn, out1, M, 384, 384);
    // 7) t = LN(out1, ffn_norm) -> bf16 (reuse aq buffer)
    ln_kernel<<<M, 128>>>(out1, ffn_norm_w, ffn_norm_b, aqb);
    // 8) x = t @ fc1_w + fc1_b  (bf16 out)
    gemm_bf16_kernel<false, true><<<dim3(2, gy), 256>>>(aqb, wbf + WOFF_FC1, fc1_b, nullptr, xfb, M, 96, 384);
    // 9) depthwise conv + GELU (bf16 out)
    dwconv_gelu_kernel<<<MROWS, HID>>>(xfb, dw_w, dw_b, xgb);
    // 10) out = out1 + xg @ fc2_w + fc2_b (fp32)
    gemm_bf16_kernel<true, false><<<dim3(6, gy), 256>>>(xgb, wbf + WOFF_FC2, fc2_b, out1, outp, M, 384, 96);
}

// round 4
// speedup vs baseline: 2.0815x; 1.1349x over previous
#include <cuda_runtime.h>
#include <cuda_bf16.h>
#include <mma.h>
#include <math.h>

using namespace nvcuda;
typedef __nv_bfloat16 bf16;

// ---------------- problem constants ----------------
#define DIM     384
#define HEADS   6
#define HDIM    64
#define HID     96
#define BB      2
#define NMID    1728
#define NTOK    15768
#define NHIGH   13824
#define NMIDEND 15552
#define MROWS   (BB*NTOK)         // 31536

// weight arena offsets (bf16 elements)
#define WOFF_VAL   0
#define WOFF_OFFAW 147456
#define WOFF_OUT   258048
#define WOFF_FC1   405504
#define WOFF_FC2   442368
#define WTOTAL     479232

// ---------------- scratch (device globals) ----------------
__device__ float g_qn   [(size_t)MROWS*DIM];
__device__ float g_out1 [(size_t)MROWS*DIM];
__device__ float g_offaw[(size_t)MROWS*288];
__device__ bf16  g_aq_b [(size_t)MROWS*DIM];   // reused as ffn-LN output
__device__ bf16  g_af_b [(size_t)MROWS*DIM];
__device__ bf16  g_val_b[(size_t)MROWS*DIM];
__device__ bf16  g_dout_b[(size_t)MROWS*DIM];
__device__ bf16  g_xf_b [(size_t)MROWS*HID];
__device__ bf16  g_xg_b [(size_t)MROWS*HID];
__device__ bf16  g_wb   [WTOTAL];

// ---------------- weight convert (off+aw interleaved to N=288) ----------------
__global__ void cvt_weights_kernel(const float* __restrict__ vw, const float* __restrict__ ow,
                                   const float* __restrict__ aww, const float* __restrict__ outw,
                                   const float* __restrict__ f1w, const float* __restrict__ f2w,
                                   bf16* __restrict__ dst)
{
    int i = blockIdx.x * blockDim.x + threadIdx.x;
    int stride = gridDim.x * blockDim.x;
    for (; i < WTOTAL; i += stride) {
        float v;
        if      (i < WOFF_OFFAW) v = vw[i];
        else if (i < WOFF_OUT) {
            int rel = i - WOFF_OFFAW;
            int k = rel / 288, j = rel % 288;
            v = (j < 216) ? ow[k * 216 + j] : aww[k * 72 + (j - 216)];
        }
        else if (i < WOFF_FC1) v = outw[i - WOFF_OUT];
        else if (i < WOFF_FC2) v = f1w[i - WOFF_FC1];
        else                   v = f2w[i - WOFF_FC2];
        dst[i] = __float2bfloat16(v);
    }
}

// ---------------- helpers ----------------
__device__ __forceinline__ float2 block_sum2(float a, float b) {
    __shared__ float sa[4], sb[4];
    int lane = threadIdx.x & 31, w = threadIdx.x >> 5;
    #pragma unroll
    for (int o = 16; o > 0; o >>= 1) {
        a += __shfl_down_sync(0xffffffffu, a, o);
        b += __shfl_down_sync(0xffffffffu, b, o);
    }
    if (lane == 0) { sa[w] = a; sb[w] = b; }
    __syncthreads();
    float ra = sa[0] + sa[1] + sa[2] + sa[3];
    float rb = sb[0] + sb[1] + sb[2] + sb[3];
    __syncthreads();
    return make_float2(ra, rb);
}

// ---------------- K1: build q (+feat), fused LN chain ----------------
__global__ void prep_kernel(const float* __restrict__ query, const float* __restrict__ feat,
                            const float* __restrict__ qw, const float* __restrict__ qb,
                            const float* __restrict__ fw, const float* __restrict__ fb,
                            const float* __restrict__ eqw, const float* __restrict__ eqb,
                            const float* __restrict__ efw, const float* __restrict__ efb,
                            float* __restrict__ qn_o, bf16* __restrict__ aq_o,
                            bf16* __restrict__ af_o)
{
    int row = blockIdx.x;
    int b = row / NTOK, t = row % NTOK;
    int tid = threadIdx.x;                // 128
    float x[3];
    float s = 0.f, ss = 0.f;
    #pragma unroll
    for (int i = 0; i < 3; i++) {
        int c = tid + i * 128;
        float v = query[(size_t)row * DIM + c];
        if (t >= NHIGH && t < NMIDEND)
            v += feat[((size_t)b * NMID + (t - NHIGH)) * DIM + c];
        x[i] = v; s += v; ss += v * v;
    }
    float2 r = block_sum2(s, ss);
    float m  = r.x * (1.f / DIM);
    float rs = rsqrtf(r.y * (1.f / DIM) - m * m + 1e-6f);

    float qv[3], fv[3];
    float s1 = 0.f, ss1 = 0.f, s2 = 0.f, ss2 = 0.f;
    #pragma unroll
    for (int i = 0; i < 3; i++) {
        int c = tid + i * 128;
        float xn = (x[i] - m) * rs;
        qv[i] = xn * qw[c] + qb[c];
        fv[i] = xn * fw[c] + fb[c];
        qn_o[(size_t)row * DIM + c] = qv[i];
        s1 += qv[i]; ss1 += qv[i] * qv[i];
        s2 += fv[i]; ss2 += fv[i] * fv[i];
    }
    float2 r1 = block_sum2(s1, ss1);
    float m1  = r1.x * (1.f / DIM);
    float rs1 = rsqrtf(r1.y * (1.f / DIM) - m1 * m1 + 1e-6f);
    float2 r2 = block_sum2(s2, ss2);
    float m2  = r2.x * (1.f / DIM);
    float rs2 = rsqrtf(r2.y * (1.f / DIM) - m2 * m2 + 1e-6f);
    #pragma unroll
    for (int i = 0; i < 3; i++) {
        int c = tid + i * 128;
        aq_o[(size_t)row * DIM + c] = __float2bfloat16((qv[i] - m1) * rs1 * eqw[c] + eqb[c]);
        af_o[(size_t)row * DIM + c] = __float2bfloat16((fv[i] - m2) * rs2 * efw[c] + efb[c]);
    }
}

// ---------------- generic LN (fp32 in -> bf16 out) ----------------
__global__ void ln_kernel(const float* __restrict__ xin, const float* __restrict__ w,
                          const float* __restrict__ bws, bf16* __restrict__ yo)
{
    int row = blockIdx.x;
    int tid = threadIdx.x;                // 128
    float x[3]; float s = 0.f, ss = 0.f;
    #pragma unroll
    for (int i = 0; i < 3; i++) {
        int c = tid + i * 128;
        x[i] = xin[(size_t)row * DIM + c];
        s += x[i]; ss += x[i] * x[i];
    }
    float2 r = block_sum2(s, ss);
    float m  = r.x * (1.f / DIM);
    float rs = rsqrtf(r.y * (1.f / DIM) - m * m + 1e-6f);
    #pragma unroll
    for (int i = 0; i < 3; i++) {
        int c = tid + i * 128;
        yo[(size_t)row * DIM + c] = __float2bfloat16((x[i] - m) * rs * w[c] + bws[c]);
    }
}

// ---------------- bf16 tensor-core GEMM, double-buffered ----------------
template<bool RESID, bool OUTBF>
__global__ void __launch_bounds__(256) gemm_bf16_kernel(
        const bf16* __restrict__ A, const bf16* __restrict__ W,
        const float* __restrict__ bias, const float* __restrict__ resid,
        void* __restrict__ Cout, int M, int N, int K)
{
    constexpr int BM = 128, BN = 64, BK = 32;
    constexpr int AP = 48, BP = 80, CP = 72;
    __shared__ __align__(16) char sraw[BM * CP * 4];
    bf16* As = (bf16*)sraw;
    bf16* Bs = (bf16*)(sraw + 2 * BM * AP * (int)sizeof(bf16));
    float* Cs = (float*)sraw;

    int tid = threadIdx.x;
    int wid = tid >> 5, wm = wid & 3, wn = wid >> 2;
    int row0 = blockIdx.y * BM, col0 = blockIdx.x * BN;

    const int am0 = tid >> 2, akq = (tid & 3) * 8;
    const int bk  = tid >> 3, bn  = (tid & 7) * 8;
    const bool a0ok = (row0 + am0)      < M;
    const bool a1ok = (row0 + am0 + 64) < M;
    const bool bok  = (col0 + bn)       < N;
    const uint4 z4 = make_uint4(0, 0, 0, 0);

    uint4 ra0, ra1, rb;
    #define LDG_TILE(K0) do { \
        ra0 = a0ok ? *(const uint4*)&A[(size_t)(row0 + am0)      * K + (K0) + akq] : z4; \
        ra1 = a1ok ? *(const uint4*)&A[(size_t)(row0 + am0 + 64) * K + (K0) + akq] : z4; \
        rb  = bok  ? *(const uint4*)&W[(size_t)((K0) + bk) * N + col0 + bn]        : z4; \
    } while (0)
    #define STS_TILE(BUF) do { \
        *(uint4*)&As[(BUF) * BM * AP + am0 * AP + akq]        = ra0; \
        *(uint4*)&As[(BUF) * BM * AP + (am0 + 64) * AP + akq] = ra1; \
        *(uint4*)&Bs[(BUF) * BK * BP + bk * BP + bn]          = rb;  \
    } while (0)

    wmma::fragment<wmma::accumulator, 16, 16, 16, float> acc[2][2];
    #pragma unroll
    for (int i = 0; i < 2; i++)
        #pragma unroll
        for (int j = 0; j < 2; j++)
            wmma::fill_fragment(acc[i][j], 0.f);

    const int nk = K / BK;
    LDG_TILE(0);
    STS_TILE(0);
    __syncthreads();

    for (int t = 0; t < nk; t++) {
        if (t + 1 < nk) LDG_TILE((t + 1) * BK);
        const bf16* Ab = As + (t & 1) * BM * AP;
        const bf16* Bb = Bs + (t & 1) * BK * BP;
        #pragma unroll
        for (int ks = 0; ks < 2; ks++) {
            wmma::fragment<wmma::matrix_a, 16, 16, 16, bf16, wmma::row_major> fa[2];
            wmma::fragment<wmma::matrix_b, 16, 16, 16, bf16, wmma::row_major> fb[2];
            #pragma unroll
            for (int i = 0; i < 2; i++)
                wmma::load_matrix_sync(fa[i], &Ab[(wm * 32 + i * 16) * AP + ks * 16], AP);
            #pragma unroll
            for (int j = 0; j < 2; j++)
                wmma::load_matrix_sync(fb[j], &Bb[(ks * 16) * BP + wn * 32 + j * 16], BP);
            #pragma unroll
            for (int i = 0; i < 2; i++)
                #pragma unroll
                for (int j = 0; j < 2; j++)
                    wmma::mma_sync(acc[i][j], fa[i], fb[j], acc[i][j]);
        }
        if (t + 1 < nk) STS_TILE((t + 1) & 1);
        __syncthreads();
    }

    #pragma unroll
    for (int i = 0; i < 2; i++)
        #pragma unroll
        for (int j = 0; j < 2; j++)
            wmma::store_matrix_sync(&Cs[(wm * 32 + i * 16) * CP + wn * 32 + j * 16],
                                    acc[i][j], CP, wmma::mem_row_major);
    __syncthreads();
    #pragma unroll
    for (int it = 0; it < (BM * BN) / 256; it++) {
        int idx = tid + it * 256;
        int r = idx >> 6, c = idx & 63;
        int gr = row0 + r, gc = col0 + c;
        if (gr < M && gc < N) {
            float v = Cs[r * CP + c] + bias[gc];
            if (RESID) v += resid[(size_t)gr * N + gc];
            if (OUTBF) ((bf16*)Cout)[(size_t)gr * N + gc] = __float2bfloat16(v);
            else       ((float*)Cout)[(size_t)gr * N + gc] = v;
        }
    }
    #undef LDG_TILE
    #undef STS_TILE
}

// ---------------- deformable sampling: branch-free, bf16x2 loads ----------------
__global__ void deform_kernel(const float* __restrict__ offaw,
                              const bf16* __restrict__ value, bf16* __restrict__ out)
{
    int gw   = (blockIdx.x * blockDim.x + threadIdx.x) >> 5;
    int lane = threadIdx.x & 31;
    if (gw >= MROWS * HEADS) return;
    int h  = gw % HEADS;
    int bq = gw / HEADS;
    int q  = bq % NTOK;
    int b  = bq / NTOK;

    float rd, rx, ry;
    {
        int S, loc;
        if (q < NHIGH)        { S = 24; loc = q; }
        else if (q < NMIDEND) { S = 12; loc = q - NHIGH; }
        else                  { S = 6;  loc = q - NMIDEND; }
        int d = loc / (S * S), y = (loc / S) % S, x = loc % S;
        float inv = 1.f / (float)S;
        rd = (d + 0.5f) * inv; ry = (y + 0.5f) * inv; rx = (x + 0.5f) * inv;
    }

    // softmax over 12 logits (combined buffer, cols 216..287)
    float aw[12];
    {
        const float* ap = offaw + (size_t)bq * 288 + 216 + h * 12;
        float mx = -1e30f;
        #pragma unroll
        for (int j = 0; j < 12; j++) { aw[j] = ap[j]; mx = fmaxf(mx, aw[j]); }
        float se = 0.f;
        #pragma unroll
        for (int j = 0; j < 12; j++) { aw[j] = expf(aw[j] - mx); se += aw[j]; }
        float inv = 1.f / se;
        #pragma unroll
        for (int j = 0; j < 12; j++) aw[j] *= inv;
    }

    const int Ls[3] = {24, 12, 6};
    const int St[3] = {0, NHIGH, NMIDEND};
    const float* offp = offaw + (size_t)bq * 288 + h * 36;
    const bf16* vb    = value + (size_t)b * NTOK * DIM + h * HDIM + lane * 2;

    float accx = 0.f, accy = 0.f;
    #pragma unroll
    for (int l = 0; l < 3; l++) {
        const int S = Ls[l], st = St[l];
        #pragma unroll
        for (int p = 0; p < 4; p++) {
            const float* o = offp + (l * 4 + p) * 3;
            float pd = rd * S + o[0] - 0.5f;
            float px = rx * S + o[1] - 0.5f;
            float py = ry * S + o[2] - 0.5f;
            float fd = floorf(pd), fx = floorf(px), fy = floorf(py);
            int d0 = (int)fd, x0 = (int)fx, y0 = (int)fy;
            int d1 = d0 + 1, x1 = x0 + 1, y1 = y0 + 1;
            float wd1 = pd - fd, wx1 = px - fx, wy1 = py - fy;
            float a = aw[l * 4 + p];
            // validity folded into weights; indices clamped
            float wD0 = a * (1.f - wd1) * ((d0 >= 0 && d0 < S) ? 1.f : 0.f);
            float wD1 = a * wd1        * ((d1 >= 0 && d1 < S) ? 1.f : 0.f);
            float wY0 = (1.f - wy1) * ((y0 >= 0 && y0 < S) ? 1.f : 0.f);
            float wY1 = wy1         * ((y1 >= 0 && y1 < S) ? 1.f : 0.f);
            float wX0 = (1.f - wx1) * ((x0 >= 0 && x0 < S) ? 1.f : 0.f);
            float wX1 = wx1         * ((x1 >= 0 && x1 < S) ? 1.f : 0.f);
            int cd0 = min(max(d0, 0), S - 1), cd1 = min(max(d1, 0), S - 1);
            int cy0 = min(max(y0, 0), S - 1), cy1 = min(max(y1, 0), S - 1);
            int cx0 = min(max(x0, 0), S - 1), cx1 = min(max(x1, 0), S - 1);
            int bD0 = st + cd0 * S * S, bD1 = st + cd1 * S * S;
            int rY0 = cy0 * S, rY1 = cy1 * S;
            int i00 = bD0 + rY0, i01 = bD0 + rY1, i10 = bD1 + rY0, i11 = bD1 + rY1;
            // 8 corner loads, all issued unconditionally
            float2 v000 = __bfloat1622float2(*(const __nv_bfloat162*)(vb + (size_t)(i00 + cx0) * DIM));
            float2 v001 = __bfloat1622float2(*(const __nv_bfloat162*)(vb + (size_t)(i00 + cx1) * DIM));
            float2 v010 = __bfloat1622float2(*(const __nv_bfloat162*)(vb + (size_t)(i01 + cx0) * DIM));
            float2 v011 = __bfloat1622float2(*(const __nv_bfloat162*)(vb + (size_t)(i01 + cx1) * DIM));
            float2 v100 = __bfloat1622float2(*(const __nv_bfloat162*)(vb + (size_t)(i10 + cx0) * DIM));
            float2 v101 = __bfloat1622float2(*(const __nv_bfloat162*)(vb + (size_t)(i10 + cx1) * DIM));
            float2 v110 = __bfloat1622float2(*(const __nv_bfloat162*)(vb + (size_t)(i11 + cx0) * DIM));
            float2 v111 = __bfloat1622float2(*(const __nv_bfloat162*)(vb + (size_t)(i11 + cx1) * DIM));
            float w000 = wD0 * wY0 * wX0, w001 = wD0 * wY0 * wX1;
            float w010 = wD0 * wY1 * wX0, w011 = wD0 * wY1 * wX1;
            float w100 = wD1 * wY0 * wX0, w101 = wD1 * wY0 * wX1;
            float w110 = wD1 * wY1 * wX0, w111 = wD1 * wY1 * wX1;
            accx += w000 * v000.x + w001 * v001.x + w010 * v010.x + w011 * v011.x
                  + w100 * v100.x + w101 * v101.x + w110 * v110.x + w111 * v111.x;
            accy += w000 * v000.y + w001 * v001.y + w010 * v010.y + w011 * v011.y
                  + w100 * v100.y + w101 * v101.y + w110 * v110.y + w111 * v111.y;
        }
    }
    __nv_bfloat162* op = (__nv_bfloat162*)(out + (size_t)bq * DIM + h * HDIM + lane * 2);
    *op = __floats2bfloat162_rn(accx, accy);
}

// ---------------- depthwise 3x3x3 conv + GELU, 16 voxels/block ----------------
__global__ void __launch_bounds__(384) dwconv_gelu_kernel(
        const bf16* __restrict__ x, const float* __restrict__ w,
        const float* __restrict__ bias, bf16* __restrict__ y)
{
    __shared__ float sw[27 * HID];
    int tid = threadIdx.x;                 // 384
    for (int i = tid; i < 27 * HID; i += 384) sw[i] = w[i];
    __syncthreads();

    int c = tid % HID;
    int g = tid / HID;                     // 0..3
    float bc = bias[c];

    #pragma unroll
    for (int iter = 0; iter < 4; iter++) {
        int vlin = blockIdx.x * 16 + iter * 4 + g;
        int b = vlin / NTOK, v = vlin % NTOK;

        int S, base;
        if (v < NHIGH)        { S = 24; base = 0; }
        else if (v < NMIDEND) { S = 12; base = NHIGH; }
        else                  { S = 6;  base = NMIDEND; }
        int loc = v - base;
        int d = loc / (S * S), yy = (loc / S) % S, xx = loc % S;

        const bf16* xb = x + ((size_t)b * NTOK + base) * HID;
        float acc = bc;
        #pragma unroll
        for (int kd = 0; kd < 3; kd++) {
            int di = d + kd - 1;
            if (di < 0 || di >= S) continue;
            #pragma unroll
            for (int kh = 0; kh < 3; kh++) {
                int yi = yy + kh - 1;
                if (yi < 0 || yi >= S) continue;
                #pragma unroll
                for (int kw = 0; kw < 3; kw++) {
                    int xi = xx + kw - 1;
                    if (xi < 0 || xi >= S) continue;
                    acc += sw[((kd * 3 + kh) * 3 + kw) * HID + c] *
                           __bfloat162float(xb[((size_t)(di * S + yi) * S + xi) * HID + c]);
                }
            }
        }
        float gl = 0.5f * acc * (1.f + erff(acc * 0.70710678118654752f));
        y[((size_t)b * NTOK + v) * HID + c] = __float2bfloat16(gl);
    }
}

// ---------------- launch ----------------
static void* sym_addr(const void* sym) {
    void* p = nullptr;
    cudaGetSymbolAddress(&p, sym);
    return p;
}

extern "C" void kernel_launch(void* const* d_in, const int* in_sizes, int n_in,
                              void* d_out, int out_size)
{
    const float* query = (const float*)d_in[0];
    const float* feat  = (const float*)d_in[2];
    int wb = n_in - 24;
    const float* qnorm_w    = (const float*)d_in[wb + 0];
    const float* qnorm_b    = (const float*)d_in[wb + 1];
    const float* fnorm_w    = (const float*)d_in[wb + 2];
    const float* fnorm_b    = (const float*)d_in[wb + 3];
    const float* ext_qnorm_w= (const float*)d_in[wb + 4];
    const float* ext_qnorm_b= (const float*)d_in[wb + 5];
    const float* ext_fnorm_w= (const float*)d_in[wb + 6];
    const float* ext_fnorm_b= (const float*)d_in[wb + 7];
    const float* ffn_norm_w = (const float*)d_in[wb + 8];
    const float* ffn_norm_b = (const float*)d_in[wb + 9];
    const float* off_w      = (const float*)d_in[wb + 10];
    const float* off_b      = (const float*)d_in[wb + 11];
    const float* aw_w       = (const float*)d_in[wb + 12];
    const float* aw_b       = (const float*)d_in[wb + 13];
    const float* val_w      = (const float*)d_in[wb + 14];
    const float* val_b      = (const float*)d_in[wb + 15];
    const float* out_w      = (const float*)d_in[wb + 16];
    const float* out_b      = (const float*)d_in[wb + 17];
    const float* fc1_w      = (const float*)d_in[wb + 18];
    const float* fc1_b      = (const float*)d_in[wb + 19];
    const float* dw_w       = (const float*)d_in[wb + 20];
    const float* dw_b       = (const float*)d_in[wb + 21];
    const float* fc2_w      = (const float*)d_in[wb + 22];
    const float* fc2_b      = (const float*)d_in[wb + 23];

    float* qn    = (float*)sym_addr(g_qn);
    float* out1  = (float*)sym_addr(g_out1);
    float* offaw = (float*)sym_addr(g_offaw);
    bf16* aqb    = (bf16*)sym_addr(g_aq_b);
    bf16* afb    = (bf16*)sym_addr(g_af_b);
    bf16* valb   = (bf16*)sym_addr(g_val_b);
    bf16* doutb  = (bf16*)sym_addr(g_dout_b);
    bf16* xfb    = (bf16*)sym_addr(g_xf_b);
    bf16* xgb    = (bf16*)sym_addr(g_xg_b);
    bf16* wbf    = (bf16*)sym_addr(g_wb);
    float* outp  = (float*)d_out;

    // combined off+aw bias staged in constant-free device memory via small kernel?
    // simplest: epilogue bias needs a [288] fp32 array; reuse tail of g_offaw? No —
    // build it into the last 288 floats of g_out1 (overwritten later AFTER use).
    // Safer: small dedicated static buffer:
    static float* offaw_bias = nullptr;
    // use the last 288 floats of the weight arena region? arena is bf16. Use a
    // dedicated device global:
    // (declared below via lambda-scope static is not allowed; use g_offaw tail is
    //  unsafe. Declare a real global.)
    extern void* _dummy_unused;
    (void)offaw_bias;

    const int M = MROWS;
    int gy = (M + 127) / 128;

    // 0) weights -> bf16 (+ interleave off/aw)
    cvt_weights_kernel<<<468, 256>>>(val_w, off_w, aw_w, out_w, fc1_w, fc2_w, wbf);
    // 0b) combined bias: copy off_b then aw_b into a contiguous 288-float buffer.
    //     Reuse the FIRST row region of g_out1 (it is fully overwritten by GEMM 6
    //     before any read). Copy async d2d.
    cudaMemcpyAsync(out1,       off_b, 216 * sizeof(float), cudaMemcpyDeviceToDevice);
    cudaMemcpyAsync(out1 + 216, aw_b,   72 * sizeof(float), cudaMemcpyDeviceToDevice);
    // 1) q build + LN chain
    prep_kernel<<<M, 128>>>(query, feat, qnorm_w, qnorm_b, fnorm_w, fnorm_b,
                            ext_qnorm_w, ext_qnorm_b, ext_fnorm_w, ext_fnorm_b,
                            qn, aqb, afb);
    // 2) value = af @ val_w + val_b   (bf16 out)
    gemm_bf16_kernel<false, true><<<dim3(6, gy), 256>>>(afb, wbf + WOFF_VAL, val_b, nullptr, valb, M, 384, 384);
    // 3) offsets+logits = aq @ [off|aw]_w + bias  (fp32 out, N=288)
    gemm_bf16_kernel<false, false><<<dim3(5, gy), 256>>>(aqb, wbf + WOFF_OFFAW, out1, nullptr, offaw, M, 288, 384);
    // 4) deformable sampling (softmax fused)
    {
        int warps = MROWS * HEADS;
        int blocks = (warps + 7) / 8;
        deform_kernel<<<blocks, 256>>>(offaw, valb, doutb);
    }
    // 5) out1 = qn + dout @ out_w + out_b (fp32)  — overwrites the bias staging
    gemm_bf16_kernel<true, false><<<dim3(6, gy), 256>>>(doutb, wbf + WOFF_OUT, out_b, qn, out1, M, 384, 384);
    // 6) t = LN(out1, ffn_norm) -> bf16
    ln_kernel<<<M, 128>>>(out1, ffn_norm_w, ffn_norm_b, aqb);
    // 7) x = t @ fc1_w + fc1_b  (bf16 out)
    gemm_bf16_kernel<false, true><<<dim3(2, gy), 256>>>(aqb, wbf + WOFF_FC1, fc1_b, nullptr, xfb, M, 96, 384);
    // 8) depthwise conv + GELU (bf16 out)
    dwconv_gelu_kernel<<<MROWS / 16, 384>>>(xfb, dw_w, dw_b, xgb);
    // 9) out = out1 + xg @ fc2_w + fc2_b (fp32)
    gemm_bf16_kernel<true, false><<<dim3(6, gy), 256>>>(xgb, wbf + WOFF_FC2, fc2_b, out1, outp, M, 384, 96);
}
void* _dummy_unused = nullptr;

// round 5
// speedup vs baseline: 2.2065x; 1.0600x over previous
#include <cuda_runtime.h>
#include <cuda_bf16.h>
#include <mma.h>
#include <math.h>

using namespace nvcuda;
typedef __nv_bfloat16 bf16;

// ---------------- problem constants ----------------
#define DIM     384
#define HEADS   6
#define HDIM    64
#define HID     96
#define BB      2
#define NMID    1728
#define NTOK    15768
#define NHIGH   13824
#define NMIDEND 15552
#define MROWS   (BB*NTOK)         // 31536

// weight arena offsets (bf16 elements)
#define WOFF_VAL   0
#define WOFF_OFFAW 147456
#define WOFF_OUT   258048
#define WOFF_FC1   405504
#define WOFF_FC2   442368
#define WTOTAL     479232

// ---------------- scratch (device globals) ----------------
__device__ float g_qn   [(size_t)MROWS*DIM];
__device__ float g_out1 [(size_t)MROWS*DIM];
__device__ float g_offaw[(size_t)MROWS*288];
__device__ bf16  g_aq_b [(size_t)MROWS*DIM];
__device__ bf16  g_af_b [(size_t)MROWS*DIM];
__device__ bf16  g_val_b[(size_t)MROWS*DIM];
__device__ bf16  g_dout_b[(size_t)MROWS*DIM];
__device__ bf16  g_xf_b [(size_t)MROWS*HID];
__device__ bf16  g_xg_b [(size_t)MROWS*HID];
__device__ bf16  g_wb   [WTOTAL];

// ---------------- weight convert (off+aw interleaved to N=288) ----------------
__global__ void cvt_weights_kernel(const float* __restrict__ vw, const float* __restrict__ ow,
                                   const float* __restrict__ aww, const float* __restrict__ outw,
                                   const float* __restrict__ f1w, const float* __restrict__ f2w,
                                   bf16* __restrict__ dst)
{
    int i = blockIdx.x * blockDim.x + threadIdx.x;
    int stride = gridDim.x * blockDim.x;
    for (; i < WTOTAL; i += stride) {
        float v;
        if      (i < WOFF_OFFAW) v = vw[i];
        else if (i < WOFF_OUT) {
            int rel = i - WOFF_OFFAW;
            int k = rel / 288, j = rel % 288;
            v = (j < 216) ? ow[k * 216 + j] : aww[k * 72 + (j - 216)];
        }
        else if (i < WOFF_FC1) v = outw[i - WOFF_OUT];
        else if (i < WOFF_FC2) v = f1w[i - WOFF_FC1];
        else                   v = f2w[i - WOFF_FC2];
        dst[i] = __float2bfloat16(v);
    }
}

// ---------------- helpers ----------------
__device__ __forceinline__ float2 block_sum2(float a, float b) {
    __shared__ float sa[4], sb[4];
    int lane = threadIdx.x & 31, w = threadIdx.x >> 5;
    #pragma unroll
    for (int o = 16; o > 0; o >>= 1) {
        a += __shfl_down_sync(0xffffffffu, a, o);
        b += __shfl_down_sync(0xffffffffu, b, o);
    }
    if (lane == 0) { sa[w] = a; sb[w] = b; }
    __syncthreads();
    float ra = sa[0] + sa[1] + sa[2] + sa[3];
    float rb = sb[0] + sb[1] + sb[2] + sb[3];
    __syncthreads();
    return make_float2(ra, rb);
}

// ---------------- K1: build q (+feat), fused LN chain ----------------
__global__ void prep_kernel(const float* __restrict__ query, const float* __restrict__ feat,
                            const float* __restrict__ qw, const float* __restrict__ qb,
                            const float* __restrict__ fw, const float* __restrict__ fb,
                            const float* __restrict__ eqw, const float* __restrict__ eqb,
                            const float* __restrict__ efw, const float* __restrict__ efb,
                            float* __restrict__ qn_o, bf16* __restrict__ aq_o,
                            bf16* __restrict__ af_o)
{
    int row = blockIdx.x;
    int b = row / NTOK, t = row % NTOK;
    int tid = threadIdx.x;                // 128
    float x[3];
    float s = 0.f, ss = 0.f;
    #pragma unroll
    for (int i = 0; i < 3; i++) {
        int c = tid + i * 128;
        float v = query[(size_t)row * DIM + c];
        if (t >= NHIGH && t < NMIDEND)
            v += feat[((size_t)b * NMID + (t - NHIGH)) * DIM + c];
        x[i] = v; s += v; ss += v * v;
    }
    float2 r = block_sum2(s, ss);
    float m  = r.x * (1.f / DIM);
    float rs = rsqrtf(r.y * (1.f / DIM) - m * m + 1e-6f);

    float qv[3], fv[3];
    float s1 = 0.f, ss1 = 0.f, s2 = 0.f, ss2 = 0.f;
    #pragma unroll
    for (int i = 0; i < 3; i++) {
        int c = tid + i * 128;
        float xn = (x[i] - m) * rs;
        qv[i] = xn * qw[c] + qb[c];
        fv[i] = xn * fw[c] + fb[c];
        qn_o[(size_t)row * DIM + c] = qv[i];
        s1 += qv[i]; ss1 += qv[i] * qv[i];
        s2 += fv[i]; ss2 += fv[i] * fv[i];
    }
    float2 r1 = block_sum2(s1, ss1);
    float m1  = r1.x * (1.f / DIM);
    float rs1 = rsqrtf(r1.y * (1.f / DIM) - m1 * m1 + 1e-6f);
    float2 r2 = block_sum2(s2, ss2);
    float m2  = r2.x * (1.f / DIM);
    float rs2 = rsqrtf(r2.y * (1.f / DIM) - m2 * m2 + 1e-6f);
    #pragma unroll
    for (int i = 0; i < 3; i++) {
        int c = tid + i * 128;
        aq_o[(size_t)row * DIM + c] = __float2bfloat16((qv[i] - m1) * rs1 * eqw[c] + eqb[c]);
        af_o[(size_t)row * DIM + c] = __float2bfloat16((fv[i] - m2) * rs2 * efw[c] + efb[c]);
    }
}

// ---------------- generic LN (fp32 in -> bf16 out) ----------------
__global__ void ln_kernel(const float* __restrict__ xin, const float* __restrict__ w,
                          const float* __restrict__ bws, bf16* __restrict__ yo)
{
    int row = blockIdx.x;
    int tid = threadIdx.x;                // 128
    float x[3]; float s = 0.f, ss = 0.f;
    #pragma unroll
    for (int i = 0; i < 3; i++) {
        int c = tid + i * 128;
        x[i] = xin[(size_t)row * DIM + c];
        s += x[i]; ss += x[i] * x[i];
    }
    float2 r = block_sum2(s, ss);
    float m  = r.x * (1.f / DIM);
    float rs = rsqrtf(r.y * (1.f / DIM) - m * m + 1e-6f);
    #pragma unroll
    for (int i = 0; i < 3; i++) {
        int c = tid + i * 128;
        yo[(size_t)row * DIM + c] = __float2bfloat16((x[i] - m) * rs * w[c] + bws[c]);
    }
}

// ---------------- bf16 tensor-core GEMM, 128x96 tile, 4 warps (64x48 each) ----
// requires N % 96 == 0, K % 32 == 0. dynamic smem = 51200 B.
template<bool RESID, bool OUTBF>
__global__ void __launch_bounds__(128) gemm_bf16_kernel(
        const bf16* __restrict__ A, const bf16* __restrict__ W,
        const float* __restrict__ bias, const float* __restrict__ resid,
        void* __restrict__ Cout, int M, int N, int K)
{
    constexpr int BM = 128, BN = 96, BK = 32;
    constexpr int AP = 40, BP = 104, CP = 100;
    extern __shared__ __align__(16) char sraw[];
    bf16* As = (bf16*)sraw;                                   // [2][BM*AP]
    bf16* Bs = (bf16*)(sraw + 2 * BM * AP * (int)sizeof(bf16)); // [2][BK*BP]
    float* Cs = (float*)sraw;                                  // [BM][CP]

    int tid = threadIdx.x;
    int wid = tid >> 5, wm = wid & 1, wn = wid >> 1;   // 2 x 2 warps
    int row0 = blockIdx.y * BM, col0 = blockIdx.x * BN;

    // load assignments
    const int arow = tid >> 2,  acq = (tid & 3) * 8;       // A: 4 vec8/thread (rows +32)
    const int brow = tid / 12,  bcq = (tid % 12) * 8;      // B: 3 vec8/thread (rows +~10.67)
    const uint4 z4 = make_uint4(0, 0, 0, 0);

    uint4 ra[4], rb[3];
    #define LDG_TILE(K0) do { \
        _Pragma("unroll") \
        for (int i = 0; i < 4; i++) { \
            int r_ = row0 + arow + i * 32; \
            ra[i] = (r_ < M) ? *(const uint4*)&A[(size_t)r_ * K + (K0) + acq] : z4; \
        } \
        _Pragma("unroll") \
        for (int i = 0; i < 3; i++) { \
            int idx = tid + i * 128; \
            int br_ = idx / 12, bc_ = (idx % 12) * 8; \
            rb[i] = *(const uint4*)&W[(size_t)((K0) + br_) * N + col0 + bc_]; \
        } \
    } while (0)
    #define STS_TILE(BUF) do { \
        _Pragma("unroll") \
        for (int i = 0; i < 4; i++) \
            *(uint4*)&As[(BUF) * BM * AP + (arow + i * 32) * AP + acq] = ra[i]; \
        _Pragma("unroll") \
        for (int i = 0; i < 3; i++) { \
            int idx = tid + i * 128; \
            int br_ = idx / 12, bc_ = (idx % 12) * 8; \
            *(uint4*)&Bs[(BUF) * BK * BP + br_ * BP + bc_] = rb[i]; \
        } \
    } while (0)

    wmma::fragment<wmma::accumulator, 16, 16, 16, float> acc[4][3];
    #pragma unroll
    for (int i = 0; i < 4; i++)
        #pragma unroll
        for (int j = 0; j < 3; j++)
            wmma::fill_fragment(acc[i][j], 0.f);

    const int nk = K / BK;
    LDG_TILE(0);
    STS_TILE(0);
    __syncthreads();

    for (int t = 0; t < nk; t++) {
        if (t + 1 < nk) LDG_TILE((t + 1) * BK);
        const bf16* Ab = As + (t & 1) * BM * AP;
        const bf16* Bb = Bs + (t & 1) * BK * BP;
        #pragma unroll
        for (int ks = 0; ks < 2; ks++) {
            wmma::fragment<wmma::matrix_a, 16, 16, 16, bf16, wmma::row_major> fa[4];
            wmma::fragment<wmma::matrix_b, 16, 16, 16, bf16, wmma::row_major> fb[3];
            #pragma unroll
            for (int i = 0; i < 4; i++)
                wmma::load_matrix_sync(fa[i], &Ab[(wm * 64 + i * 16) * AP + ks * 16], AP);
            #pragma unroll
            for (int j = 0; j < 3; j++)
                wmma::load_matrix_sync(fb[j], &Bb[(ks * 16) * BP + wn * 48 + j * 16], BP);
            #pragma unroll
            for (int i = 0; i < 4; i++)
                #pragma unroll
                for (int j = 0; j < 3; j++)
                    wmma::mma_sync(acc[i][j], fa[i], fb[j], acc[i][j]);
        }
        if (t + 1 < nk) STS_TILE((t + 1) & 1);
        __syncthreads();
    }

    // stage C in shared (reuses AB space), then vectorized epilogue
    #pragma unroll
    for (int i = 0; i < 4; i++)
        #pragma unroll
        for (int j = 0; j < 3; j++)
            wmma::store_matrix_sync(&Cs[(wm * 64 + i * 16) * CP + wn * 48 + j * 16],
                                    acc[i][j], CP, wmma::mem_row_major);
    __syncthreads();
    #pragma unroll
    for (int it = 0; it < 24; it++) {               // 128*96/4 = 3072 float4 / 128 thr
        int idx = tid + it * 128;
        int r = idx / 24, cq = (idx % 24) * 4;
        int gr = row0 + r, gc = col0 + cq;
        if (gr < M) {
            float4 v = *(const float4*)&Cs[r * CP + cq];
            float4 bv = *(const float4*)&bias[gc];
            v.x += bv.x; v.y += bv.y; v.z += bv.z; v.w += bv.w;
            if (RESID) {
                float4 rv = *(const float4*)&resid[(size_t)gr * N + gc];
                v.x += rv.x; v.y += rv.y; v.z += rv.z; v.w += rv.w;
            }
            if (OUTBF) {
                __nv_bfloat162 p0 = __floats2bfloat162_rn(v.x, v.y);
                __nv_bfloat162 p1 = __floats2bfloat162_rn(v.z, v.w);
                *(__nv_bfloat162*)((bf16*)Cout + (size_t)gr * N + gc)     = p0;
                *(__nv_bfloat162*)((bf16*)Cout + (size_t)gr * N + gc + 2) = p1;
            } else {
                *(float4*)((float*)Cout + (size_t)gr * N + gc) = v;
            }
        }
    }
    #undef LDG_TILE
    #undef STS_TILE
}
#define GEMM_SMEM 51200

// ---------------- deformable sampling: branch-free, bf16x2 loads ----------------
__global__ void deform_kernel(const float* __restrict__ offaw,
                              const bf16* __restrict__ value, bf16* __restrict__ out)
{
    int gw   = (blockIdx.x * blockDim.x + threadIdx.x) >> 5;
    int lane = threadIdx.x & 31;
    if (gw >= MROWS * HEADS) return;
    int h  = gw % HEADS;
    int bq = gw / HEADS;
    int q  = bq % NTOK;
    int b  = bq / NTOK;

    float rd, rx, ry;
    {
        int S, loc;
        if (q < NHIGH)        { S = 24; loc = q; }
        else if (q < NMIDEND) { S = 12; loc = q - NHIGH; }
        else                  { S = 6;  loc = q - NMIDEND; }
        int d = loc / (S * S), y = (loc / S) % S, x = loc % S;
        float inv = 1.f / (float)S;
        rd = (d + 0.5f) * inv; ry = (y + 0.5f) * inv; rx = (x + 0.5f) * inv;
    }

    float aw[12];
    {
        const float* ap = offaw + (size_t)bq * 288 + 216 + h * 12;
        float mx = -1e30f;
        #pragma unroll
        for (int j = 0; j < 12; j++) { aw[j] = ap[j]; mx = fmaxf(mx, aw[j]); }
        float se = 0.f;
        #pragma unroll
        for (int j = 0; j < 12; j++) { aw[j] = expf(aw[j] - mx); se += aw[j]; }
        float inv = 1.f / se;
        #pragma unroll
        for (int j = 0; j < 12; j++) aw[j] *= inv;
    }

    const int Ls[3] = {24, 12, 6};
    const int St[3] = {0, NHIGH, NMIDEND};
    const float* offp = offaw + (size_t)bq * 288 + h * 36;
    const bf16* vb    = value + (size_t)b * NTOK * DIM + h * HDIM + lane * 2;

    float accx = 0.f, accy = 0.f;
    #pragma unroll
    for (int l = 0; l < 3; l++) {
        const int S = Ls[l], st = St[l];
        #pragma unroll
        for (int p = 0; p < 4; p++) {
            const float* o = offp + (l * 4 + p) * 3;
            float pd = rd * S + o[0] - 0.5f;
            float px = rx * S + o[1] - 0.5f;
            float py = ry * S + o[2] - 0.5f;
            float fd = floorf(pd), fx = floorf(px), fy = floorf(py);
            int d0 = (int)fd, x0 = (int)fx, y0 = (int)fy;
            int d1 = d0 + 1, x1 = x0 + 1, y1 = y0 + 1;
            float wd1 = pd - fd, wx1 = px - fx, wy1 = py - fy;
            float a = aw[l * 4 + p];
            float wD0 = a * (1.f - wd1) * ((d0 >= 0 && d0 < S) ? 1.f : 0.f);
            float wD1 = a * wd1        * ((d1 >= 0 && d1 < S) ? 1.f : 0.f);
            float wY0 = (1.f - wy1) * ((y0 >= 0 && y0 < S) ? 1.f : 0.f);
            float wY1 = wy1         * ((y1 >= 0 && y1 < S) ? 1.f : 0.f);
            float wX0 = (1.f - wx1) * ((x0 >= 0 && x0 < S) ? 1.f : 0.f);
            float wX1 = wx1         * ((x1 >= 0 && x1 < S) ? 1.f : 0.f);
            int cd0 = min(max(d0, 0), S - 1), cd1 = min(max(d1, 0), S - 1);
            int cy0 = min(max(y0, 0), S - 1), cy1 = min(max(y1, 0), S - 1);
            int cx0 = min(max(x0, 0), S - 1), cx1 = min(max(x1, 0), S - 1);
            int bD0 = st + cd0 * S * S, bD1 = st + cd1 * S * S;
            int rY0 = cy0 * S, rY1 = cy1 * S;
            int i00 = bD0 + rY0, i01 = bD0 + rY1, i10 = bD1 + rY0, i11 = bD1 + rY1;
            float2 v000 = __bfloat1622float2(*(const __nv_bfloat162*)(vb + (size_t)(i00 + cx0) * DIM));
            float2 v001 = __bfloat1622float2(*(const __nv_bfloat162*)(vb + (size_t)(i00 + cx1) * DIM));
            float2 v010 = __bfloat1622float2(*(const __nv_bfloat162*)(vb + (size_t)(i01 + cx0) * DIM));
            float2 v011 = __bfloat1622float2(*(const __nv_bfloat162*)(vb + (size_t)(i01 + cx1) * DIM));
            float2 v100 = __bfloat1622float2(*(const __nv_bfloat162*)(vb + (size_t)(i10 + cx0) * DIM));
            float2 v101 = __bfloat1622float2(*(const __nv_bfloat162*)(vb + (size_t)(i10 + cx1) * DIM));
            float2 v110 = __bfloat1622float2(*(const __nv_bfloat162*)(vb + (size_t)(i11 + cx0) * DIM));
            float2 v111 = __bfloat1622float2(*(const __nv_bfloat162*)(vb + (size_t)(i11 + cx1) * DIM));
            float w000 = wD0 * wY0 * wX0, w001 = wD0 * wY0 * wX1;
            float w010 = wD0 * wY1 * wX0, w011 = wD0 * wY1 * wX1;
            float w100 = wD1 * wY0 * wX0, w101 = wD1 * wY0 * wX1;
            float w110 = wD1 * wY1 * wX0, w111 = wD1 * wY1 * wX1;
            accx += w000 * v000.x + w001 * v001.x + w010 * v010.x + w011 * v011.x
                  + w100 * v100.x + w101 * v101.x + w110 * v110.x + w111 * v111.x;
            accy += w000 * v000.y + w001 * v001.y + w010 * v010.y + w011 * v011.y
                  + w100 * v100.y + w101 * v101.y + w110 * v110.y + w111 * v111.y;
        }
    }
    __nv_bfloat162* op = (__nv_bfloat162*)(out + (size_t)bq * DIM + h * HDIM + lane * 2);
    *op = __floats2bfloat162_rn(accx, accy);
}

// ---------------- depthwise 3x3x3 conv + GELU, 16 voxels/block ----------------
__global__ void __launch_bounds__(384) dwconv_gelu_kernel(
        const bf16* __restrict__ x, const float* __restrict__ w,
        const float* __restrict__ bias, bf16* __restrict__ y)
{
    __shared__ float sw[27 * HID];
    int tid = threadIdx.x;                 // 384
    for (int i = tid; i < 27 * HID; i += 384) sw[i] = w[i];
    __syncthreads();

    int c = tid % HID;
    int g = tid / HID;                     // 0..3
    float bc = bias[c];

    #pragma unroll
    for (int iter = 0; iter < 4; iter++) {
        int vlin = blockIdx.x * 16 + iter * 4 + g;
        int b = vlin / NTOK, v = vlin % NTOK;

        int S, base;
        if (v < NHIGH)        { S = 24; base = 0; }
        else if (v < NMIDEND) { S = 12; base = NHIGH; }
        else                  { S = 6;  base = NMIDEND; }
        int loc = v - base;
        int d = loc / (S * S), yy = (loc / S) % S, xx = loc % S;

        const bf16* xb = x + ((size_t)b * NTOK + base) * HID;
        float acc = bc;
        #pragma unroll
        for (int kd = 0; kd < 3; kd++) {
            int di = d + kd - 1;
            if (di < 0 || di >= S) continue;
            #pragma unroll
            for (int kh = 0; kh < 3; kh++) {
                int yi = yy + kh - 1;
                if (yi < 0 || yi >= S) continue;
                #pragma unroll
                for (int kw = 0; kw < 3; kw++) {
                    int xi = xx + kw - 1;
                    if (xi < 0 || xi >= S) continue;
                    acc += sw[((kd * 3 + kh) * 3 + kw) * HID + c] *
                           __bfloat162float(xb[((size_t)(di * S + yi) * S + xi) * HID + c]);
                }
            }
        }
        float gl = 0.5f * acc * (1.f + erff(acc * 0.70710678118654752f));
        y[((size_t)b * NTOK + v) * HID + c] = __float2bfloat16(gl);
    }
}

// ---------------- launch ----------------
static void* sym_addr(const void* sym) {
    void* p = nullptr;
    cudaGetSymbolAddress(&p, sym);
    return p;
}

extern "C" void kernel_launch(void* const* d_in, const int* in_sizes, int n_in,
                              void* d_out, int out_size)
{
    const float* query = (const float*)d_in[0];
    const float* feat  = (const float*)d_in[2];
    int wb = n_in - 24;
    const float* qnorm_w    = (const float*)d_in[wb + 0];
    const float* qnorm_b    = (const float*)d_in[wb + 1];
    const float* fnorm_w    = (const float*)d_in[wb + 2];
    const float* fnorm_b    = (const float*)d_in[wb + 3];
    const float* ext_qnorm_w= (const float*)d_in[wb + 4];
    const float* ext_qnorm_b= (const float*)d_in[wb + 5];
    const float* ext_fnorm_w= (const float*)d_in[wb + 6];
    const float* ext_fnorm_b= (const float*)d_in[wb + 7];
    const float* ffn_norm_w = (const float*)d_in[wb + 8];
    const float* ffn_norm_b = (const float*)d_in[wb + 9];
    const float* off_w      = (const float*)d_in[wb + 10];
    const float* off_b      = (const float*)d_in[wb + 11];
    const float* aw_w       = (const float*)d_in[wb + 12];
    const float* aw_b       = (const float*)d_in[wb + 13];
    const float* val_w      = (const float*)d_in[wb + 14];
    const float* val_b      = (const float*)d_in[wb + 15];
    const float* out_w      = (const float*)d_in[wb + 16];
    const float* out_b      = (const float*)d_in[wb + 17];
    const float* fc1_w      = (const float*)d_in[wb + 18];
    const float* fc1_b      = (const float*)d_in[wb + 19];
    const float* dw_w       = (const float*)d_in[wb + 20];
    const float* dw_b       = (const float*)d_in[wb + 21];
    const float* fc2_w      = (const float*)d_in[wb + 22];
    const float* fc2_b      = (const float*)d_in[wb + 23];

    float* qn    = (float*)sym_addr(g_qn);
    float* out1  = (float*)sym_addr(g_out1);
    float* offaw = (float*)sym_addr(g_offaw);
    bf16* aqb    = (bf16*)sym_addr(g_aq_b);
    bf16* afb    = (bf16*)sym_addr(g_af_b);
    bf16* valb   = (bf16*)sym_addr(g_val_b);
    bf16* doutb  = (bf16*)sym_addr(g_dout_b);
    bf16* xfb    = (bf16*)sym_addr(g_xf_b);
    bf16* xgb    = (bf16*)sym_addr(g_xg_b);
    bf16* wbf    = (bf16*)sym_addr(g_wb);
    float* outp  = (float*)d_out;

    // opt in to 50 KB dynamic smem for all gemm instantiations (host-side config;
    // not a stream op, safe under graph capture)
    cudaFuncSetAttribute(gemm_bf16_kernel<false, true>,  cudaFuncAttributeMaxDynamicSharedMemorySize, GEMM_SMEM);
    cudaFuncSetAttribute(gemm_bf16_kernel<false, false>, cudaFuncAttributeMaxDynamicSharedMemorySize, GEMM_SMEM);
    cudaFuncSetAttribute(gemm_bf16_kernel<true,  false>, cudaFuncAttributeMaxDynamicSharedMemorySize, GEMM_SMEM);

    const int M = MROWS;
    int gy = (M + 127) / 128;

    // 0) weights -> bf16 (+ interleave off/aw)
    cvt_weights_kernel<<<468, 256>>>(val_w, off_w, aw_w, out_w, fc1_w, fc2_w, wbf);
    // 0b) combined [off|aw] bias staged in out1[0:288] (overwritten by GEMM 5 later)
    cudaMemcpyAsync(out1,       off_b, 216 * sizeof(float), cudaMemcpyDeviceToDevice);
    cudaMemcpyAsync(out1 + 216, aw_b,   72 * sizeof(float), cudaMemcpyDeviceToDevice);
    // 1) q build + LN chain
    prep_kernel<<<M, 128>>>(query, feat, qnorm_w, qnorm_b, fnorm_w, fnorm_b,
                            ext_qnorm_w, ext_qnorm_b, ext_fnorm_w, ext_fnorm_b,
                            qn, aqb, afb);
    // 2) value = af @ val_w + val_b   (bf16 out)
    gemm_bf16_kernel<false, true><<<dim3(4, gy), 128, GEMM_SMEM>>>(afb, wbf + WOFF_VAL, val_b, nullptr, valb, M, 384, 384);
    // 3) offsets+logits = aq @ [off|aw]_w + bias  (fp32 out, N=288)
    gemm_bf16_kernel<false, false><<<dim3(3, gy), 128, GEMM_SMEM>>>(aqb, wbf + WOFF_OFFAW, out1, nullptr, offaw, M, 288, 384);
    // 4) deformable sampling (softmax fused)
    {
        int warps = MROWS * HEADS;
        int blocks = (warps + 7) / 8;
        deform_kernel<<<blocks, 256>>>(offaw, valb, doutb);
    }
    // 5) out1 = qn + dout @ out_w + out_b (fp32)
    gemm_bf16_kernel<true, false><<<dim3(4, gy), 128, GEMM_SMEM>>>(doutb, wbf + WOFF_OUT, out_b, qn, out1, M, 384, 384);
    // 6) t = LN(out1, ffn_norm) -> bf16
    ln_kernel<<<M, 128>>>(out1, ffn_norm_w, ffn_norm_b, aqb);
    // 7) x = t @ fc1_w + fc1_b  (bf16 out)
    gemm_bf16_kernel<false, true><<<dim3(1, gy), 128, GEMM_SMEM>>>(aqb, wbf + WOFF_FC1, fc1_b, nullptr, xfb, M, 96, 384);
    // 8) depthwise conv + GELU (bf16 out)
    dwconv_gelu_kernel<<<MROWS / 16, 384>>>(xfb, dw_w, dw_b, xgb);
    // 9) out = out1 + xg @ fc2_w + fc2_b (fp32)
    gemm_bf16_kernel<true, false><<<dim3(4, gy), 128, GEMM_SMEM>>>(xgb, wbf + WOFF_FC2, fc2_b, out1, outp, M, 384, 96);
}

// round 6
// speedup vs baseline: 2.4092x; 1.0919x over previous
#include <cuda_runtime.h>
#include <cuda_bf16.h>
#include <mma.h>
#include <math.h>

using namespace nvcuda;
typedef __nv_bfloat16 bf16;

// ---------------- problem constants ----------------
#define DIM     384
#define HEADS   6
#define HDIM    64
#define HID     96
#define BB      2
#define NMID    1728
#define NTOK    15768
#define NHIGH   13824
#define NMIDEND 15552
#define MROWS   (BB*NTOK)         // 31536

// weight arena offsets (bf16 elements)
#define WOFF_VAL   0
#define WOFF_OFFAW 147456
#define WOFF_OUT   258048
#define WOFF_FC1   405504
#define WOFF_FC2   442368
#define WTOTAL     479232

// ---------------- scratch (device globals) ----------------
__device__ float g_qn   [(size_t)MROWS*DIM];
__device__ float g_out1 [(size_t)MROWS*DIM];
__device__ float g_offaw[(size_t)MROWS*288];
__device__ bf16  g_aq_b [(size_t)MROWS*DIM];
__device__ bf16  g_af_b [(size_t)MROWS*DIM];
__device__ bf16  g_val_b[(size_t)MROWS*DIM];
__device__ bf16  g_dout_b[(size_t)MROWS*DIM];
__device__ bf16  g_xf_b [(size_t)MROWS*HID];
__device__ bf16  g_xg_b [(size_t)MROWS*HID];
__device__ bf16  g_wb   [WTOTAL];

// ---------------- weight convert (off+aw interleaved to N=288) ----------------
__global__ void cvt_weights_kernel(const float* __restrict__ vw, const float* __restrict__ ow,
                                   const float* __restrict__ aww, const float* __restrict__ outw,
                                   const float* __restrict__ f1w, const float* __restrict__ f2w,
                                   bf16* __restrict__ dst)
{
    int i = blockIdx.x * blockDim.x + threadIdx.x;
    int stride = gridDim.x * blockDim.x;
    for (; i < WTOTAL; i += stride) {
        float v;
        if      (i < WOFF_OFFAW) v = vw[i];
        else if (i < WOFF_OUT) {
            int rel = i - WOFF_OFFAW;
            int k = rel / 288, j = rel % 288;
            v = (j < 216) ? ow[k * 216 + j] : aww[k * 72 + (j - 216)];
        }
        else if (i < WOFF_FC1) v = outw[i - WOFF_OUT];
        else if (i < WOFF_FC2) v = f1w[i - WOFF_FC1];
        else                   v = f2w[i - WOFF_FC2];
        dst[i] = __float2bfloat16(v);
    }
}

// ---------------- helpers ----------------
__device__ __forceinline__ float2 warp_sum2(float a, float b) {
    #pragma unroll
    for (int o = 16; o > 0; o >>= 1) {
        a += __shfl_xor_sync(0xffffffffu, a, o);
        b += __shfl_xor_sync(0xffffffffu, b, o);
    }
    return make_float2(a, b);
}

// ---------------- K1: build q (+feat), fused LN chain — warp per row ----------
__global__ void __launch_bounds__(256) prep_kernel(
        const float* __restrict__ query, const float* __restrict__ feat,
        const float* __restrict__ qw, const float* __restrict__ qb,
        const float* __restrict__ fw, const float* __restrict__ fb,
        const float* __restrict__ eqw, const float* __restrict__ eqb,
        const float* __restrict__ efw, const float* __restrict__ efb,
        float* __restrict__ qn_o, bf16* __restrict__ aq_o, bf16* __restrict__ af_o)
{
    int row = blockIdx.x * 8 + (threadIdx.x >> 5);
    if (row >= MROWS) return;
    int lane = threadIdx.x & 31;
    int b = row / NTOK, t = row % NTOK;

    float x[12];
    float s = 0.f, ss = 0.f;
    const bool addf = (t >= NHIGH && t < NMIDEND);
    const float* qrow = query + (size_t)row * DIM;
    const float* frow = addf ? feat + ((size_t)b * NMID + (t - NHIGH)) * DIM : nullptr;
    #pragma unroll
    for (int i = 0; i < 12; i++) {
        int c = lane + i * 32;
        float v = qrow[c];
        if (addf) v += frow[c];
        x[i] = v; s += v; ss += v * v;
    }
    float2 r = warp_sum2(s, ss);
    float m  = r.x * (1.f / DIM);
    float rs = rsqrtf(r.y * (1.f / DIM) - m * m + 1e-6f);

    float qv[12], fv[12];
    float s1 = 0.f, ss1 = 0.f, s2 = 0.f, ss2 = 0.f;
    #pragma unroll
    for (int i = 0; i < 12; i++) {
        int c = lane + i * 32;
        float xn = (x[i] - m) * rs;
        qv[i] = xn * qw[c] + qb[c];
        fv[i] = xn * fw[c] + fb[c];
        qn_o[(size_t)row * DIM + c] = qv[i];
        s1 += qv[i]; ss1 += qv[i] * qv[i];
        s2 += fv[i]; ss2 += fv[i] * fv[i];
    }
    float2 r1 = warp_sum2(s1, ss1);
    float m1  = r1.x * (1.f / DIM);
    float rs1 = rsqrtf(r1.y * (1.f / DIM) - m1 * m1 + 1e-6f);
    float2 r2 = warp_sum2(s2, ss2);
    float m2  = r2.x * (1.f / DIM);
    float rs2 = rsqrtf(r2.y * (1.f / DIM) - m2 * m2 + 1e-6f);
    #pragma unroll
    for (int i = 0; i < 12; i++) {
        int c = lane + i * 32;
        aq_o[(size_t)row * DIM + c] = __float2bfloat16((qv[i] - m1) * rs1 * eqw[c] + eqb[c]);
        af_o[(size_t)row * DIM + c] = __float2bfloat16((fv[i] - m2) * rs2 * efw[c] + efb[c]);
    }
}

// ---------------- generic LN (fp32 in -> bf16 out) — warp per row ------------
__global__ void __launch_bounds__(256) ln_kernel(
        const float* __restrict__ xin, const float* __restrict__ w,
        const float* __restrict__ bws, bf16* __restrict__ yo)
{
    int row = blockIdx.x * 8 + (threadIdx.x >> 5);
    if (row >= MROWS) return;
    int lane = threadIdx.x & 31;
    float x[12]; float s = 0.f, ss = 0.f;
    const float* xr = xin + (size_t)row * DIM;
    #pragma unroll
    for (int i = 0; i < 12; i++) {
        x[i] = xr[lane + i * 32];
        s += x[i]; ss += x[i] * x[i];
    }
    float2 r = warp_sum2(s, ss);
    float m  = r.x * (1.f / DIM);
    float rs = rsqrtf(r.y * (1.f / DIM) - m * m + 1e-6f);
    #pragma unroll
    for (int i = 0; i < 12; i++) {
        int c = lane + i * 32;
        yo[(size_t)row * DIM + c] = __float2bfloat16((x[i] - m) * rs * w[c] + bws[c]);
    }
}

// ---------------- bf16 tensor-core GEMM, 128x96 tile, 8 warps (32x48 each) ----
// requires N % 96 == 0, K % 32 == 0. dynamic smem = 51200 B.
template<bool RESID, bool OUTBF>
__global__ void __launch_bounds__(256, 2) gemm_bf16_kernel(
        const bf16* __restrict__ A, const bf16* __restrict__ W,
        const float* __restrict__ bias, const float* __restrict__ resid,
        void* __restrict__ Cout, int M, int N, int K)
{
    constexpr int BM = 128, BN = 96, BK = 32;
    constexpr int AP = 40, BP = 104, CP = 100;
    extern __shared__ __align__(16) char sraw[];
    bf16* As = (bf16*)sraw;                                     // [2][BM*AP]
    bf16* Bs = (bf16*)(sraw + 2 * BM * AP * (int)sizeof(bf16)); // [2][BK*BP]
    float* Cs = (float*)sraw;                                    // [BM][CP]

    int tid = threadIdx.x;
    int wid = tid >> 5, wm = wid & 3, wn = wid >> 2;   // 4 x 2 warps, tile 32x48
    int row0 = blockIdx.y * BM, col0 = blockIdx.x * BN;

    // A: 512 vec8, 2/thread; B: 384 vec8, 1.5/thread
    const int arow = tid >> 2, acq = (tid & 3) * 8;
    const int br0 = tid / 12,  bc0 = (tid % 12) * 8;
    const int idx2 = tid + 256;
    const int br1 = idx2 / 12, bc1 = (idx2 % 12) * 8;
    const bool haveB1 = (tid < 128);
    const uint4 z4 = make_uint4(0, 0, 0, 0);

    uint4 ra0, ra1, rb0, rb1;
    #define LDG_TILE(K0) do { \
        int r0_ = row0 + arow, r1_ = row0 + arow + 64; \
        ra0 = (r0_ < M) ? *(const uint4*)&A[(size_t)r0_ * K + (K0) + acq] : z4; \
        ra1 = (r1_ < M) ? *(const uint4*)&A[(size_t)r1_ * K + (K0) + acq] : z4; \
        rb0 = *(const uint4*)&W[(size_t)((K0) + br0) * N + col0 + bc0]; \
        if (haveB1) rb1 = *(const uint4*)&W[(size_t)((K0) + br1) * N + col0 + bc1]; \
    } while (0)
    #define STS_TILE(BUF) do { \
        *(uint4*)&As[(BUF) * BM * AP + arow * AP + acq]        = ra0; \
        *(uint4*)&As[(BUF) * BM * AP + (arow + 64) * AP + acq] = ra1; \
        *(uint4*)&Bs[(BUF) * BK * BP + br0 * BP + bc0]         = rb0; \
        if (haveB1) *(uint4*)&Bs[(BUF) * BK * BP + br1 * BP + bc1] = rb1; \
    } while (0)

    wmma::fragment<wmma::accumulator, 16, 16, 16, float> acc[2][3];
    #pragma unroll
    for (int i = 0; i < 2; i++)
        #pragma unroll
        for (int j = 0; j < 3; j++)
            wmma::fill_fragment(acc[i][j], 0.f);

    const int nk = K / BK;
    LDG_TILE(0);
    STS_TILE(0);
    __syncthreads();

    for (int t = 0; t < nk; t++) {
        if (t + 1 < nk) LDG_TILE((t + 1) * BK);
        const bf16* Ab = As + (t & 1) * BM * AP;
        const bf16* Bb = Bs + (t & 1) * BK * BP;
        #pragma unroll
        for (int ks = 0; ks < 2; ks++) {
            wmma::fragment<wmma::matrix_a, 16, 16, 16, bf16, wmma::row_major> fa[2];
            wmma::fragment<wmma::matrix_b, 16, 16, 16, bf16, wmma::row_major> fb[3];
            #pragma unroll
            for (int i = 0; i < 2; i++)
                wmma::load_matrix_sync(fa[i], &Ab[(wm * 32 + i * 16) * AP + ks * 16], AP);
            #pragma unroll
            for (int j = 0; j < 3; j++)
                wmma::load_matrix_sync(fb[j], &Bb[(ks * 16) * BP + wn * 48 + j * 16], BP);
            #pragma unroll
            for (int i = 0; i < 2; i++)
                #pragma unroll
                for (int j = 0; j < 3; j++)
                    wmma::mma_sync(acc[i][j], fa[i], fb[j], acc[i][j]);
        }
        if (t + 1 < nk) STS_TILE((t + 1) & 1);
        __syncthreads();
    }

    // stage C in shared (reuses AB space), then vectorized epilogue
    #pragma unroll
    for (int i = 0; i < 2; i++)
        #pragma unroll
        for (int j = 0; j < 3; j++)
            wmma::store_matrix_sync(&Cs[(wm * 32 + i * 16) * CP + wn * 48 + j * 16],
                                    acc[i][j], CP, wmma::mem_row_major);
    __syncthreads();
    #pragma unroll
    for (int it = 0; it < 12; it++) {               // 128*96/4 = 3072 float4 / 256 thr
        int idx = tid + it * 256;
        int r = idx / 24, cq = (idx % 24) * 4;
        int gr = row0 + r, gc = col0 + cq;
        if (gr < M) {
            float4 v = *(const float4*)&Cs[r * CP + cq];
            float4 bv = *(const float4*)&bias[gc];
            v.x += bv.x; v.y += bv.y; v.z += bv.z; v.w += bv.w;
            if (RESID) {
                float4 rv = *(const float4*)&resid[(size_t)gr * N + gc];
                v.x += rv.x; v.y += rv.y; v.z += rv.z; v.w += rv.w;
            }
            if (OUTBF) {
                __nv_bfloat162 p0 = __floats2bfloat162_rn(v.x, v.y);
                __nv_bfloat162 p1 = __floats2bfloat162_rn(v.z, v.w);
                *(__nv_bfloat162*)((bf16*)Cout + (size_t)gr * N + gc)     = p0;
                *(__nv_bfloat162*)((bf16*)Cout + (size_t)gr * N + gc + 2) = p1;
            } else {
                *(float4*)((float*)Cout + (size_t)gr * N + gc) = v;
            }
        }
    }
    #undef LDG_TILE
    #undef STS_TILE
}
#define GEMM_SMEM 51200

// ---------------- deformable sampling: branch-free, bf16x2 loads ----------------
__global__ void deform_kernel(const float* __restrict__ offaw,
                              const bf16* __restrict__ value, bf16* __restrict__ out)
{
    int gw   = (blockIdx.x * blockDim.x + threadIdx.x) >> 5;
    int lane = threadIdx.x & 31;
    if (gw >= MROWS * HEADS) return;
    int h  = gw % HEADS;
    int bq = gw / HEADS;
    int q  = bq % NTOK;
    int b  = bq / NTOK;

    float rd, rx, ry;
    {
        int S, loc;
        if (q < NHIGH)        { S = 24; loc = q; }
        else if (q < NMIDEND) { S = 12; loc = q - NHIGH; }
        else                  { S = 6;  loc = q - NMIDEND; }
        int d = loc / (S * S), y = (loc / S) % S, x = loc % S;
        float inv = 1.f / (float)S;
        rd = (d + 0.5f) * inv; ry = (y + 0.5f) * inv; rx = (x + 0.5f) * inv;
    }

    float aw[12];
    {
        const float* ap = offaw + (size_t)bq * 288 + 216 + h * 12;
        float mx = -1e30f;
        #pragma unroll
        for (int j = 0; j < 12; j++) { aw[j] = ap[j]; mx = fmaxf(mx, aw[j]); }
        float se = 0.f;
        #pragma unroll
        for (int j = 0; j < 12; j++) { aw[j] = expf(aw[j] - mx); se += aw[j]; }
        float inv = 1.f / se;
        #pragma unroll
        for (int j = 0; j < 12; j++) aw[j] *= inv;
    }

    const int Ls[3] = {24, 12, 6};
    const int St[3] = {0, NHIGH, NMIDEND};
    const float* offp = offaw + (size_t)bq * 288 + h * 36;
    const bf16* vb    = value + (size_t)b * NTOK * DIM + h * HDIM + lane * 2;

    float accx = 0.f, accy = 0.f;
    #pragma unroll
    for (int l = 0; l < 3; l++) {
        const int S = Ls[l], st = St[l];
        #pragma unroll
        for (int p = 0; p < 4; p++) {
            const float* o = offp + (l * 4 + p) * 3;
            float pd = rd * S + o[0] - 0.5f;
            float px = rx * S + o[1] - 0.5f;
            float py = ry * S + o[2] - 0.5f;
            float fd = floorf(pd), fx = floorf(px), fy = floorf(py);
            int d0 = (int)fd, x0 = (int)fx, y0 = (int)fy;
            int d1 = d0 + 1, x1 = x0 + 1, y1 = y0 + 1;
            float wd1 = pd - fd, wx1 = px - fx, wy1 = py - fy;
            float a = aw[l * 4 + p];
            float wD0 = a * (1.f - wd1) * ((d0 >= 0 && d0 < S) ? 1.f : 0.f);
            float wD1 = a * wd1        * ((d1 >= 0 && d1 < S) ? 1.f : 0.f);
            float wY0 = (1.f - wy1) * ((y0 >= 0 && y0 < S) ? 1.f : 0.f);
            float wY1 = wy1         * ((y1 >= 0 && y1 < S) ? 1.f : 0.f);
            float wX0 = (1.f - wx1) * ((x0 >= 0 && x0 < S) ? 1.f : 0.f);
            float wX1 = wx1         * ((x1 >= 0 && x1 < S) ? 1.f : 0.f);
            int cd0 = min(max(d0, 0), S - 1), cd1 = min(max(d1, 0), S - 1);
            int cy0 = min(max(y0, 0), S - 1), cy1 = min(max(y1, 0), S - 1);
            int cx0 = min(max(x0, 0), S - 1), cx1 = min(max(x1, 0), S - 1);
            int bD0 = st + cd0 * S * S, bD1 = st + cd1 * S * S;
            int rY0 = cy0 * S, rY1 = cy1 * S;
            int i00 = bD0 + rY0, i01 = bD0 + rY1, i10 = bD1 + rY0, i11 = bD1 + rY1;
            float2 v000 = __bfloat1622float2(*(const __nv_bfloat162*)(vb + (size_t)(i00 + cx0) * DIM));
            float2 v001 = __bfloat1622float2(*(const __nv_bfloat162*)(vb + (size_t)(i00 + cx1) * DIM));
            float2 v010 = __bfloat1622float2(*(const __nv_bfloat162*)(vb + (size_t)(i01 + cx0) * DIM));
            float2 v011 = __bfloat1622float2(*(const __nv_bfloat162*)(vb + (size_t)(i01 + cx1) * DIM));
            float2 v100 = __bfloat1622float2(*(const __nv_bfloat162*)(vb + (size_t)(i10 + cx0) * DIM));
            float2 v101 = __bfloat1622float2(*(const __nv_bfloat162*)(vb + (size_t)(i10 + cx1) * DIM));
            float2 v110 = __bfloat1622float2(*(const __nv_bfloat162*)(vb + (size_t)(i11 + cx0) * DIM));
            float2 v111 = __bfloat1622float2(*(const __nv_bfloat162*)(vb + (size_t)(i11 + cx1) * DIM));
            float w000 = wD0 * wY0 * wX0, w001 = wD0 * wY0 * wX1;
            float w010 = wD0 * wY1 * wX0, w011 = wD0 * wY1 * wX1;
            float w100 = wD1 * wY0 * wX0, w101 = wD1 * wY0 * wX1;
            float w110 = wD1 * wY1 * wX0, w111 = wD1 * wY1 * wX1;
            accx += w000 * v000.x + w001 * v001.x + w010 * v010.x + w011 * v011.x
                  + w100 * v100.x + w101 * v101.x + w110 * v110.x + w111 * v111.x;
            accy += w000 * v000.y + w001 * v001.y + w010 * v010.y + w011 * v011.y
                  + w100 * v100.y + w101 * v101.y + w110 * v110.y + w111 * v111.y;
        }
    }
    __nv_bfloat162* op = (__nv_bfloat162*)(out + (size_t)bq * DIM + h * HDIM + lane * 2);
    *op = __floats2bfloat162_rn(accx, accy);
}

// ---------------- depthwise 3x3x3 conv + GELU, 16 voxels/block ----------------
__global__ void __launch_bounds__(384) dwconv_gelu_kernel(
        const bf16* __restrict__ x, const float* __restrict__ w,
        const float* __restrict__ bias, bf16* __restrict__ y)
{
    __shared__ float sw[27 * HID];
    int tid = threadIdx.x;                 // 384
    for (int i = tid; i < 27 * HID; i += 384) sw[i] = w[i];
    __syncthreads();

    int c = tid % HID;
    int g = tid / HID;                     // 0..3
    float bc = bias[c];

    #pragma unroll
    for (int iter = 0; iter < 4; iter++) {
        int vlin = blockIdx.x * 16 + iter * 4 + g;
        int b = vlin / NTOK, v = vlin % NTOK;

        int S, base;
        if (v < NHIGH)        { S = 24; base = 0; }
        else if (v < NMIDEND) { S = 12; base = NHIGH; }
        else                  { S = 6;  base = NMIDEND; }
        int loc = v - base;
        int d = loc / (S * S), yy = (loc / S) % S, xx = loc % S;

        const bf16* xb = x + ((size_t)b * NTOK + base) * HID;
        float acc = bc;
        #pragma unroll
        for (int kd = 0; kd < 3; kd++) {
            int di = d + kd - 1;
            if (di < 0 || di >= S) continue;
            #pragma unroll
            for (int kh = 0; kh < 3; kh++) {
                int yi = yy + kh - 1;
                if (yi < 0 || yi >= S) continue;
                #pragma unroll
                for (int kw = 0; kw < 3; kw++) {
                    int xi = xx + kw - 1;
                    if (xi < 0 || xi >= S) continue;
                    acc += sw[((kd * 3 + kh) * 3 + kw) * HID + c] *
                           __bfloat162float(xb[((size_t)(di * S + yi) * S + xi) * HID + c]);
                }
            }
        }
        float gl = 0.5f * acc * (1.f + erff(acc * 0.70710678118654752f));
        y[((size_t)b * NTOK + v) * HID + c] = __float2bfloat16(gl);
    }
}

// ---------------- launch ----------------
static void* sym_addr(const void* sym) {
    void* p = nullptr;
    cudaGetSymbolAddress(&p, sym);
    return p;
}

extern "C" void kernel_launch(void* const* d_in, const int* in_sizes, int n_in,
                              void* d_out, int out_size)
{
    const float* query = (const float*)d_in[0];
    const float* feat  = (const float*)d_in[2];
    int wb = n_in - 24;
    const float* qnorm_w    = (const float*)d_in[wb + 0];
    const float* qnorm_b    = (const float*)d_in[wb + 1];
    const float* fnorm_w    = (const float*)d_in[wb + 2];
    const float* fnorm_b    = (const float*)d_in[wb + 3];
    const float* ext_qnorm_w= (const float*)d_in[wb + 4];
    const float* ext_qnorm_b= (const float*)d_in[wb + 5];
    const float* ext_fnorm_w= (const float*)d_in[wb + 6];
    const float* ext_fnorm_b= (const float*)d_in[wb + 7];
    const float* ffn_norm_w = (const float*)d_in[wb + 8];
    const float* ffn_norm_b = (const float*)d_in[wb + 9];
    const float* off_w      = (const float*)d_in[wb + 10];
    const float* off_b      = (const float*)d_in[wb + 11];
    const float* aw_w       = (const float*)d_in[wb + 12];
    const float* aw_b       = (const float*)d_in[wb + 13];
    const float* val_w      = (const float*)d_in[wb + 14];
    const float* val_b      = (const float*)d_in[wb + 15];
    const float* out_w      = (const float*)d_in[wb + 16];
    const float* out_b      = (const float*)d_in[wb + 17];
    const float* fc1_w      = (const float*)d_in[wb + 18];
    const float* fc1_b      = (const float*)d_in[wb + 19];
    const float* dw_w       = (const float*)d_in[wb + 20];
    const float* dw_b       = (const float*)d_in[wb + 21];
    const float* fc2_w      = (const float*)d_in[wb + 22];
    const float* fc2_b      = (const float*)d_in[wb + 23];

    float* qn    = (float*)sym_addr(g_qn);
    float* out1  = (float*)sym_addr(g_out1);
    float* offaw = (float*)sym_addr(g_offaw);
    bf16* aqb    = (bf16*)sym_addr(g_aq_b);
    bf16* afb    = (bf16*)sym_addr(g_af_b);
    bf16* valb   = (bf16*)sym_addr(g_val_b);
    bf16* doutb  = (bf16*)sym_addr(g_dout_b);
    bf16* xfb    = (bf16*)sym_addr(g_xf_b);
    bf16* xgb    = (bf16*)sym_addr(g_xg_b);
    bf16* wbf    = (bf16*)sym_addr(g_wb);
    float* outp  = (float*)d_out;

    cudaFuncSetAttribute(gemm_bf16_kernel<false, true>,  cudaFuncAttributeMaxDynamicSharedMemorySize, GEMM_SMEM);
    cudaFuncSetAttribute(gemm_bf16_kernel<false, false>, cudaFuncAttributeMaxDynamicSharedMemorySize, GEMM_SMEM);
    cudaFuncSetAttribute(gemm_bf16_kernel<true,  false>, cudaFuncAttributeMaxDynamicSharedMemorySize, GEMM_SMEM);

    const int M = MROWS;
    int gy = (M + 127) / 128;
    int grow = (M + 7) / 8;

    // 0) weights -> bf16 (+ interleave off/aw)
    cvt_weights_kernel<<<468, 256>>>(val_w, off_w, aw_w, out_w, fc1_w, fc2_w, wbf);
    // 0b) combined [off|aw] bias staged in out1[0:288] (overwritten by GEMM 5 later)
    cudaMemcpyAsync(out1,       off_b, 216 * sizeof(float), cudaMemcpyDeviceToDevice);
    cudaMemcpyAsync(out1 + 216, aw_b,   72 * sizeof(float), cudaMemcpyDeviceToDevice);
    // 1) q build + LN chain (warp per row)
    prep_kernel<<<grow, 256>>>(query, feat, qnorm_w, qnorm_b, fnorm_w, fnorm_b,
                               ext_qnorm_w, ext_qnorm_b, ext_fnorm_w, ext_fnorm_b,
                               qn, aqb, afb);
    // 2) value = af @ val_w + val_b   (bf16 out)
    gemm_bf16_kernel<false, true><<<dim3(4, gy), 256, GEMM_SMEM>>>(afb, wbf + WOFF_VAL, val_b, nullptr, valb, M, 384, 384);
    // 3) offsets+logits = aq @ [off|aw]_w + bias  (fp32 out, N=288)
    gemm_bf16_kernel<false, false><<<dim3(3, gy), 256, GEMM_SMEM>>>(aqb, wbf + WOFF_OFFAW, out1, nullptr, offaw, M, 288, 384);
    // 4) deformable sampling (softmax fused)
    {
        int warps = MROWS * HEADS;
        int blocks = (warps + 7) / 8;
        deform_kernel<<<blocks, 256>>>(offaw, valb, doutb);
    }
    // 5) out1 = qn + dout @ out_w + out_b (fp32)
    gemm_bf16_kernel<true, false><<<dim3(4, gy), 256, GEMM_SMEM>>>(doutb, wbf + WOFF_OUT, out_b, qn, out1, M, 384, 384);
    // 6) t = LN(out1, ffn_norm) -> bf16
    ln_kernel<<<grow, 256>>>(out1, ffn_norm_w, ffn_norm_b, aqb);
    // 7) x = t @ fc1_w + fc1_b  (bf16 out)
    gemm_bf16_kernel<false, true><<<dim3(1, gy), 256, GEMM_SMEM>>>(aqb, wbf + WOFF_FC1, fc1_b, nullptr, xfb, M, 96, 384);
    // 8) depthwise conv + GELU (bf16 out)
    dwconv_gelu_kernel<<<MROWS / 16, 384>>>(xfb, dw_w, dw_b, xgb);
    // 9) out = out1 + xg @ fc2_w + fc2_b (fp32)
    gemm_bf16_kernel<true, false><<<dim3(4, gy), 256, GEMM_SMEM>>>(xgb, wbf + WOFF_FC2, fc2_b, out1, outp, M, 384, 96);
}

// round 9
// speedup vs baseline: 2.7815x; 1.1545x over previous
#include <cstdint>
#include <cstddef>
#include <cuda_runtime.h>
#include <cuda_bf16.h>
#include <mma.h>
#include <math.h>

using namespace nvcuda;
typedef __nv_bfloat16 bf16;

// ---------------- problem constants ----------------
#define DIM     384
#define HEADS   6
#define HDIM    64
#define HID     96
#define BB      2
#define NMID    1728
#define NTOK    15768
#define NHIGH   13824
#define NMIDEND 15552
#define MROWS   (BB*NTOK)         // 31536

// weight arena offsets (bf16 elements), [K,N] layout (off+aw interleaved to N=288)
#define WOFF_VAL   0
#define WOFF_OFFAW 147456
#define WOFF_OUT   258048
#define WOFF_FC1   405504
#define WOFF_FC2   442368
#define WTOTAL     479232

// ---------------- scratch (device globals) ----------------
__device__ float g_qn   [(size_t)MROWS*DIM];
__device__ float g_out1 [(size_t)MROWS*DIM];
__device__ float g_offaw[(size_t)MROWS*288];
__device__ bf16  g_aq_b [(size_t)MROWS*DIM];
__device__ bf16  g_af_b [(size_t)MROWS*DIM];
__device__ bf16  g_val_b[(size_t)MROWS*DIM];
__device__ bf16  g_dout_b[(size_t)MROWS*DIM];
__device__ bf16  g_xf_b [(size_t)MROWS*HID];
__device__ bf16  g_xg_b [(size_t)MROWS*HID];
__device__ bf16  g_wb   [WTOTAL];

// ---------------- weight convert (off+aw interleaved to N=288) ----------------
__global__ void cvt_weights_kernel(const float* __restrict__ vw, const float* __restrict__ ow,
                                   const float* __restrict__ aww, const float* __restrict__ outw,
                                   const float* __restrict__ f1w, const float* __restrict__ f2w,
                                   bf16* __restrict__ dst)
{
    int i = blockIdx.x * blockDim.x + threadIdx.x;
    int stride = gridDim.x * blockDim.x;
    for (; i < WTOTAL; i += stride) {
        float v;
        if      (i < WOFF_OFFAW) v = vw[i];
        else if (i < WOFF_OUT) {
            int rel = i - WOFF_OFFAW;
            int k = rel / 288, j = rel % 288;
            v = (j < 216) ? ow[k * 216 + j] : aww[k * 72 + (j - 216)];
        }
        else if (i < WOFF_FC1) v = outw[i - WOFF_OUT];
        else if (i < WOFF_FC2) v = f1w[i - WOFF_FC1];
        else                   v = f2w[i - WOFF_FC2];
        dst[i] = __float2bfloat16(v);
    }
}

// ---------------- helpers ----------------
__device__ __forceinline__ float2 warp_sum2(float a, float b) {
    #pragma unroll
    for (int o = 16; o > 0; o >>= 1) {
        a += __shfl_xor_sync(0xffffffffu, a, o);
        b += __shfl_xor_sync(0xffffffffu, b, o);
    }
    return make_float2(a, b);
}
__device__ __forceinline__ uint32_t pack_bf16x2(float a, float b) {
    __nv_bfloat162 p = __floats2bfloat162_rn(a, b);
    return *reinterpret_cast<uint32_t*>(&p);
}

// ---------------- K1: build q (+feat), fused LN chain — warp per row, float4 ----
__global__ void __launch_bounds__(256) prep_kernel(
        const float* __restrict__ query, const float* __restrict__ feat,
        const float* __restrict__ qw, const float* __restrict__ qb,
        const float* __restrict__ fw, const float* __restrict__ fb,
        const float* __restrict__ eqw, const float* __restrict__ eqb,
        const float* __restrict__ efw, const float* __restrict__ efb,
        float* __restrict__ qn_o, bf16* __restrict__ aq_o, bf16* __restrict__ af_o)
{
    int row = blockIdx.x * 8 + (threadIdx.x >> 5);
    if (row >= MROWS) return;
    int lane = threadIdx.x & 31;
    int b = row / NTOK, t = row % NTOK;

    float x[12];
    float s = 0.f, ss = 0.f;
    const bool addf = (t >= NHIGH && t < NMIDEND);
    const float* qrow = query + (size_t)row * DIM;
    const float* frow = addf ? feat + ((size_t)b * NMID + (t - NHIGH)) * DIM : nullptr;
    #pragma unroll
    for (int i = 0; i < 3; i++) {
        int c = (lane + i * 32) * 4;
        float4 v = *(const float4*)&qrow[c];
        if (addf) {
            float4 f = *(const float4*)&frow[c];
            v.x += f.x; v.y += f.y; v.z += f.z; v.w += f.w;
        }
        x[i*4+0] = v.x; x[i*4+1] = v.y; x[i*4+2] = v.z; x[i*4+3] = v.w;
        s += v.x + v.y + v.z + v.w;
        ss += v.x*v.x + v.y*v.y + v.z*v.z + v.w*v.w;
    }
    float2 r = warp_sum2(s, ss);
    float m  = r.x * (1.f / DIM);
    float rs = rsqrtf(r.y * (1.f / DIM) - m * m + 1e-6f);

    float qv[12], fv[12];
    float s1 = 0.f, ss1 = 0.f, s2 = 0.f, ss2 = 0.f;
    #pragma unroll
    for (int i = 0; i < 3; i++) {
        int c = (lane + i * 32) * 4;
        float4 qwv = *(const float4*)&qw[c];
        float4 qbv = *(const float4*)&qb[c];
        float4 fwv = *(const float4*)&fw[c];
        float4 fbv = *(const float4*)&fb[c];
        float4 o;
        #pragma unroll
        for (int j = 0; j < 4; j++) {
            float xn = (x[i*4+j] - m) * rs;
            float qq = xn * ((&qwv.x)[j]) + ((&qbv.x)[j]);
            float ff = xn * ((&fwv.x)[j]) + ((&fbv.x)[j]);
            qv[i*4+j] = qq; fv[i*4+j] = ff;
            (&o.x)[j] = qq;
            s1 += qq; ss1 += qq*qq;
            s2 += ff; ss2 += ff*ff;
        }
        *(float4*)&qn_o[(size_t)row * DIM + c] = o;
    }
    float2 r1 = warp_sum2(s1, ss1);
    float m1  = r1.x * (1.f / DIM);
    float rs1 = rsqrtf(r1.y * (1.f / DIM) - m1 * m1 + 1e-6f);
    float2 r2 = warp_sum2(s2, ss2);
    float m2  = r2.x * (1.f / DIM);
    float rs2 = rsqrtf(r2.y * (1.f / DIM) - m2 * m2 + 1e-6f);
    #pragma unroll
    for (int i = 0; i < 3; i++) {
        int c = (lane + i * 32) * 4;
        float4 ewv = *(const float4*)&eqw[c];
        float4 ebv = *(const float4*)&eqb[c];
        float4 fwv = *(const float4*)&efw[c];
        float4 fbv = *(const float4*)&efb[c];
        float aqv[4], afv[4];
        #pragma unroll
        for (int j = 0; j < 4; j++) {
            aqv[j] = (qv[i*4+j] - m1) * rs1 * ((&ewv.x)[j]) + ((&ebv.x)[j]);
            afv[j] = (fv[i*4+j] - m2) * rs2 * ((&fwv.x)[j]) + ((&fbv.x)[j]);
        }
        uint2 pa, pf;
        pa.x = pack_bf16x2(aqv[0], aqv[1]); pa.y = pack_bf16x2(aqv[2], aqv[3]);
        pf.x = pack_bf16x2(afv[0], afv[1]); pf.y = pack_bf16x2(afv[2], afv[3]);
        *(uint2*)&aq_o[(size_t)row * DIM + c] = pa;
        *(uint2*)&af_o[(size_t)row * DIM + c] = pf;
    }
}

// ---------------- generic LN (fp32 in -> bf16 out) — warp per row, float4 -----
__global__ void __launch_bounds__(256) ln_kernel(
        const float* __restrict__ xin, const float* __restrict__ w,
        const float* __restrict__ bws, bf16* __restrict__ yo)
{
    int row = blockIdx.x * 8 + (threadIdx.x >> 5);
    if (row >= MROWS) return;
    int lane = threadIdx.x & 31;
    float x[12]; float s = 0.f, ss = 0.f;
    const float* xr = xin + (size_t)row * DIM;
    #pragma unroll
    for (int i = 0; i < 3; i++) {
        int c = (lane + i * 32) * 4;
        float4 v = *(const float4*)&xr[c];
        x[i*4+0] = v.x; x[i*4+1] = v.y; x[i*4+2] = v.z; x[i*4+3] = v.w;
        s += v.x + v.y + v.z + v.w;
        ss += v.x*v.x + v.y*v.y + v.z*v.z + v.w*v.w;
    }
    float2 r = warp_sum2(s, ss);
    float m  = r.x * (1.f / DIM);
    float rs = rsqrtf(r.y * (1.f / DIM) - m * m + 1e-6f);
    #pragma unroll
    for (int i = 0; i < 3; i++) {
        int c = (lane + i * 32) * 4;
        float4 wv = *(const float4*)&w[c];
        float4 bv = *(const float4*)&bws[c];
        float y0 = (x[i*4+0] - m) * rs * wv.x + bv.x;
        float y1 = (x[i*4+1] - m) * rs * wv.y + bv.y;
        float y2 = (x[i*4+2] - m) * rs * wv.z + bv.z;
        float y3 = (x[i*4+3] - m) * rs * wv.w + bv.w;
        uint2 p;
        p.x = pack_bf16x2(y0, y1); p.y = pack_bf16x2(y2, y3);
        *(uint2*)&yo[(size_t)row * DIM + c] = p;
    }
}

// ---------------- bf16 wmma GEMM, 128x96 tile, 8 warps (32x48 each) ----------
// requires N % 96 == 0, K % 32 == 0. dynamic smem = 51200 B.
template<bool RESID, bool OUTBF>
__global__ void __launch_bounds__(256, 2) gemm_bf16_kernel(
        const bf16* __restrict__ A, const bf16* __restrict__ W,
        const float* __restrict__ bias, const float* __restrict__ resid,
        void* __restrict__ Cout, int M, int N, int K)
{
    constexpr int BM = 128, BN = 96, BK = 32;
    constexpr int AP = 40, BP = 104, CP = 100;
    extern __shared__ __align__(16) char sraw[];
    bf16* As = (bf16*)sraw;
    bf16* Bs = (bf16*)(sraw + 2 * BM * AP * (int)sizeof(bf16));
    float* Cs = (float*)sraw;

    int tid = threadIdx.x;
    int wid = tid >> 5, wm = wid & 3, wn = wid >> 2;
    int row0 = blockIdx.y * BM, col0 = blockIdx.x * BN;

    const int arow = tid >> 2, acq = (tid & 3) * 8;
    const int br0 = tid / 12,  bc0 = (tid % 12) * 8;
    const int idx2 = tid + 256;
    const int br1 = idx2 / 12, bc1 = (idx2 % 12) * 8;
    const bool haveB1 = (tid < 128);
    const uint4 z4 = make_uint4(0, 0, 0, 0);

    uint4 ra0, ra1, rb0, rb1;
    #define LDG_TILE(K0) do { \
        int r0_ = row0 + arow, r1_ = row0 + arow + 64; \
        ra0 = (r0_ < M) ? *(const uint4*)&A[(size_t)r0_ * K + (K0) + acq] : z4; \
        ra1 = (r1_ < M) ? *(const uint4*)&A[(size_t)r1_ * K + (K0) + acq] : z4; \
        rb0 = *(const uint4*)&W[(size_t)((K0) + br0) * N + col0 + bc0]; \
        if (haveB1) rb1 = *(const uint4*)&W[(size_t)((K0) + br1) * N + col0 + bc1]; \
    } while (0)
    #define STS_TILE(BUF) do { \
        *(uint4*)&As[(BUF) * BM * AP + arow * AP + acq]        = ra0; \
        *(uint4*)&As[(BUF) * BM * AP + (arow + 64) * AP + acq] = ra1; \
        *(uint4*)&Bs[(BUF) * BK * BP + br0 * BP + bc0]         = rb0; \
        if (haveB1) *(uint4*)&Bs[(BUF) * BK * BP + br1 * BP + bc1] = rb1; \
    } while (0)

    wmma::fragment<wmma::accumulator, 16, 16, 16, float> acc[2][3];
    #pragma unroll
    for (int i = 0; i < 2; i++)
        #pragma unroll
        for (int j = 0; j < 3; j++)
            wmma::fill_fragment(acc[i][j], 0.f);

    const int nk = K / BK;
    LDG_TILE(0);
    STS_TILE(0);
    __syncthreads();

    for (int t = 0; t < nk; t++) {
        if (t + 1 < nk) LDG_TILE((t + 1) * BK);
        const bf16* Ab = As + (t & 1) * BM * AP;
        const bf16* Bb = Bs + (t & 1) * BK * BP;
        #pragma unroll
        for (int ks = 0; ks < 2; ks++) {
            wmma::fragment<wmma::matrix_a, 16, 16, 16, bf16, wmma::row_major> fa[2];
            wmma::fragment<wmma::matrix_b, 16, 16, 16, bf16, wmma::row_major> fb[3];
            #pragma unroll
            for (int i = 0; i < 2; i++)
                wmma::load_matrix_sync(fa[i], &Ab[(wm * 32 + i * 16) * AP + ks * 16], AP);
            #pragma unroll
            for (int j = 0; j < 3; j++)
                wmma::load_matrix_sync(fb[j], &Bb[(ks * 16) * BP + wn * 48 + j * 16], BP);
            #pragma unroll
            for (int i = 0; i < 2; i++)
                #pragma unroll
                for (int j = 0; j < 3; j++)
                    wmma::mma_sync(acc[i][j], fa[i], fb[j], acc[i][j]);
        }
        if (t + 1 < nk) STS_TILE((t + 1) & 1);
        __syncthreads();
    }

    #pragma unroll
    for (int i = 0; i < 2; i++)
        #pragma unroll
        for (int j = 0; j < 3; j++)
            wmma::store_matrix_sync(&Cs[(wm * 32 + i * 16) * CP + wn * 48 + j * 16],
                                    acc[i][j], CP, wmma::mem_row_major);
    __syncthreads();
    #pragma unroll
    for (int it = 0; it < 12; it++) {
        int idx = tid + it * 256;
        int r = idx / 24, cq = (idx % 24) * 4;
        int gr = row0 + r, gc = col0 + cq;
        if (gr < M) {
            float4 v = *(const float4*)&Cs[r * CP + cq];
            float4 bv = *(const float4*)&bias[gc];
            v.x += bv.x; v.y += bv.y; v.z += bv.z; v.w += bv.w;
            if (RESID) {
                float4 rv = *(const float4*)&resid[(size_t)gr * N + gc];
                v.x += rv.x; v.y += rv.y; v.z += rv.z; v.w += rv.w;
            }
            if (OUTBF) {
                uint2 p;
                p.x = pack_bf16x2(v.x, v.y);
                p.y = pack_bf16x2(v.z, v.w);
                *(uint2*)((bf16*)Cout + (size_t)gr * N + gc) = p;
            } else {
                *(float4*)((float*)Cout + (size_t)gr * N + gc) = v;
            }
        }
    }
    #undef LDG_TILE
    #undef STS_TILE
}
#define GEMM_SMEM 51200

// ---------------- deformable sampling: half-warp pairs, 8B loads --------------
// lane layout: half = lane>>4 (corner parity), lane&15 -> 4 channels each.
__global__ void deform_kernel(const float* __restrict__ offaw,
                              const bf16* __restrict__ value, bf16* __restrict__ out)
{
    int gw   = (blockIdx.x * blockDim.x + threadIdx.x) >> 5;
    int lane = threadIdx.x & 31;
    if (gw >= MROWS * HEADS) return;
    int h  = gw % HEADS;
    int bq = gw / HEADS;
    int q  = bq % NTOK;
    int b  = bq / NTOK;

    float rd, rx, ry;
    {
        int S, loc;
        if (q < NHIGH)        { S = 24; loc = q; }
        else if (q < NMIDEND) { S = 12; loc = q - NHIGH; }
        else                  { S = 6;  loc = q - NMIDEND; }
        int d = loc / (S * S), y = (loc / S) % S, x = loc % S;
        float inv = 1.f / (float)S;
        rd = (d + 0.5f) * inv; ry = (y + 0.5f) * inv; rx = (x + 0.5f) * inv;
    }

    float aw[12];
    {
        const float* ap = offaw + (size_t)bq * 288 + 216 + h * 12;
        float mx = -1e30f;
        #pragma unroll
        for (int j = 0; j < 12; j++) { aw[j] = ap[j]; mx = fmaxf(mx, aw[j]); }
        float se = 0.f;
        #pragma unroll
        for (int j = 0; j < 12; j++) { aw[j] = expf(aw[j] - mx); se += aw[j]; }
        float inv = 1.f / se;
        #pragma unroll
        for (int j = 0; j < 12; j++) aw[j] *= inv;
    }

    const int Ls[3] = {24, 12, 6};
    const int St[3] = {0, NHIGH, NMIDEND};
    const float* offp = offaw + (size_t)bq * 288 + h * 36;
    const int half = lane >> 4;
    const int ch4  = (lane & 15) * 4;
    const bf16* vb = value + (size_t)b * NTOK * DIM + h * HDIM + ch4;

    float a0 = 0.f, a1 = 0.f, a2 = 0.f, a3 = 0.f;
    #pragma unroll
    for (int l = 0; l < 3; l++) {
        const int S = Ls[l], st = St[l];
        #pragma unroll
        for (int p = 0; p < 4; p++) {
            const float* o = offp + (l * 4 + p) * 3;
            float pd = rd * S + o[0] - 0.5f;
            float px = rx * S + o[1] - 0.5f;
            float py = ry * S + o[2] - 0.5f;
            float fd = floorf(pd), fx = floorf(px), fy = floorf(py);
            int d0 = (int)fd, x0 = (int)fx, y0 = (int)fy;
            int d1 = d0 + 1, x1 = x0 + 1, y1 = y0 + 1;
            float wd1 = pd - fd, wx1 = px - fx, wy1 = py - fy;
            float a = aw[l * 4 + p];
            float wD0 = a * (1.f - wd1) * ((d0 >= 0 && d0 < S) ? 1.f : 0.f);
            float wD1 = a * wd1        * ((d1 >= 0 && d1 < S) ? 1.f : 0.f);
            float wY0 = (1.f - wy1) * ((y0 >= 0 && y0 < S) ? 1.f : 0.f);
            float wY1 = wy1         * ((y1 >= 0 && y1 < S) ? 1.f : 0.f);
            float wX0 = (1.f - wx1) * ((x0 >= 0 && x0 < S) ? 1.f : 0.f);
            float wX1 = wx1         * ((x1 >= 0 && x1 < S) ? 1.f : 0.f);
            int cd0 = min(max(d0, 0), S - 1), cd1 = min(max(d1, 0), S - 1);
            int cy0 = min(max(y0, 0), S - 1), cy1 = min(max(y1, 0), S - 1);
            int cx0 = min(max(x0, 0), S - 1), cx1 = min(max(x1, 0), S - 1);
            int bD0 = st + cd0 * S * S, bD1 = st + cd1 * S * S;
            int rY0 = cy0 * S, rY1 = cy1 * S;
            // 8 corners -> 4 pairs; this half-warp takes x0 (half=0) or x1 (half=1)
            int cxs = half ? cx1 : cx0;
            float wxs = half ? wX1 : wX0;
            int i0 = bD0 + rY0 + cxs;       float w0 = wD0 * wY0 * wxs;
            int i1 = bD0 + rY1 + cxs;       float w1 = wD0 * wY1 * wxs;
            int i2 = bD1 + rY0 + cxs;       float w2 = wD1 * wY0 * wxs;
            int i3 = bD1 + rY1 + cxs;       float w3 = wD1 * wY1 * wxs;
            uint2 r0 = *(const uint2*)(vb + (size_t)i0 * DIM);
            uint2 r1 = *(const uint2*)(vb + (size_t)i1 * DIM);
            uint2 r2 = *(const uint2*)(vb + (size_t)i2 * DIM);
            uint2 r3 = *(const uint2*)(vb + (size_t)i3 * DIM);
            float2 v0a = __bfloat1622float2(*(const __nv_bfloat162*)&r0.x);
            float2 v0b = __bfloat1622float2(*(const __nv_bfloat162*)&r0.y);
            float2 v1a = __bfloat1622float2(*(const __nv_bfloat162*)&r1.x);
            float2 v1b = __bfloat1622float2(*(const __nv_bfloat162*)&r1.y);
            float2 v2a = __bfloat1622float2(*(const __nv_bfloat162*)&r2.x);
            float2 v2b = __bfloat1622float2(*(const __nv_bfloat162*)&r2.y);
            float2 v3a = __bfloat1622float2(*(const __nv_bfloat162*)&r3.x);
            float2 v3b = __bfloat1622float2(*(const __nv_bfloat162*)&r3.y);
            a0 += w0 * v0a.x + w1 * v1a.x + w2 * v2a.x + w3 * v3a.x;
            a1 += w0 * v0a.y + w1 * v1a.y + w2 * v2a.y + w3 * v3a.y;
            a2 += w0 * v0b.x + w1 * v1b.x + w2 * v2b.x + w3 * v3b.x;
            a3 += w0 * v0b.y + w1 * v1b.y + w2 * v2b.y + w3 * v3b.y;
        }
    }
    // combine the two half-warps (same channels, different corner parity)
    a0 += __shfl_down_sync(0xffffffffu, a0, 16);
    a1 += __shfl_down_sync(0xffffffffu, a1, 16);
    a2 += __shfl_down_sync(0xffffffffu, a2, 16);
    a3 += __shfl_down_sync(0xffffffffu, a3, 16);
    if (half == 0) {
        uint2 pkt;
        pkt.x = pack_bf16x2(a0, a1);
        pkt.y = pack_bf16x2(a2, a3);
        *(uint2*)(out + (size_t)bq * DIM + h * HDIM + ch4) = pkt;
    }
}

// ---------------- depthwise 3x3x3 conv + GELU: 16 voxels/block, 4ch/thread ----
__global__ void __launch_bounds__(384) dwconv_gelu_kernel(
        const bf16* __restrict__ x, const float* __restrict__ w,
        const float* __restrict__ bias, bf16* __restrict__ y)
{
    __shared__ float sw[27 * HID];
    int tid = threadIdx.x;                 // 384
    for (int i = tid; i < 27 * HID; i += 384) sw[i] = w[i];
    __syncthreads();

    int c4  = (tid % 24) * 4;              // channel group
    int vox = tid / 24;                    // 0..15
    int vlin = blockIdx.x * 16 + vox;
    int b = vlin / NTOK, v = vlin % NTOK;

    int S, base;
    if (v < NHIGH)        { S = 24; base = 0; }
    else if (v < NMIDEND) { S = 12; base = NHIGH; }
    else                  { S = 6;  base = NMIDEND; }
    int loc = v - base;
    int d = loc / (S * S), yy = (loc / S) % S, xx = loc % S;

    const bf16* xb = x + ((size_t)b * NTOK + base) * HID + c4;
    float4 bv = *(const float4*)&bias[c4];
    float a0 = bv.x, a1 = bv.y, a2 = bv.z, a3 = bv.w;
    #pragma unroll
    for (int kd = 0; kd < 3; kd++) {
        int di = d + kd - 1;
        if (di < 0 || di >= S) continue;
        #pragma unroll
        for (int kh = 0; kh < 3; kh++) {
            int yi = yy + kh - 1;
            if (yi < 0 || yi >= S) continue;
            #pragma unroll
            for (int kw = 0; kw < 3; kw++) {
                int xi = xx + kw - 1;
                if (xi < 0 || xi >= S) continue;
                uint2 raw = *(const uint2*)(xb + (size_t)((di * S + yi) * S + xi) * HID);
                float2 va = __bfloat1622float2(*(const __nv_bfloat162*)&raw.x);
                float2 vbb = __bfloat1622float2(*(const __nv_bfloat162*)&raw.y);
                float4 wv = *(const float4*)&sw[((kd * 3 + kh) * 3 + kw) * HID + c4];
                a0 += wv.x * va.x;  a1 += wv.y * va.y;
                a2 += wv.z * vbb.x; a3 += wv.w * vbb.y;
            }
        }
    }
    const float ISQ2 = 0.70710678118654752f;
    float g0 = 0.5f * a0 * (1.f + erff(a0 * ISQ2));
    float g1 = 0.5f * a1 * (1.f + erff(a1 * ISQ2));
    float g2 = 0.5f * a2 * (1.f + erff(a2 * ISQ2));
    float g3 = 0.5f * a3 * (1.f + erff(a3 * ISQ2));
    uint2 pkt;
    pkt.x = pack_bf16x2(g0, g1);
    pkt.y = pack_bf16x2(g2, g3);
    *(uint2*)(y + ((size_t)b * NTOK + v) * HID + c4) = pkt;
}

// ---------------- launch ----------------
static void* sym_addr(const void* sym) {
    void* p = nullptr;
    cudaGetSymbolAddress(&p, sym);
    return p;
}

extern "C" void kernel_launch(void* const* d_in, const int* in_sizes, int n_in,
                              void* d_out, int out_size)
{
    const float* query = (const float*)d_in[0];
    const float* feat  = (const float*)d_in[2];
    int wb = n_in - 24;
    const float* qnorm_w    = (const float*)d_in[wb + 0];
    const float* qnorm_b    = (const float*)d_in[wb + 1];
    const float* fnorm_w    = (const float*)d_in[wb + 2];
    const float* fnorm_b    = (const float*)d_in[wb + 3];
    const float* ext_qnorm_w= (const float*)d_in[wb + 4];
    const float* ext_qnorm_b= (const float*)d_in[wb + 5];
    const float* ext_fnorm_w= (const float*)d_in[wb + 6];
    const float* ext_fnorm_b= (const float*)d_in[wb + 7];
    const float* ffn_norm_w = (const float*)d_in[wb + 8];
    const float* ffn_norm_b = (const float*)d_in[wb + 9];
    const float* off_w      = (const float*)d_in[wb + 10];
    const float* off_b      = (const float*)d_in[wb + 11];
    const float* aw_w       = (const float*)d_in[wb + 12];
    const float* aw_b       = (const float*)d_in[wb + 13];
    const float* val_w      = (const float*)d_in[wb + 14];
    const float* val_b      = (const float*)d_in[wb + 15];
    const float* out_w      = (const float*)d_in[wb + 16];
    const float* out_b      = (const float*)d_in[wb + 17];
    const float* fc1_w      = (const float*)d_in[wb + 18];
    const float* fc1_b      = (const float*)d_in[wb + 19];
    const float* dw_w       = (const float*)d_in[wb + 20];
    const float* dw_b       = (const float*)d_in[wb + 21];
    const float* fc2_w      = (const float*)d_in[wb + 22];
    const float* fc2_b      = (const float*)d_in[wb + 23];

    float* qn    = (float*)sym_addr(g_qn);
    float* out1  = (float*)sym_addr(g_out1);
    float* offaw = (float*)sym_addr(g_offaw);
    bf16* aqb    = (bf16*)sym_addr(g_aq_b);
    bf16* afb    = (bf16*)sym_addr(g_af_b);
    bf16* valb   = (bf16*)sym_addr(g_val_b);
    bf16* doutb  = (bf16*)sym_addr(g_dout_b);
    bf16* xfb    = (bf16*)sym_addr(g_xf_b);
    bf16* xgb    = (bf16*)sym_addr(g_xg_b);
    bf16* wbf    = (bf16*)sym_addr(g_wb);
    float* outp  = (float*)d_out;

    cudaFuncSetAttribute(gemm_bf16_kernel<false, true>,  cudaFuncAttributeMaxDynamicSharedMemorySize, GEMM_SMEM);
    cudaFuncSetAttribute(gemm_bf16_kernel<false, false>, cudaFuncAttributeMaxDynamicSharedMemorySize, GEMM_SMEM);
    cudaFuncSetAttribute(gemm_bf16_kernel<true,  false>, cudaFuncAttributeMaxDynamicSharedMemorySize, GEMM_SMEM);

    const int M = MROWS;
    int gy = (M + 127) / 128;
    int grow = (M + 7) / 8;

    // 0) weights -> bf16 (+ interleave off/aw)
    cvt_weights_kernel<<<468, 256>>>(val_w, off_w, aw_w, out_w, fc1_w, fc2_w, wbf);
    // 0b) combined [off|aw] bias staged in out1[0:288] (overwritten by GEMM 5 later)
    cudaMemcpyAsync(out1,       off_b, 216 * sizeof(float), cudaMemcpyDeviceToDevice);
    cudaMemcpyAsync(out1 + 216, aw_b,   72 * sizeof(float), cudaMemcpyDeviceToDevice);
    // 1) q build + LN chain (warp per row)
    prep_kernel<<<grow, 256>>>(query, feat, qnorm_w, qnorm_b, fnorm_w, fnorm_b,
                               ext_qnorm_w, ext_qnorm_b, ext_fnorm_w, ext_fnorm_b,
                               qn, aqb, afb);
    // 2) value = af @ val_w + val_b   (bf16 out)
    gemm_bf16_kernel<false, true><<<dim3(4, gy), 256, GEMM_SMEM>>>(afb, wbf + WOFF_VAL, val_b, nullptr, valb, M, 384, 384);
    // 3) offsets+logits = aq @ [off|aw]_w + bias  (fp32 out, N=288)
    gemm_bf16_kernel<false, false><<<dim3(3, gy), 256, GEMM_SMEM>>>(aqb, wbf + WOFF_OFFAW, out1, nullptr, offaw, M, 288, 384);
    // 4) deformable sampling (softmax fused)
    {
        int warps = MROWS * HEADS;
        int blocks = (warps + 7) / 8;
        deform_kernel<<<blocks, 256>>>(offaw, valb, doutb);
    }
    // 5) out1 = qn + dout @ out_w + out_b (fp32)
    gemm_bf16_kernel<true, false><<<dim3(4, gy), 256, GEMM_SMEM>>>(doutb, wbf + WOFF_OUT, out_b, qn, out1, M, 384, 384);
    // 6) t = LN(out1, ffn_norm) -> bf16
    ln_kernel<<<grow, 256>>>(out1, ffn_norm_w, ffn_norm_b, aqb);
    // 7) x = t @ fc1_w + fc1_b  (bf16 out)
    gemm_bf16_kernel<false, true><<<dim3(1, gy), 256, GEMM_SMEM>>>(aqb, wbf + WOFF_FC1, fc1_b, nullptr, xfb, M, 96, 384);
    // 8) depthwise conv + GELU (bf16 out)
    dwconv_gelu_kernel<<<MROWS / 16, 384>>>(xfb, dw_w, dw_b, xgb);
    // 9) out = out1 + xg @ fc2_w + fc2_b (fp32)
    gemm_bf16_kernel<true, false><<<dim3(4, gy), 256, GEMM_SMEM>>>(xgb, wbf + WOFF_FC2, fc2_b, out1, outp, M, 384, 96);
}

// round 10
// speedup vs baseline: 3.1862x; 1.1455x over previous
#include <cstdint>
#include <cstddef>
#include <cuda_runtime.h>
#include <cuda_bf16.h>
#include <mma.h>
#include <math.h>

using namespace nvcuda;
typedef __nv_bfloat16 bf16;

// ---------------- problem constants ----------------
#define DIM     384
#define HEADS   6
#define HDIM    64
#define HID     96
#define BB      2
#define NMID    1728
#define NTOK    15768
#define NHIGH   13824
#define NMIDEND 15552
#define MROWS   (BB*NTOK)         // 31536

// weight arena offsets (bf16 elements), [K,N] layout (off+aw interleaved to N=288)
#define WOFF_VAL   0
#define WOFF_OFFAW 147456
#define WOFF_OUT   258048
#define WOFF_FC1   405504
#define WOFF_FC2   442368
#define WTOTAL     479232

// ---------------- scratch (device globals) ----------------
__device__ float g_qn   [(size_t)MROWS*DIM];
__device__ float g_out1 [(size_t)MROWS*DIM];
__device__ float g_offaw[(size_t)MROWS*288];
__device__ bf16  g_aq_b [(size_t)MROWS*DIM];
__device__ bf16  g_af_b [(size_t)MROWS*DIM];
__device__ bf16  g_val_b[(size_t)MROWS*DIM];
__device__ bf16  g_dout_b[(size_t)MROWS*DIM];
__device__ bf16  g_xf_b [(size_t)MROWS*HID];
__device__ bf16  g_xg_b [(size_t)MROWS*HID];
__device__ bf16  g_wb   [WTOTAL];

// ---------------- weight convert (off+aw interleaved to N=288) ----------------
__global__ void cvt_weights_kernel(const float* __restrict__ vw, const float* __restrict__ ow,
                                   const float* __restrict__ aww, const float* __restrict__ outw,
                                   const float* __restrict__ f1w, const float* __restrict__ f2w,
                                   bf16* __restrict__ dst)
{
    int i = blockIdx.x * blockDim.x + threadIdx.x;
    int stride = gridDim.x * blockDim.x;
    for (; i < WTOTAL; i += stride) {
        float v;
        if      (i < WOFF_OFFAW) v = vw[i];
        else if (i < WOFF_OUT) {
            int rel = i - WOFF_OFFAW;
            int k = rel / 288, j = rel % 288;
            v = (j < 216) ? ow[k * 216 + j] : aww[k * 72 + (j - 216)];
        }
        else if (i < WOFF_FC1) v = outw[i - WOFF_OUT];
        else if (i < WOFF_FC2) v = f1w[i - WOFF_FC1];
        else                   v = f2w[i - WOFF_FC2];
        dst[i] = __float2bfloat16(v);
    }
}

// ---------------- helpers ----------------
__device__ __forceinline__ float2 warp_sum2(float a, float b) {
    #pragma unroll
    for (int o = 16; o > 0; o >>= 1) {
        a += __shfl_xor_sync(0xffffffffu, a, o);
        b += __shfl_xor_sync(0xffffffffu, b, o);
    }
    return make_float2(a, b);
}
__device__ __forceinline__ uint32_t pack_bf16x2(float a, float b) {
    __nv_bfloat162 p = __floats2bfloat162_rn(a, b);
    return *reinterpret_cast<uint32_t*>(&p);
}

// ---------------- K1: build q (+feat), fused LN chain — warp per row, float4 ----
__global__ void __launch_bounds__(256) prep_kernel(
        const float* __restrict__ query, const float* __restrict__ feat,
        const float* __restrict__ qw, const float* __restrict__ qb,
        const float* __restrict__ fw, const float* __restrict__ fb,
        const float* __restrict__ eqw, const float* __restrict__ eqb,
        const float* __restrict__ efw, const float* __restrict__ efb,
        float* __restrict__ qn_o, bf16* __restrict__ aq_o, bf16* __restrict__ af_o)
{
    int row = blockIdx.x * 8 + (threadIdx.x >> 5);
    if (row >= MROWS) return;
    int lane = threadIdx.x & 31;
    int b = row / NTOK, t = row % NTOK;

    float x[12];
    float s = 0.f, ss = 0.f;
    const bool addf = (t >= NHIGH && t < NMIDEND);
    const float* qrow = query + (size_t)row * DIM;
    const float* frow = addf ? feat + ((size_t)b * NMID + (t - NHIGH)) * DIM : nullptr;
    #pragma unroll
    for (int i = 0; i < 3; i++) {
        int c = (lane + i * 32) * 4;
        float4 v = *(const float4*)&qrow[c];
        if (addf) {
            float4 f = *(const float4*)&frow[c];
            v.x += f.x; v.y += f.y; v.z += f.z; v.w += f.w;
        }
        x[i*4+0] = v.x; x[i*4+1] = v.y; x[i*4+2] = v.z; x[i*4+3] = v.w;
        s += v.x + v.y + v.z + v.w;
        ss += v.x*v.x + v.y*v.y + v.z*v.z + v.w*v.w;
    }
    float2 r = warp_sum2(s, ss);
    float m  = r.x * (1.f / DIM);
    float rs = rsqrtf(r.y * (1.f / DIM) - m * m + 1e-6f);

    float qv[12], fv[12];
    float s1 = 0.f, ss1 = 0.f, s2 = 0.f, ss2 = 0.f;
    #pragma unroll
    for (int i = 0; i < 3; i++) {
        int c = (lane + i * 32) * 4;
        float4 qwv = *(const float4*)&qw[c];
        float4 qbv = *(const float4*)&qb[c];
        float4 fwv = *(const float4*)&fw[c];
        float4 fbv = *(const float4*)&fb[c];
        float4 o;
        #pragma unroll
        for (int j = 0; j < 4; j++) {
            float xn = (x[i*4+j] - m) * rs;
            float qq = xn * ((&qwv.x)[j]) + ((&qbv.x)[j]);
            float ff = xn * ((&fwv.x)[j]) + ((&fbv.x)[j]);
            qv[i*4+j] = qq; fv[i*4+j] = ff;
            (&o.x)[j] = qq;
            s1 += qq; ss1 += qq*qq;
            s2 += ff; ss2 += ff*ff;
        }
        *(float4*)&qn_o[(size_t)row * DIM + c] = o;
    }
    float2 r1 = warp_sum2(s1, ss1);
    float m1  = r1.x * (1.f / DIM);
    float rs1 = rsqrtf(r1.y * (1.f / DIM) - m1 * m1 + 1e-6f);
    float2 r2 = warp_sum2(s2, ss2);
    float m2  = r2.x * (1.f / DIM);
    float rs2 = rsqrtf(r2.y * (1.f / DIM) - m2 * m2 + 1e-6f);
    #pragma unroll
    for (int i = 0; i < 3; i++) {
        int c = (lane + i * 32) * 4;
        float4 ewv = *(const float4*)&eqw[c];
        float4 ebv = *(const float4*)&eqb[c];
        float4 fwv = *(const float4*)&efw[c];
        float4 fbv = *(const float4*)&efb[c];
        float aqv[4], afv[4];
        #pragma unroll
        for (int j = 0; j < 4; j++) {
            aqv[j] = (qv[i*4+j] - m1) * rs1 * ((&ewv.x)[j]) + ((&ebv.x)[j]);
            afv[j] = (fv[i*4+j] - m2) * rs2 * ((&fwv.x)[j]) + ((&fbv.x)[j]);
        }
        uint2 pa, pf;
        pa.x = pack_bf16x2(aqv[0], aqv[1]); pa.y = pack_bf16x2(aqv[2], aqv[3]);
        pf.x = pack_bf16x2(afv[0], afv[1]); pf.y = pack_bf16x2(afv[2], afv[3]);
        *(uint2*)&aq_o[(size_t)row * DIM + c] = pa;
        *(uint2*)&af_o[(size_t)row * DIM + c] = pf;
    }
}

// ---------------- generic LN (fp32 in -> bf16 out) — warp per row, float4 -----
__global__ void __launch_bounds__(256) ln_kernel(
        const float* __restrict__ xin, const float* __restrict__ w,
        const float* __restrict__ bws, bf16* __restrict__ yo)
{
    int row = blockIdx.x * 8 + (threadIdx.x >> 5);
    if (row >= MROWS) return;
    int lane = threadIdx.x & 31;
    float x[12]; float s = 0.f, ss = 0.f;
    const float* xr = xin + (size_t)row * DIM;
    #pragma unroll
    for (int i = 0; i < 3; i++) {
        int c = (lane + i * 32) * 4;
        float4 v = *(const float4*)&xr[c];
        x[i*4+0] = v.x; x[i*4+1] = v.y; x[i*4+2] = v.z; x[i*4+3] = v.w;
        s += v.x + v.y + v.z + v.w;
        ss += v.x*v.x + v.y*v.y + v.z*v.z + v.w*v.w;
    }
    float2 r = warp_sum2(s, ss);
    float m  = r.x * (1.f / DIM);
    float rs = rsqrtf(r.y * (1.f / DIM) - m * m + 1e-6f);
    #pragma unroll
    for (int i = 0; i < 3; i++) {
        int c = (lane + i * 32) * 4;
        float4 wv = *(const float4*)&w[c];
        float4 bv = *(const float4*)&bws[c];
        float y0 = (x[i*4+0] - m) * rs * wv.x + bv.x;
        float y1 = (x[i*4+1] - m) * rs * wv.y + bv.y;
        float y2 = (x[i*4+2] - m) * rs * wv.z + bv.z;
        float y3 = (x[i*4+3] - m) * rs * wv.w + bv.w;
        uint2 p;
        p.x = pack_bf16x2(y0, y1); p.y = pack_bf16x2(y2, y3);
        *(uint2*)&yo[(size_t)row * DIM + c] = p;
    }
}

// ---------------- bf16 wmma GEMM, 128x96 tile, 8 warps (32x48 each) ----------
template<bool RESID, bool OUTBF>
__global__ void __launch_bounds__(256, 2) gemm_bf16_kernel(
        const bf16* __restrict__ A, const bf16* __restrict__ W,
        const float* __restrict__ bias, const float* __restrict__ resid,
        void* __restrict__ Cout, int M, int N, int K)
{
    constexpr int BM = 128, BN = 96, BK = 32;
    constexpr int AP = 40, BP = 104, CP = 100;
    extern __shared__ __align__(16) char sraw[];
    bf16* As = (bf16*)sraw;
    bf16* Bs = (bf16*)(sraw + 2 * BM * AP * (int)sizeof(bf16));
    float* Cs = (float*)sraw;

    int tid = threadIdx.x;
    int wid = tid >> 5, wm = wid & 3, wn = wid >> 2;
    int row0 = blockIdx.y * BM, col0 = blockIdx.x * BN;

    const int arow = tid >> 2, acq = (tid & 3) * 8;
    const int br0 = tid / 12,  bc0 = (tid % 12) * 8;
    const int idx2 = tid + 256;
    const int br1 = idx2 / 12, bc1 = (idx2 % 12) * 8;
    const bool haveB1 = (tid < 128);
    const uint4 z4 = make_uint4(0, 0, 0, 0);

    uint4 ra0, ra1, rb0, rb1;
    #define LDG_TILE(K0) do { \
        int r0_ = row0 + arow, r1_ = row0 + arow + 64; \
        ra0 = (r0_ < M) ? *(const uint4*)&A[(size_t)r0_ * K + (K0) + acq] : z4; \
        ra1 = (r1_ < M) ? *(const uint4*)&A[(size_t)r1_ * K + (K0) + acq] : z4; \
        rb0 = *(const uint4*)&W[(size_t)((K0) + br0) * N + col0 + bc0]; \
        if (haveB1) rb1 = *(const uint4*)&W[(size_t)((K0) + br1) * N + col0 + bc1]; \
    } while (0)
    #define STS_TILE(BUF) do { \
        *(uint4*)&As[(BUF) * BM * AP + arow * AP + acq]        = ra0; \
        *(uint4*)&As[(BUF) * BM * AP + (arow + 64) * AP + acq] = ra1; \
        *(uint4*)&Bs[(BUF) * BK * BP + br0 * BP + bc0]         = rb0; \
        if (haveB1) *(uint4*)&Bs[(BUF) * BK * BP + br1 * BP + bc1] = rb1; \
    } while (0)

    wmma::fragment<wmma::accumulator, 16, 16, 16, float> acc[2][3];
    #pragma unroll
    for (int i = 0; i < 2; i++)
        #pragma unroll
        for (int j = 0; j < 3; j++)
            wmma::fill_fragment(acc[i][j], 0.f);

    const int nk = K / BK;
    LDG_TILE(0);
    STS_TILE(0);
    __syncthreads();

    for (int t = 0; t < nk; t++) {
        if (t + 1 < nk) LDG_TILE((t + 1) * BK);
        const bf16* Ab = As + (t & 1) * BM * AP;
        const bf16* Bb = Bs + (t & 1) * BK * BP;
        #pragma unroll
        for (int ks = 0; ks < 2; ks++) {
            wmma::fragment<wmma::matrix_a, 16, 16, 16, bf16, wmma::row_major> fa[2];
            wmma::fragment<wmma::matrix_b, 16, 16, 16, bf16, wmma::row_major> fb[3];
            #pragma unroll
            for (int i = 0; i < 2; i++)
                wmma::load_matrix_sync(fa[i], &Ab[(wm * 32 + i * 16) * AP + ks * 16], AP);
            #pragma unroll
            for (int j = 0; j < 3; j++)
                wmma::load_matrix_sync(fb[j], &Bb[(ks * 16) * BP + wn * 48 + j * 16], BP);
            #pragma unroll
            for (int i = 0; i < 2; i++)
                #pragma unroll
                for (int j = 0; j < 3; j++)
                    wmma::mma_sync(acc[i][j], fa[i], fb[j], acc[i][j]);
        }
        if (t + 1 < nk) STS_TILE((t + 1) & 1);
        __syncthreads();
    }

    #pragma unroll
    for (int i = 0; i < 2; i++)
        #pragma unroll
        for (int j = 0; j < 3; j++)
            wmma::store_matrix_sync(&Cs[(wm * 32 + i * 16) * CP + wn * 48 + j * 16],
                                    acc[i][j], CP, wmma::mem_row_major);
    __syncthreads();
    #pragma unroll
    for (int it = 0; it < 12; it++) {
        int idx = tid + it * 256;
        int r = idx / 24, cq = (idx % 24) * 4;
        int gr = row0 + r, gc = col0 + cq;
        if (gr < M) {
            float4 v = *(const float4*)&Cs[r * CP + cq];
            float4 bv = *(const float4*)&bias[gc];
            v.x += bv.x; v.y += bv.y; v.z += bv.z; v.w += bv.w;
            if (RESID) {
                float4 rv = *(const float4*)&resid[(size_t)gr * N + gc];
                v.x += rv.x; v.y += rv.y; v.z += rv.z; v.w += rv.w;
            }
            if (OUTBF) {
                uint2 p;
                p.x = pack_bf16x2(v.x, v.y);
                p.y = pack_bf16x2(v.z, v.w);
                *(uint2*)((bf16*)Cout + (size_t)gr * N + gc) = p;
            } else {
                *(float4*)((float*)Cout + (size_t)gr * N + gc) = v;
            }
        }
    }
    #undef LDG_TILE
    #undef STS_TILE
}
#define GEMM_SMEM 51200

// ---------------- deformable sampling v3: lane-parallel params + shfl --------
// warp = (bq,h). lanes 0..11 compute point params; sampling loop broadcasts.
// half = lane>>4 takes x-corner parity; lane&15 -> 4 channels each.
__global__ void deform_kernel(const float* __restrict__ offaw,
                              const bf16* __restrict__ value, bf16* __restrict__ out)
{
    const unsigned FULL = 0xffffffffu;
    int gw   = (blockIdx.x * blockDim.x + threadIdx.x) >> 5;
    int lane = threadIdx.x & 31;
    if (gw >= MROWS * HEADS) return;
    int h  = gw % HEADS;
    int bq = gw / HEADS;
    int q  = bq % NTOK;
    int b  = bq / NTOK;

    // reference point (order d,x,y)
    float rd, rx, ry;
    {
        int S, loc;
        if (q < NHIGH)        { S = 24; loc = q; }
        else if (q < NMIDEND) { S = 12; loc = q - NHIGH; }
        else                  { S = 6;  loc = q - NMIDEND; }
        int d = loc / (S * S), y = (loc / S) % S, x = loc % S;
        float inv = 1.f / (float)S;
        rd = (d + 0.5f) * inv; ry = (y + 0.5f) * inv; rx = (x + 0.5f) * inv;
    }

    // softmax over 12 logits
    float aw[12];
    {
        const float* ap = offaw + (size_t)bq * 288 + 216 + h * 12;
        float mx = -1e30f;
        #pragma unroll
        for (int j = 0; j < 12; j++) { aw[j] = ap[j]; mx = fmaxf(mx, aw[j]); }
        float se = 0.f;
        #pragma unroll
        for (int j = 0; j < 12; j++) { aw[j] = expf(aw[j] - mx); se += aw[j]; }
        float inv = 1.f / se;
        #pragma unroll
        for (int j = 0; j < 12; j++) aw[j] *= inv;
    }

    // ---- phase 1: lane pp computes params for point pp (pp = min(lane,11)) ----
    float wDY00, wDY01, wDY10, wDY11, wX0, wX1;
    int   iDY00, iDY01, iDY10, iDY11, cx0, cx1;
    {
        int pp = (lane < 12) ? lane : 0;
        int l = pp >> 2;
        int S  = (l == 0) ? 24 : ((l == 1) ? 12 : 6);
        int st = (l == 0) ? 0  : ((l == 1) ? NHIGH : NMIDEND);
        const float* o = offaw + (size_t)bq * 288 + h * 36 + pp * 3;
        float pd = rd * S + o[0] - 0.5f;
        float px = rx * S + o[1] - 0.5f;
        float py = ry * S + o[2] - 0.5f;
        float fd = floorf(pd), fx = floorf(px), fy = floorf(py);
        int d0 = (int)fd, x0 = (int)fx, y0 = (int)fy;
        int d1 = d0 + 1, x1 = x0 + 1, y1 = y0 + 1;
        float wd1 = pd - fd, wx1 = px - fx, wy1 = py - fy;
        float a = aw[pp];
        float wD0 = a * (1.f - wd1) * ((d0 >= 0 && d0 < S) ? 1.f : 0.f);
        float wD1 = a * wd1        * ((d1 >= 0 && d1 < S) ? 1.f : 0.f);
        float wY0 = (1.f - wy1) * ((y0 >= 0 && y0 < S) ? 1.f : 0.f);
        float wY1 = wy1         * ((y1 >= 0 && y1 < S) ? 1.f : 0.f);
        wX0 = (1.f - wx1) * ((x0 >= 0 && x0 < S) ? 1.f : 0.f);
        wX1 = wx1         * ((x1 >= 0 && x1 < S) ? 1.f : 0.f);
        int cd0 = min(max(d0, 0), S - 1), cd1 = min(max(d1, 0), S - 1);
        int cy0 = min(max(y0, 0), S - 1), cy1 = min(max(y1, 0), S - 1);
        cx0 = min(max(x0, 0), S - 1);
        cx1 = min(max(x1, 0), S - 1);
        int bD0 = st + cd0 * S * S, bD1 = st + cd1 * S * S;
        int rY0 = cy0 * S, rY1 = cy1 * S;
        wDY00 = wD0 * wY0; wDY01 = wD0 * wY1;
        wDY10 = wD1 * wY0; wDY11 = wD1 * wY1;
        iDY00 = bD0 + rY0; iDY01 = bD0 + rY1;
        iDY10 = bD1 + rY0; iDY11 = bD1 + rY1;
    }

    // ---- phase 2: broadcast + gather ----
    const int half = lane >> 4;
    const int ch4  = (lane & 15) * 4;
    const bf16* vb = value + (size_t)b * NTOK * DIM + h * HDIM + ch4;

    float a0 = 0.f, a1 = 0.f, a2 = 0.f, a3 = 0.f;
    #pragma unroll
    for (int p = 0; p < 12; p++) {
        float w00 = __shfl_sync(FULL, wDY00, p);
        float w01 = __shfl_sync(FULL, wDY01, p);
        float w10 = __shfl_sync(FULL, wDY10, p);
        float w11 = __shfl_sync(FULL, wDY11, p);
        float wx0 = __shfl_sync(FULL, wX0, p);
        float wx1 = __shfl_sync(FULL, wX1, p);
        int i00 = __shfl_sync(FULL, iDY00, p);
        int i01 = __shfl_sync(FULL, iDY01, p);
        int i10 = __shfl_sync(FULL, iDY10, p);
        int i11 = __shfl_sync(FULL, iDY11, p);
        int c0  = __shfl_sync(FULL, cx0, p);
        int c1  = __shfl_sync(FULL, cx1, p);
        int   cxs = half ? c1 : c0;
        float wxs = half ? wx1 : wx0;

        uint2 r0 = *(const uint2*)(vb + (size_t)(i00 + cxs) * DIM);
        uint2 r1 = *(const uint2*)(vb + (size_t)(i01 + cxs) * DIM);
        uint2 r2 = *(const uint2*)(vb + (size_t)(i10 + cxs) * DIM);
        uint2 r3 = *(const uint2*)(vb + (size_t)(i11 + cxs) * DIM);
        float w0 = w00 * wxs, w1 = w01 * wxs, w2 = w10 * wxs, w3 = w11 * wxs;
        float2 v0a = __bfloat1622float2(*(const __nv_bfloat162*)&r0.x);
        float2 v0b = __bfloat1622float2(*(const __nv_bfloat162*)&r0.y);
        float2 v1a = __bfloat1622float2(*(const __nv_bfloat162*)&r1.x);
        float2 v1b = __bfloat1622float2(*(const __nv_bfloat162*)&r1.y);
        float2 v2a = __bfloat1622float2(*(const __nv_bfloat162*)&r2.x);
        float2 v2b = __bfloat1622float2(*(const __nv_bfloat162*)&r2.y);
        float2 v3a = __bfloat1622float2(*(const __nv_bfloat162*)&r3.x);
        float2 v3b = __bfloat1622float2(*(const __nv_bfloat162*)&r3.y);
        a0 += w0 * v0a.x + w1 * v1a.x + w2 * v2a.x + w3 * v3a.x;
        a1 += w0 * v0a.y + w1 * v1a.y + w2 * v2a.y + w3 * v3a.y;
        a2 += w0 * v0b.x + w1 * v1b.x + w2 * v2b.x + w3 * v3b.x;
        a3 += w0 * v0b.y + w1 * v1b.y + w2 * v2b.y + w3 * v3b.y;
    }
    // combine the two half-warps (same channels, different x-corner parity)
    a0 += __shfl_down_sync(FULL, a0, 16);
    a1 += __shfl_down_sync(FULL, a1, 16);
    a2 += __shfl_down_sync(FULL, a2, 16);
    a3 += __shfl_down_sync(FULL, a3, 16);
    if (half == 0) {
        uint2 pkt;
        pkt.x = pack_bf16x2(a0, a1);
        pkt.y = pack_bf16x2(a2, a3);
        *(uint2*)(out + (size_t)bq * DIM + h * HDIM + ch4) = pkt;
    }
}

// ---------------- depthwise 3x3x3 conv + GELU: 16 voxels/block, 4ch/thread ----
__global__ void __launch_bounds__(384) dwconv_gelu_kernel(
        const bf16* __restrict__ x, const float* __restrict__ w,
        const float* __restrict__ bias, bf16* __restrict__ y)
{
    __shared__ float sw[27 * HID];
    int tid = threadIdx.x;                 // 384
    for (int i = tid; i < 27 * HID; i += 384) sw[i] = w[i];
    __syncthreads();

    int c4  = (tid % 24) * 4;              // channel group
    int vox = tid / 24;                    // 0..15
    int vlin = blockIdx.x * 16 + vox;
    int b = vlin / NTOK, v = vlin % NTOK;

    int S, base;
    if (v < NHIGH)        { S = 24; base = 0; }
    else if (v < NMIDEND) { S = 12; base = NHIGH; }
    else                  { S = 6;  base = NMIDEND; }
    int loc = v - base;
    int d = loc / (S * S), yy = (loc / S) % S, xx = loc % S;

    const bf16* xb = x + ((size_t)b * NTOK + base) * HID + c4;
    float4 bv = *(const float4*)&bias[c4];
    float a0 = bv.x, a1 = bv.y, a2 = bv.z, a3 = bv.w;
    #pragma unroll
    for (int kd = 0; kd < 3; kd++) {
        int di = d + kd - 1;
        if (di < 0 || di >= S) continue;
        #pragma unroll
        for (int kh = 0; kh < 3; kh++) {
            int yi = yy + kh - 1;
            if (yi < 0 || yi >= S) continue;
            #pragma unroll
            for (int kw = 0; kw < 3; kw++) {
                int xi = xx + kw - 1;
                if (xi < 0 || xi >= S) continue;
                uint2 raw = *(const uint2*)(xb + (size_t)((di * S + yi) * S + xi) * HID);
                float2 va = __bfloat1622float2(*(const __nv_bfloat162*)&raw.x);
                float2 vbb = __bfloat1622float2(*(const __nv_bfloat162*)&raw.y);
                float4 wv = *(const float4*)&sw[((kd * 3 + kh) * 3 + kw) * HID + c4];
                a0 += wv.x * va.x;  a1 += wv.y * va.y;
                a2 += wv.z * vbb.x; a3 += wv.w * vbb.y;
            }
        }
    }
    const float ISQ2 = 0.70710678118654752f;
    float g0 = 0.5f * a0 * (1.f + erff(a0 * ISQ2));
    float g1 = 0.5f * a1 * (1.f + erff(a1 * ISQ2));
    float g2 = 0.5f * a2 * (1.f + erff(a2 * ISQ2));
    float g3 = 0.5f * a3 * (1.f + erff(a3 * ISQ2));
    uint2 pkt;
    pkt.x = pack_bf16x2(g0, g1);
    pkt.y = pack_bf16x2(g2, g3);
    *(uint2*)(y + ((size_t)b * NTOK + v) * HID + c4) = pkt;
}

// ---------------- launch ----------------
static void* sym_addr(const void* sym) {
    void* p = nullptr;
    cudaGetSymbolAddress(&p, sym);
    return p;
}

extern "C" void kernel_launch(void* const* d_in, const int* in_sizes, int n_in,
                              void* d_out, int out_size)
{
    const float* query = (const float*)d_in[0];
    const float* feat  = (const float*)d_in[2];
    int wb = n_in - 24;
    const float* qnorm_w    = (const float*)d_in[wb + 0];
    const float* qnorm_b    = (const float*)d_in[wb + 1];
    const float* fnorm_w    = (const float*)d_in[wb + 2];
    const float* fnorm_b    = (const float*)d_in[wb + 3];
    const float* ext_qnorm_w= (const float*)d_in[wb + 4];
    const float* ext_qnorm_b= (const float*)d_in[wb + 5];
    const float* ext_fnorm_w= (const float*)d_in[wb + 6];
    const float* ext_fnorm_b= (const float*)d_in[wb + 7];
    const float* ffn_norm_w = (const float*)d_in[wb + 8];
    const float* ffn_norm_b = (const float*)d_in[wb + 9];
    const float* off_w      = (const float*)d_in[wb + 10];
    const float* off_b      = (const float*)d_in[wb + 11];
    const float* aw_w       = (const float*)d_in[wb + 12];
    const float* aw_b       = (const float*)d_in[wb + 13];
    const float* val_w      = (const float*)d_in[wb + 14];
    const float* val_b      = (const float*)d_in[wb + 15];
    const float* out_w      = (const float*)d_in[wb + 16];
    const float* out_b      = (const float*)d_in[wb + 17];
    const float* fc1_w      = (const float*)d_in[wb + 18];
    const float* fc1_b      = (const float*)d_in[wb + 19];
    const float* dw_w       = (const float*)d_in[wb + 20];
    const float* dw_b       = (const float*)d_in[wb + 21];
    const float* fc2_w      = (const float*)d_in[wb + 22];
    const float* fc2_b      = (const float*)d_in[wb + 23];

    float* qn    = (float*)sym_addr(g_qn);
    float* out1  = (float*)sym_addr(g_out1);
    float* offaw = (float*)sym_addr(g_offaw);
    bf16* aqb    = (bf16*)sym_addr(g_aq_b);
    bf16* afb    = (bf16*)sym_addr(g_af_b);
    bf16* valb   = (bf16*)sym_addr(g_val_b);
    bf16* doutb  = (bf16*)sym_addr(g_dout_b);
    bf16* xfb    = (bf16*)sym_addr(g_xf_b);
    bf16* xgb    = (bf16*)sym_addr(g_xg_b);
    bf16* wbf    = (bf16*)sym_addr(g_wb);
    float* outp  = (float*)d_out;

    cudaFuncSetAttribute(gemm_bf16_kernel<false, true>,  cudaFuncAttributeMaxDynamicSharedMemorySize, GEMM_SMEM);
    cudaFuncSetAttribute(gemm_bf16_kernel<false, false>, cudaFuncAttributeMaxDynamicSharedMemorySize, GEMM_SMEM);
    cudaFuncSetAttribute(gemm_bf16_kernel<true,  false>, cudaFuncAttributeMaxDynamicSharedMemorySize, GEMM_SMEM);

    const int M = MROWS;
    int gy = (M + 127) / 128;
    int grow = (M + 7) / 8;

    // 0) weights -> bf16 (+ interleave off/aw)
    cvt_weights_kernel<<<468, 256>>>(val_w, off_w, aw_w, out_w, fc1_w, fc2_w, wbf);
    // 0b) combined [off|aw] bias staged in out1[0:288] (overwritten by GEMM 5 later)
    cudaMemcpyAsync(out1,       off_b, 216 * sizeof(float), cudaMemcpyDeviceToDevice);
    cudaMemcpyAsync(out1 + 216, aw_b,   72 * sizeof(float), cudaMemcpyDeviceToDevice);
    // 1) q build + LN chain (warp per row)
    prep_kernel<<<grow, 256>>>(query, feat, qnorm_w, qnorm_b, fnorm_w, fnorm_b,
                               ext_qnorm_w, ext_qnorm_b, ext_fnorm_w, ext_fnorm_b,
                               qn, aqb, afb);
    // 2) value = af @ val_w + val_b   (bf16 out)
    gemm_bf16_kernel<false, true><<<dim3(4, gy), 256, GEMM_SMEM>>>(afb, wbf + WOFF_VAL, val_b, nullptr, valb, M, 384, 384);
    // 3) offsets+logits = aq @ [off|aw]_w + bias  (fp32 out, N=288)
    gemm_bf16_kernel<false, false><<<dim3(3, gy), 256, GEMM_SMEM>>>(aqb, wbf + WOFF_OFFAW, out1, nullptr, offaw, M, 288, 384);
    // 4) deformable sampling (softmax fused)
    {
        int warps = MROWS * HEADS;
        int blocks = (warps + 7) / 8;
        deform_kernel<<<blocks, 256>>>(offaw, valb, doutb);
    }
    // 5) out1 = qn + dout @ out_w + out_b (fp32)
    gemm_bf16_kernel<true, false><<<dim3(4, gy), 256, GEMM_SMEM>>>(doutb, wbf + WOFF_OUT, out_b, qn, out1, M, 384, 384);
    // 6) t = LN(out1, ffn_norm) -> bf16
    ln_kernel<<<grow, 256>>>(out1, ffn_norm_w, ffn_norm_b, aqb);
    // 7) x = t @ fc1_w + fc1_b  (bf16 out)
    gemm_bf16_kernel<false, true><<<dim3(1, gy), 256, GEMM_SMEM>>>(aqb, wbf + WOFF_FC1, fc1_b, nullptr, xfb, M, 96, 384);
    // 8) depthwise conv + GELU (bf16 out)
    dwconv_gelu_kernel<<<MROWS / 16, 384>>>(xfb, dw_w, dw_b, xgb);
    // 9) out = out1 + xg @ fc2_w + fc2_b (fp32)
    gemm_bf16_kernel<true, false><<<dim3(4, gy), 256, GEMM_SMEM>>>(xgb, wbf + WOFF_FC2, fc2_b, out1, outp, M, 384, 96);
}

// round 11
// speedup vs baseline: 3.3076x; 1.0381x over previous
#include <cstdint>
#include <cstddef>
#include <cuda_runtime.h>
#include <cuda_bf16.h>
#include <mma.h>
#include <math.h>

using namespace nvcuda;
typedef __nv_bfloat16 bf16;

// ---------------- problem constants ----------------
#define DIM     384
#define HEADS   6
#define HDIM    64
#define HID     96
#define BB      2
#define NMID    1728
#define NTOK    15768
#define NHIGH   13824
#define NMIDEND 15552
#define MROWS   (BB*NTOK)         // 31536

// weight arena offsets (bf16 elements), [K,N] layout (off+aw interleaved to N=288)
#define WOFF_VAL   0
#define WOFF_OFFAW 147456
#define WOFF_OUT   258048
#define WOFF_FC1   405504
#define WOFF_FC2   442368
#define WTOTAL     479232

// ---------------- scratch (device globals) ----------------
__device__ float g_qn   [(size_t)MROWS*DIM];
__device__ float g_out1 [(size_t)MROWS*DIM];
__device__ float g_offaw[(size_t)MROWS*288];
__device__ bf16  g_aq_b [(size_t)MROWS*DIM];
__device__ bf16  g_af_b [(size_t)MROWS*DIM];
__device__ bf16  g_val_b[(size_t)MROWS*DIM];
__device__ bf16  g_dout_b[(size_t)MROWS*DIM];
__device__ bf16  g_xf_b [(size_t)MROWS*HID];
__device__ bf16  g_xg_b [(size_t)MROWS*HID];
__device__ bf16  g_wb   [WTOTAL];

// ---------------- weight convert (off+aw interleaved to N=288) ----------------
__global__ void cvt_weights_kernel(const float* __restrict__ vw, const float* __restrict__ ow,
                                   const float* __restrict__ aww, const float* __restrict__ outw,
                                   const float* __restrict__ f1w, const float* __restrict__ f2w,
                                   bf16* __restrict__ dst)
{
    int i = blockIdx.x * blockDim.x + threadIdx.x;
    int stride = gridDim.x * blockDim.x;
    for (; i < WTOTAL; i += stride) {
        float v;
        if      (i < WOFF_OFFAW) v = vw[i];
        else if (i < WOFF_OUT) {
            int rel = i - WOFF_OFFAW;
            int k = rel / 288, j = rel % 288;
            v = (j < 216) ? ow[k * 216 + j] : aww[k * 72 + (j - 216)];
        }
        else if (i < WOFF_FC1) v = outw[i - WOFF_OUT];
        else if (i < WOFF_FC2) v = f1w[i - WOFF_FC1];
        else                   v = f2w[i - WOFF_FC2];
        dst[i] = __float2bfloat16(v);
    }
}

// ---------------- helpers ----------------
__device__ __forceinline__ float2 warp_sum2(float a, float b) {
    #pragma unroll
    for (int o = 16; o > 0; o >>= 1) {
        a += __shfl_xor_sync(0xffffffffu, a, o);
        b += __shfl_xor_sync(0xffffffffu, b, o);
    }
    return make_float2(a, b);
}
__device__ __forceinline__ uint32_t pack_bf16x2(float a, float b) {
    __nv_bfloat162 p = __floats2bfloat162_rn(a, b);
    return *reinterpret_cast<uint32_t*>(&p);
}

// ---------------- K1: build q (+feat), fused LN chain — warp per row, float4 ----
__global__ void __launch_bounds__(256) prep_kernel(
        const float* __restrict__ query, const float* __restrict__ feat,
        const float* __restrict__ qw, const float* __restrict__ qb,
        const float* __restrict__ fw, const float* __restrict__ fb,
        const float* __restrict__ eqw, const float* __restrict__ eqb,
        const float* __restrict__ efw, const float* __restrict__ efb,
        float* __restrict__ qn_o, bf16* __restrict__ aq_o, bf16* __restrict__ af_o)
{
    int row = blockIdx.x * 8 + (threadIdx.x >> 5);
    if (row >= MROWS) return;
    int lane = threadIdx.x & 31;
    int b = row / NTOK, t = row % NTOK;

    float x[12];
    float s = 0.f, ss = 0.f;
    const bool addf = (t >= NHIGH && t < NMIDEND);
    const float* qrow = query + (size_t)row * DIM;
    const float* frow = addf ? feat + ((size_t)b * NMID + (t - NHIGH)) * DIM : nullptr;
    #pragma unroll
    for (int i = 0; i < 3; i++) {
        int c = (lane + i * 32) * 4;
        float4 v = *(const float4*)&qrow[c];
        if (addf) {
            float4 f = *(const float4*)&frow[c];
            v.x += f.x; v.y += f.y; v.z += f.z; v.w += f.w;
        }
        x[i*4+0] = v.x; x[i*4+1] = v.y; x[i*4+2] = v.z; x[i*4+3] = v.w;
        s += v.x + v.y + v.z + v.w;
        ss += v.x*v.x + v.y*v.y + v.z*v.z + v.w*v.w;
    }
    float2 r = warp_sum2(s, ss);
    float m  = r.x * (1.f / DIM);
    float rs = rsqrtf(r.y * (1.f / DIM) - m * m + 1e-6f);

    float qv[12], fv[12];
    float s1 = 0.f, ss1 = 0.f, s2 = 0.f, ss2 = 0.f;
    #pragma unroll
    for (int i = 0; i < 3; i++) {
        int c = (lane + i * 32) * 4;
        float4 qwv = *(const float4*)&qw[c];
        float4 qbv = *(const float4*)&qb[c];
        float4 fwv = *(const float4*)&fw[c];
        float4 fbv = *(const float4*)&fb[c];
        float4 o;
        #pragma unroll
        for (int j = 0; j < 4; j++) {
            float xn = (x[i*4+j] - m) * rs;
            float qq = xn * ((&qwv.x)[j]) + ((&qbv.x)[j]);
            float ff = xn * ((&fwv.x)[j]) + ((&fbv.x)[j]);
            qv[i*4+j] = qq; fv[i*4+j] = ff;
            (&o.x)[j] = qq;
            s1 += qq; ss1 += qq*qq;
            s2 += ff; ss2 += ff*ff;
        }
        *(float4*)&qn_o[(size_t)row * DIM + c] = o;
    }
    float2 r1 = warp_sum2(s1, ss1);
    float m1  = r1.x * (1.f / DIM);
    float rs1 = rsqrtf(r1.y * (1.f / DIM) - m1 * m1 + 1e-6f);
    float2 r2 = warp_sum2(s2, ss2);
    float m2  = r2.x * (1.f / DIM);
    float rs2 = rsqrtf(r2.y * (1.f / DIM) - m2 * m2 + 1e-6f);
    #pragma unroll
    for (int i = 0; i < 3; i++) {
        int c = (lane + i * 32) * 4;
        float4 ewv = *(const float4*)&eqw[c];
        float4 ebv = *(const float4*)&eqb[c];
        float4 fwv = *(const float4*)&efw[c];
        float4 fbv = *(const float4*)&efb[c];
        float aqv[4], afv[4];
        #pragma unroll
        for (int j = 0; j < 4; j++) {
            aqv[j] = (qv[i*4+j] - m1) * rs1 * ((&ewv.x)[j]) + ((&ebv.x)[j]);
            afv[j] = (fv[i*4+j] - m2) * rs2 * ((&fwv.x)[j]) + ((&fbv.x)[j]);
        }
        uint2 pa, pf;
        pa.x = pack_bf16x2(aqv[0], aqv[1]); pa.y = pack_bf16x2(aqv[2], aqv[3]);
        pf.x = pack_bf16x2(afv[0], afv[1]); pf.y = pack_bf16x2(afv[2], afv[3]);
        *(uint2*)&aq_o[(size_t)row * DIM + c] = pa;
        *(uint2*)&af_o[(size_t)row * DIM + c] = pf;
    }
}

// ---------------- generic LN (fp32 in -> bf16 out) — warp per row, float4 -----
__global__ void __launch_bounds__(256) ln_kernel(
        const float* __restrict__ xin, const float* __restrict__ w,
        const float* __restrict__ bws, bf16* __restrict__ yo)
{
    int row = blockIdx.x * 8 + (threadIdx.x >> 5);
    if (row >= MROWS) return;
    int lane = threadIdx.x & 31;
    float x[12]; float s = 0.f, ss = 0.f;
    const float* xr = xin + (size_t)row * DIM;
    #pragma unroll
    for (int i = 0; i < 3; i++) {
        int c = (lane + i * 32) * 4;
        float4 v = *(const float4*)&xr[c];
        x[i*4+0] = v.x; x[i*4+1] = v.y; x[i*4+2] = v.z; x[i*4+3] = v.w;
        s += v.x + v.y + v.z + v.w;
        ss += v.x*v.x + v.y*v.y + v.z*v.z + v.w*v.w;
    }
    float2 r = warp_sum2(s, ss);
    float m  = r.x * (1.f / DIM);
    float rs = rsqrtf(r.y * (1.f / DIM) - m * m + 1e-6f);
    #pragma unroll
    for (int i = 0; i < 3; i++) {
        int c = (lane + i * 32) * 4;
        float4 wv = *(const float4*)&w[c];
        float4 bv = *(const float4*)&bws[c];
        float y0 = (x[i*4+0] - m) * rs * wv.x + bv.x;
        float y1 = (x[i*4+1] - m) * rs * wv.y + bv.y;
        float y2 = (x[i*4+2] - m) * rs * wv.z + bv.z;
        float y3 = (x[i*4+3] - m) * rs * wv.w + bv.w;
        uint2 p;
        p.x = pack_bf16x2(y0, y1); p.y = pack_bf16x2(y2, y3);
        *(uint2*)&yo[(size_t)row * DIM + c] = p;
    }
}

// ---------------- bf16 wmma GEMM, 128x96 tile, 8 warps (32x48 each) ----------
template<bool RESID, bool OUTBF>
__global__ void __launch_bounds__(256, 2) gemm_bf16_kernel(
        const bf16* __restrict__ A, const bf16* __restrict__ W,
        const float* __restrict__ bias, const float* __restrict__ resid,
        void* __restrict__ Cout, int M, int N, int K)
{
    constexpr int BM = 128, BN = 96, BK = 32;
    constexpr int AP = 40, BP = 104, CP = 100;
    extern __shared__ __align__(16) char sraw[];
    bf16* As = (bf16*)sraw;
    bf16* Bs = (bf16*)(sraw + 2 * BM * AP * (int)sizeof(bf16));
    float* Cs = (float*)sraw;

    int tid = threadIdx.x;
    int wid = tid >> 5, wm = wid & 3, wn = wid >> 2;
    int row0 = blockIdx.y * BM, col0 = blockIdx.x * BN;

    const int arow = tid >> 2, acq = (tid & 3) * 8;
    const int br0 = tid / 12,  bc0 = (tid % 12) * 8;
    const int idx2 = tid + 256;
    const int br1 = idx2 / 12, bc1 = (idx2 % 12) * 8;
    const bool haveB1 = (tid < 128);
    const uint4 z4 = make_uint4(0, 0, 0, 0);

    uint4 ra0, ra1, rb0, rb1;
    #define LDG_TILE(K0) do { \
        int r0_ = row0 + arow, r1_ = row0 + arow + 64; \
        ra0 = (r0_ < M) ? *(const uint4*)&A[(size_t)r0_ * K + (K0) + acq] : z4; \
        ra1 = (r1_ < M) ? *(const uint4*)&A[(size_t)r1_ * K + (K0) + acq] : z4; \
        rb0 = *(const uint4*)&W[(size_t)((K0) + br0) * N + col0 + bc0]; \
        if (haveB1) rb1 = *(const uint4*)&W[(size_t)((K0) + br1) * N + col0 + bc1]; \
    } while (0)
    #define STS_TILE(BUF) do { \
        *(uint4*)&As[(BUF) * BM * AP + arow * AP + acq]        = ra0; \
        *(uint4*)&As[(BUF) * BM * AP + (arow + 64) * AP + acq] = ra1; \
        *(uint4*)&Bs[(BUF) * BK * BP + br0 * BP + bc0]         = rb0; \
        if (haveB1) *(uint4*)&Bs[(BUF) * BK * BP + br1 * BP + bc1] = rb1; \
    } while (0)

    wmma::fragment<wmma::accumulator, 16, 16, 16, float> acc[2][3];
    #pragma unroll
    for (int i = 0; i < 2; i++)
        #pragma unroll
        for (int j = 0; j < 3; j++)
            wmma::fill_fragment(acc[i][j], 0.f);

    const int nk = K / BK;
    LDG_TILE(0);
    STS_TILE(0);
    __syncthreads();

    for (int t = 0; t < nk; t++) {
        if (t + 1 < nk) LDG_TILE((t + 1) * BK);
        const bf16* Ab = As + (t & 1) * BM * AP;
        const bf16* Bb = Bs + (t & 1) * BK * BP;
        #pragma unroll
        for (int ks = 0; ks < 2; ks++) {
            wmma::fragment<wmma::matrix_a, 16, 16, 16, bf16, wmma::row_major> fa[2];
            wmma::fragment<wmma::matrix_b, 16, 16, 16, bf16, wmma::row_major> fb[3];
            #pragma unroll
            for (int i = 0; i < 2; i++)
                wmma::load_matrix_sync(fa[i], &Ab[(wm * 32 + i * 16) * AP + ks * 16], AP);
            #pragma unroll
            for (int j = 0; j < 3; j++)
                wmma::load_matrix_sync(fb[j], &Bb[(ks * 16) * BP + wn * 48 + j * 16], BP);
            #pragma unroll
            for (int i = 0; i < 2; i++)
                #pragma unroll
                for (int j = 0; j < 3; j++)
                    wmma::mma_sync(acc[i][j], fa[i], fb[j], acc[i][j]);
        }
        if (t + 1 < nk) STS_TILE((t + 1) & 1);
        __syncthreads();
    }

    #pragma unroll
    for (int i = 0; i < 2; i++)
        #pragma unroll
        for (int j = 0; j < 3; j++)
            wmma::store_matrix_sync(&Cs[(wm * 32 + i * 16) * CP + wn * 48 + j * 16],
                                    acc[i][j], CP, wmma::mem_row_major);
    __syncthreads();
    #pragma unroll
    for (int it = 0; it < 12; it++) {
        int idx = tid + it * 256;
        int r = idx / 24, cq = (idx % 24) * 4;
        int gr = row0 + r, gc = col0 + cq;
        if (gr < M) {
            float4 v = *(const float4*)&Cs[r * CP + cq];
            float4 bv = *(const float4*)&bias[gc];
            v.x += bv.x; v.y += bv.y; v.z += bv.z; v.w += bv.w;
            if (RESID) {
                float4 rv = *(const float4*)&resid[(size_t)gr * N + gc];
                v.x += rv.x; v.y += rv.y; v.z += rv.z; v.w += rv.w;
            }
            if (OUTBF) {
                uint2 p;
                p.x = pack_bf16x2(v.x, v.y);
                p.y = pack_bf16x2(v.z, v.w);
                *(uint2*)((bf16*)Cout + (size_t)gr * N + gc) = p;
            } else {
                *(float4*)((float*)Cout + (size_t)gr * N + gc) = v;
            }
        }
    }
    #undef LDG_TILE
    #undef STS_TILE
}
#define GEMM_SMEM 51200

// ---------------- deformable sampling v5: corner-parallel uint4 gathers ------
// warp = (bq,h). lanes 0..11 compute point params (phase 1).
// phase 2: cg = lane>>3 -> (d,y) corner combo; (lane&7)*8 -> 8 channels (16B load).
// x-parity handled by 2 sequential iterations. Cross-cg reduce via 2 shfl rounds.
__global__ void deform_kernel(const float* __restrict__ offaw,
                              const bf16* __restrict__ value, bf16* __restrict__ out)
{
    const unsigned FULL = 0xffffffffu;
    int gw   = (blockIdx.x * blockDim.x + threadIdx.x) >> 5;
    int lane = threadIdx.x & 31;
    if (gw >= MROWS * HEADS) return;
    int h  = gw % HEADS;
    int bq = gw / HEADS;
    int q  = bq % NTOK;
    int b  = bq / NTOK;

    // reference point (order d,x,y)
    float rd, rx, ry;
    {
        int S, loc;
        if (q < NHIGH)        { S = 24; loc = q; }
        else if (q < NMIDEND) { S = 12; loc = q - NHIGH; }
        else                  { S = 6;  loc = q - NMIDEND; }
        int d = loc / (S * S), y = (loc / S) % S, x = loc % S;
        float inv = 1.f / (float)S;
        rd = (d + 0.5f) * inv; ry = (y + 0.5f) * inv; rx = (x + 0.5f) * inv;
    }

    // softmax over 12 logits
    float aw[12];
    {
        const float* ap = offaw + (size_t)bq * 288 + 216 + h * 12;
        float mx = -1e30f;
        #pragma unroll
        for (int j = 0; j < 12; j++) { aw[j] = ap[j]; mx = fmaxf(mx, aw[j]); }
        float se = 0.f;
        #pragma unroll
        for (int j = 0; j < 12; j++) { aw[j] = expf(aw[j] - mx); se += aw[j]; }
        float inv = 1.f / se;
        #pragma unroll
        for (int j = 0; j < 12; j++) aw[j] *= inv;
    }

    // ---- phase 1: lane pp computes params for point pp ----
    float wDY00, wDY01, wDY10, wDY11, wX0, wX1;
    int   iDY00, iDY01, iDY10, iDY11, cx0, cx1;
    {
        int pp = (lane < 12) ? lane : 0;
        int l = pp >> 2;
        int S  = (l == 0) ? 24 : ((l == 1) ? 12 : 6);
        int st = (l == 0) ? 0  : ((l == 1) ? NHIGH : NMIDEND);
        const float* o = offaw + (size_t)bq * 288 + h * 36 + pp * 3;
        float pd = rd * S + o[0] - 0.5f;
        float px = rx * S + o[1] - 0.5f;
        float py = ry * S + o[2] - 0.5f;
        float fd = floorf(pd), fx = floorf(px), fy = floorf(py);
        int d0 = (int)fd, x0 = (int)fx, y0 = (int)fy;
        int d1 = d0 + 1, x1 = x0 + 1, y1 = y0 + 1;
        float wd1 = pd - fd, wx1 = px - fx, wy1 = py - fy;
        float a = aw[pp];
        float wD0 = a * (1.f - wd1) * ((d0 >= 0 && d0 < S) ? 1.f : 0.f);
        float wD1 = a * wd1        * ((d1 >= 0 && d1 < S) ? 1.f : 0.f);
        float wY0 = (1.f - wy1) * ((y0 >= 0 && y0 < S) ? 1.f : 0.f);
        float wY1 = wy1         * ((y1 >= 0 && y1 < S) ? 1.f : 0.f);
        wX0 = (1.f - wx1) * ((x0 >= 0 && x0 < S) ? 1.f : 0.f);
        wX1 = wx1         * ((x1 >= 0 && x1 < S) ? 1.f : 0.f);
        int cd0 = min(max(d0, 0), S - 1), cd1 = min(max(d1, 0), S - 1);
        int cy0 = min(max(y0, 0), S - 1), cy1 = min(max(y1, 0), S - 1);
        cx0 = min(max(x0, 0), S - 1);
        cx1 = min(max(x1, 0), S - 1);
        int bD0 = st + cd0 * S * S, bD1 = st + cd1 * S * S;
        int rY0 = cy0 * S, rY1 = cy1 * S;
        wDY00 = wD0 * wY0; wDY01 = wD0 * wY1;
        wDY10 = wD1 * wY0; wDY11 = wD1 * wY1;
        iDY00 = bD0 + rY0; iDY01 = bD0 + rY1;
        iDY10 = bD1 + rY0; iDY11 = bD1 + rY1;
    }

    // ---- phase 2: broadcast + corner-parallel gather ----
    const int cg  = lane >> 3;             // 0..3 = (d,y) corner combo
    const int ch8 = (lane & 7) * 8;        // 8 channels per lane
    const bf16* vb = value + (size_t)b * NTOK * DIM + h * HDIM + ch8;

    float a0 = 0.f, a1 = 0.f, a2 = 0.f, a3 = 0.f;
    float a4 = 0.f, a5 = 0.f, a6 = 0.f, a7 = 0.f;
    #pragma unroll
    for (int p = 0; p < 12; p++) {
        float w00 = __shfl_sync(FULL, wDY00, p);
        float w01 = __shfl_sync(FULL, wDY01, p);
        float w10 = __shfl_sync(FULL, wDY10, p);
        float w11 = __shfl_sync(FULL, wDY11, p);
        int i00 = __shfl_sync(FULL, iDY00, p);
        int i01 = __shfl_sync(FULL, iDY01, p);
        int i10 = __shfl_sync(FULL, iDY10, p);
        int i11 = __shfl_sync(FULL, iDY11, p);
        float wx0 = __shfl_sync(FULL, wX0, p);
        float wx1 = __shfl_sync(FULL, wX1, p);
        int c0  = __shfl_sync(FULL, cx0, p);
        int c1  = __shfl_sync(FULL, cx1, p);
        // per-lane corner select
        float wcg = (cg & 2) ? ((cg & 1) ? w11 : w10) : ((cg & 1) ? w01 : w00);
        int   icg = (cg & 2) ? ((cg & 1) ? i11 : i10) : ((cg & 1) ? i01 : i00);

        // x = 0 parity
        {
            uint4 raw = *(const uint4*)(vb + (size_t)(icg + c0) * DIM);
            float w = wcg * wx0;
            float2 va = __bfloat1622float2(*(const __nv_bfloat162*)&raw.x);
            float2 vb2 = __bfloat1622float2(*(const __nv_bfloat162*)&raw.y);
            float2 vc = __bfloat1622float2(*(const __nv_bfloat162*)&raw.z);
            float2 vd = __bfloat1622float2(*(const __nv_bfloat162*)&raw.w);
            a0 += w * va.x;  a1 += w * va.y;
            a2 += w * vb2.x; a3 += w * vb2.y;
            a4 += w * vc.x;  a5 += w * vc.y;
            a6 += w * vd.x;  a7 += w * vd.y;
        }
        // x = 1 parity
        {
            uint4 raw = *(const uint4*)(vb + (size_t)(icg + c1) * DIM);
            float w = wcg * wx1;
            float2 va = __bfloat1622float2(*(const __nv_bfloat162*)&raw.x);
            float2 vb2 = __bfloat1622float2(*(const __nv_bfloat162*)&raw.y);
            float2 vc = __bfloat1622float2(*(const __nv_bfloat162*)&raw.z);
            float2 vd = __bfloat1622float2(*(const __nv_bfloat162*)&raw.w);
            a0 += w * va.x;  a1 += w * va.y;
            a2 += w * vb2.x; a3 += w * vb2.y;
            a4 += w * vc.x;  a5 += w * vc.y;
            a6 += w * vd.x;  a7 += w * vd.y;
        }
    }
    // reduce across the 4 corner groups: lanes l, l+8, l+16, l+24 share channels
    #pragma unroll
    for (int o = 16; o >= 8; o >>= 1) {
        a0 += __shfl_down_sync(FULL, a0, o);
        a1 += __shfl_down_sync(FULL, a1, o);
        a2 += __shfl_down_sync(FULL, a2, o);
        a3 += __shfl_down_sync(FULL, a3, o);
        a4 += __shfl_down_sync(FULL, a4, o);
        a5 += __shfl_down_sync(FULL, a5, o);
        a6 += __shfl_down_sync(FULL, a6, o);
        a7 += __shfl_down_sync(FULL, a7, o);
    }
    if (lane < 8) {
        uint4 pkt;
        pkt.x = pack_bf16x2(a0, a1);
        pkt.y = pack_bf16x2(a2, a3);
        pkt.z = pack_bf16x2(a4, a5);
        pkt.w = pack_bf16x2(a6, a7);
        *(uint4*)(out + (size_t)bq * DIM + h * HDIM + ch8) = pkt;
    }
}

// ---------------- depthwise 3x3x3 conv + GELU: 16 voxels/block, 4ch/thread ----
__global__ void __launch_bounds__(384) dwconv_gelu_kernel(
        const bf16* __restrict__ x, const float* __restrict__ w,
        const float* __restrict__ bias, bf16* __restrict__ y)
{
    __shared__ float sw[27 * HID];
    int tid = threadIdx.x;                 // 384
    for (int i = tid; i < 27 * HID; i += 384) sw[i] = w[i];
    __syncthreads();

    int c4  = (tid % 24) * 4;              // channel group
    int vox = tid / 24;                    // 0..15
    int vlin = blockIdx.x * 16 + vox;
    int b = vlin / NTOK, v = vlin % NTOK;

    int S, base;
    if (v < NHIGH)        { S = 24; base = 0; }
    else if (v < NMIDEND) { S = 12; base = NHIGH; }
    else                  { S = 6;  base = NMIDEND; }
    int loc = v - base;
    int d = loc / (S * S), yy = (loc / S) % S, xx = loc % S;

    const bf16* xb = x + ((size_t)b * NTOK + base) * HID + c4;
    float4 bv = *(const float4*)&bias[c4];
    float a0 = bv.x, a1 = bv.y, a2 = bv.z, a3 = bv.w;
    #pragma unroll
    for (int kd = 0; kd < 3; kd++) {
        int di = d + kd - 1;
        if (di < 0 || di >= S) continue;
        #pragma unroll
        for (int kh = 0; kh < 3; kh++) {
            int yi = yy + kh - 1;
            if (yi < 0 || yi >= S) continue;
            #pragma unroll
            for (int kw = 0; kw < 3; kw++) {
                int xi = xx + kw - 1;
                if (xi < 0 || xi >= S) continue;
                uint2 raw = *(const uint2*)(xb + (size_t)((di * S + yi) * S + xi) * HID);
                float2 va = __bfloat1622float2(*(const __nv_bfloat162*)&raw.x);
                float2 vbb = __bfloat1622float2(*(const __nv_bfloat162*)&raw.y);
                float4 wv = *(const float4*)&sw[((kd * 3 + kh) * 3 + kw) * HID + c4];
                a0 += wv.x * va.x;  a1 += wv.y * va.y;
                a2 += wv.z * vbb.x; a3 += wv.w * vbb.y;
            }
        }
    }
    const float ISQ2 = 0.70710678118654752f;
    float g0 = 0.5f * a0 * (1.f + erff(a0 * ISQ2));
    float g1 = 0.5f * a1 * (1.f + erff(a1 * ISQ2));
    float g2 = 0.5f * a2 * (1.f + erff(a2 * ISQ2));
    float g3 = 0.5f * a3 * (1.f + erff(a3 * ISQ2));
    uint2 pkt;
    pkt.x = pack_bf16x2(g0, g1);
    pkt.y = pack_bf16x2(g2, g3);
    *(uint2*)(y + ((size_t)b * NTOK + v) * HID + c4) = pkt;
}

// ---------------- launch ----------------
static void* sym_addr(const void* sym) {
    void* p = nullptr;
    cudaGetSymbolAddress(&p, sym);
    return p;
}

extern "C" void kernel_launch(void* const* d_in, const int* in_sizes, int n_in,
                              void* d_out, int out_size)
{
    const float* query = (const float*)d_in[0];
    const float* feat  = (const float*)d_in[2];
    int wb = n_in - 24;
    const float* qnorm_w    = (const float*)d_in[wb + 0];
    const float* qnorm_b    = (const float*)d_in[wb + 1];
    const float* fnorm_w    = (const float*)d_in[wb + 2];
    const float* fnorm_b    = (const float*)d_in[wb + 3];
    const float* ext_qnorm_w= (const float*)d_in[wb + 4];
    const float* ext_qnorm_b= (const float*)d_in[wb + 5];
    const float* ext_fnorm_w= (const float*)d_in[wb + 6];
    const float* ext_fnorm_b= (const float*)d_in[wb + 7];
    const float* ffn_norm_w = (const float*)d_in[wb + 8];
    const float* ffn_norm_b = (const float*)d_in[wb + 9];
    const float* off_w      = (const float*)d_in[wb + 10];
    const float* off_b      = (const float*)d_in[wb + 11];
    const float* aw_w       = (const float*)d_in[wb + 12];
    const float* aw_b       = (const float*)d_in[wb + 13];
    const float* val_w      = (const float*)d_in[wb + 14];
    const float* val_b      = (const float*)d_in[wb + 15];
    const float* out_w      = (const float*)d_in[wb + 16];
    const float* out_b      = (const float*)d_in[wb + 17];
    const float* fc1_w      = (const float*)d_in[wb + 18];
    const float* fc1_b      = (const float*)d_in[wb + 19];
    const float* dw_w       = (const float*)d_in[wb + 20];
    const float* dw_b       = (const float*)d_in[wb + 21];
    const float* fc2_w      = (const float*)d_in[wb + 22];
    const float* fc2_b      = (const float*)d_in[wb + 23];

    float* qn    = (float*)sym_addr(g_qn);
    float* out1  = (float*)sym_addr(g_out1);
    float* offaw = (float*)sym_addr(g_offaw);
    bf16* aqb    = (bf16*)sym_addr(g_aq_b);
    bf16* afb    = (bf16*)sym_addr(g_af_b);
    bf16* valb   = (bf16*)sym_addr(g_val_b);
    bf16* doutb  = (bf16*)sym_addr(g_dout_b);
    bf16* xfb    = (bf16*)sym_addr(g_xf_b);
    bf16* xgb    = (bf16*)sym_addr(g_xg_b);
    bf16* wbf    = (bf16*)sym_addr(g_wb);
    float* outp  = (float*)d_out;

    cudaFuncSetAttribute(gemm_bf16_kernel<false, true>,  cudaFuncAttributeMaxDynamicSharedMemorySize, GEMM_SMEM);
    cudaFuncSetAttribute(gemm_bf16_kernel<false, false>, cudaFuncAttributeMaxDynamicSharedMemorySize, GEMM_SMEM);
    cudaFuncSetAttribute(gemm_bf16_kernel<true,  false>, cudaFuncAttributeMaxDynamicSharedMemorySize, GEMM_SMEM);

    const int M = MROWS;
    int gy = (M + 127) / 128;
    int grow = (M + 7) / 8;

    // 0) weights -> bf16 (+ interleave off/aw)
    cvt_weights_kernel<<<468, 256>>>(val_w, off_w, aw_w, out_w, fc1_w, fc2_w, wbf);
    // 0b) combined [off|aw] bias staged in out1[0:288] (overwritten by GEMM 5 later)
    cudaMemcpyAsync(out1,       off_b, 216 * sizeof(float), cudaMemcpyDeviceToDevice);
    cudaMemcpyAsync(out1 + 216, aw_b,   72 * sizeof(float), cudaMemcpyDeviceToDevice);
    // 1) q build + LN chain (warp per row)
    prep_kernel<<<grow, 256>>>(query, feat, qnorm_w, qnorm_b, fnorm_w, fnorm_b,
                               ext_qnorm_w, ext_qnorm_b, ext_fnorm_w, ext_fnorm_b,
                               qn, aqb, afb);
    // 2) value = af @ val_w + val_b   (bf16 out)
    gemm_bf16_kernel<false, true><<<dim3(4, gy), 256, GEMM_SMEM>>>(afb, wbf + WOFF_VAL, val_b, nullptr, valb, M, 384, 384);
    // 3) offsets+logits = aq @ [off|aw]_w + bias  (fp32 out, N=288)
    gemm_bf16_kernel<false, false><<<dim3(3, gy), 256, GEMM_SMEM>>>(aqb, wbf + WOFF_OFFAW, out1, nullptr, offaw, M, 288, 384);
    // 4) deformable sampling (softmax fused)
    {
        int warps = MROWS * HEADS;
        int blocks = (warps + 7) / 8;
        deform_kernel<<<blocks, 256>>>(offaw, valb, doutb);
    }
    // 5) out1 = qn + dout @ out_w + out_b (fp32)
    gemm_bf16_kernel<true, false><<<dim3(4, gy), 256, GEMM_SMEM>>>(doutb, wbf + WOFF_OUT, out_b, qn, out1, M, 384, 384);
    // 6) t = LN(out1, ffn_norm) -> bf16
    ln_kernel<<<grow, 256>>>(out1, ffn_norm_w, ffn_norm_b, aqb);
    // 7) x = t @ fc1_w + fc1_b  (bf16 out)
    gemm_bf16_kernel<false, true><<<dim3(1, gy), 256, GEMM_SMEM>>>(aqb, wbf + WOFF_FC1, fc1_b, nullptr, xfb, M, 96, 384);
    // 8) depthwise conv + GELU (bf16 out)
    dwconv_gelu_kernel<<<MROWS / 16, 384>>>(xfb, dw_w, dw_b, xgb);
    // 9) out = out1 + xg @ fc2_w + fc2_b (fp32)
    gemm_bf16_kernel<true, false><<<dim3(4, gy), 256, GEMM_SMEM>>>(xgb, wbf + WOFF_FC2, fc2_b, out1, outp, M, 384, 96);
}

// round 12
// speedup vs baseline: 3.4215x; 1.0344x over previous
#include <cstdint>
#include <cstddef>
#include <cuda_runtime.h>
#include <cuda_bf16.h>
#include <mma.h>
#include <math.h>

using namespace nvcuda;
typedef __nv_bfloat16 bf16;

// ---------------- problem constants ----------------
#define DIM     384
#define HEADS   6
#define HDIM    64
#define HID     96
#define BB      2
#define NMID    1728
#define NTOK    15768
#define NHIGH   13824
#define NMIDEND 15552
#define MROWS   (BB*NTOK)         // 31536

// weight arena offsets (bf16 elements), [K,N] layout (off+aw interleaved to N=288)
#define WOFF_VAL   0
#define WOFF_OFFAW 147456
#define WOFF_OUT   258048
#define WOFF_FC1   405504
#define WOFF_FC2   442368
#define WTOTAL     479232

// ---------------- scratch (device globals) ----------------
__device__ float g_qn   [(size_t)MROWS*DIM];
__device__ float g_out1 [(size_t)MROWS*DIM];
__device__ float g_offaw[(size_t)MROWS*288];
__device__ bf16  g_aq_b [(size_t)MROWS*DIM];
__device__ bf16  g_af_b [(size_t)MROWS*DIM];
__device__ bf16  g_val_b[(size_t)MROWS*DIM];
__device__ bf16  g_dout_b[(size_t)MROWS*DIM];
__device__ bf16  g_xf_b [(size_t)MROWS*HID];
__device__ bf16  g_xg_b [(size_t)MROWS*HID];
__device__ bf16  g_wb   [WTOTAL];

// ---------------- weight convert (off+aw interleaved to N=288) ----------------
__global__ void cvt_weights_kernel(const float* __restrict__ vw, const float* __restrict__ ow,
                                   const float* __restrict__ aww, const float* __restrict__ outw,
                                   const float* __restrict__ f1w, const float* __restrict__ f2w,
                                   bf16* __restrict__ dst)
{
    int i = blockIdx.x * blockDim.x + threadIdx.x;
    int stride = gridDim.x * blockDim.x;
    for (; i < WTOTAL; i += stride) {
        float v;
        if      (i < WOFF_OFFAW) v = vw[i];
        else if (i < WOFF_OUT) {
            int rel = i - WOFF_OFFAW;
            int k = rel / 288, j = rel % 288;
            v = (j < 216) ? ow[k * 216 + j] : aww[k * 72 + (j - 216)];
        }
        else if (i < WOFF_FC1) v = outw[i - WOFF_OUT];
        else if (i < WOFF_FC2) v = f1w[i - WOFF_FC1];
        else                   v = f2w[i - WOFF_FC2];
        dst[i] = __float2bfloat16(v);
    }
}

// ---------------- helpers ----------------
__device__ __forceinline__ float2 warp_sum2(float a, float b) {
    #pragma unroll
    for (int o = 16; o > 0; o >>= 1) {
        a += __shfl_xor_sync(0xffffffffu, a, o);
        b += __shfl_xor_sync(0xffffffffu, b, o);
    }
    return make_float2(a, b);
}
__device__ __forceinline__ uint32_t pack_bf16x2(float a, float b) {
    __nv_bfloat162 p = __floats2bfloat162_rn(a, b);
    return *reinterpret_cast<uint32_t*>(&p);
}

// ---------------- K1: build q (+feat), fused LN chain — warp per row, float4 ----
__global__ void __launch_bounds__(256) prep_kernel(
        const float* __restrict__ query, const float* __restrict__ feat,
        const float* __restrict__ qw, const float* __restrict__ qb,
        const float* __restrict__ fw, const float* __restrict__ fb,
        const float* __restrict__ eqw, const float* __restrict__ eqb,
        const float* __restrict__ efw, const float* __restrict__ efb,
        float* __restrict__ qn_o, bf16* __restrict__ aq_o, bf16* __restrict__ af_o)
{
    int row = blockIdx.x * 8 + (threadIdx.x >> 5);
    if (row >= MROWS) return;
    int lane = threadIdx.x & 31;
    int b = row / NTOK, t = row % NTOK;

    float x[12];
    float s = 0.f, ss = 0.f;
    const bool addf = (t >= NHIGH && t < NMIDEND);
    const float* qrow = query + (size_t)row * DIM;
    const float* frow = addf ? feat + ((size_t)b * NMID + (t - NHIGH)) * DIM : nullptr;
    #pragma unroll
    for (int i = 0; i < 3; i++) {
        int c = (lane + i * 32) * 4;
        float4 v = *(const float4*)&qrow[c];
        if (addf) {
            float4 f = *(const float4*)&frow[c];
            v.x += f.x; v.y += f.y; v.z += f.z; v.w += f.w;
        }
        x[i*4+0] = v.x; x[i*4+1] = v.y; x[i*4+2] = v.z; x[i*4+3] = v.w;
        s += v.x + v.y + v.z + v.w;
        ss += v.x*v.x + v.y*v.y + v.z*v.z + v.w*v.w;
    }
    float2 r = warp_sum2(s, ss);
    float m  = r.x * (1.f / DIM);
    float rs = rsqrtf(r.y * (1.f / DIM) - m * m + 1e-6f);

    float qv[12], fv[12];
    float s1 = 0.f, ss1 = 0.f, s2 = 0.f, ss2 = 0.f;
    #pragma unroll
    for (int i = 0; i < 3; i++) {
        int c = (lane + i * 32) * 4;
        float4 qwv = *(const float4*)&qw[c];
        float4 qbv = *(const float4*)&qb[c];
        float4 fwv = *(const float4*)&fw[c];
        float4 fbv = *(const float4*)&fb[c];
        float4 o;
        #pragma unroll
        for (int j = 0; j < 4; j++) {
            float xn = (x[i*4+j] - m) * rs;
            float qq = xn * ((&qwv.x)[j]) + ((&qbv.x)[j]);
            float ff = xn * ((&fwv.x)[j]) + ((&fbv.x)[j]);
            qv[i*4+j] = qq; fv[i*4+j] = ff;
            (&o.x)[j] = qq;
            s1 += qq; ss1 += qq*qq;
            s2 += ff; ss2 += ff*ff;
        }
        *(float4*)&qn_o[(size_t)row * DIM + c] = o;
    }
    float2 r1 = warp_sum2(s1, ss1);
    float m1  = r1.x * (1.f / DIM);
    float rs1 = rsqrtf(r1.y * (1.f / DIM) - m1 * m1 + 1e-6f);
    float2 r2 = warp_sum2(s2, ss2);
    float m2  = r2.x * (1.f / DIM);
    float rs2 = rsqrtf(r2.y * (1.f / DIM) - m2 * m2 + 1e-6f);
    #pragma unroll
    for (int i = 0; i < 3; i++) {
        int c = (lane + i * 32) * 4;
        float4 ewv = *(const float4*)&eqw[c];
        float4 ebv = *(const float4*)&eqb[c];
        float4 fwv = *(const float4*)&efw[c];
        float4 fbv = *(const float4*)&efb[c];
        float aqv[4], afv[4];
        #pragma unroll
        for (int j = 0; j < 4; j++) {
            aqv[j] = (qv[i*4+j] - m1) * rs1 * ((&ewv.x)[j]) + ((&ebv.x)[j]);
            afv[j] = (fv[i*4+j] - m2) * rs2 * ((&fwv.x)[j]) + ((&fbv.x)[j]);
        }
        uint2 pa, pf;
        pa.x = pack_bf16x2(aqv[0], aqv[1]); pa.y = pack_bf16x2(aqv[2], aqv[3]);
        pf.x = pack_bf16x2(afv[0], afv[1]); pf.y = pack_bf16x2(afv[2], afv[3]);
        *(uint2*)&aq_o[(size_t)row * DIM + c] = pa;
        *(uint2*)&af_o[(size_t)row * DIM + c] = pf;
    }
}

// ---------------- generic LN (fp32 in -> bf16 out) — warp per row, float4 -----
__global__ void __launch_bounds__(256) ln_kernel(
        const float* __restrict__ xin, const float* __restrict__ w,
        const float* __restrict__ bws, bf16* __restrict__ yo)
{
    int row = blockIdx.x * 8 + (threadIdx.x >> 5);
    if (row >= MROWS) return;
    int lane = threadIdx.x & 31;
    float x[12]; float s = 0.f, ss = 0.f;
    const float* xr = xin + (size_t)row * DIM;
    #pragma unroll
    for (int i = 0; i < 3; i++) {
        int c = (lane + i * 32) * 4;
        float4 v = *(const float4*)&xr[c];
        x[i*4+0] = v.x; x[i*4+1] = v.y; x[i*4+2] = v.z; x[i*4+3] = v.w;
        s += v.x + v.y + v.z + v.w;
        ss += v.x*v.x + v.y*v.y + v.z*v.z + v.w*v.w;
    }
    float2 r = warp_sum2(s, ss);
    float m  = r.x * (1.f / DIM);
    float rs = rsqrtf(r.y * (1.f / DIM) - m * m + 1e-6f);
    #pragma unroll
    for (int i = 0; i < 3; i++) {
        int c = (lane + i * 32) * 4;
        float4 wv = *(const float4*)&w[c];
        float4 bv = *(const float4*)&bws[c];
        float y0 = (x[i*4+0] - m) * rs * wv.x + bv.x;
        float y1 = (x[i*4+1] - m) * rs * wv.y + bv.y;
        float y2 = (x[i*4+2] - m) * rs * wv.z + bv.z;
        float y3 = (x[i*4+3] - m) * rs * wv.w + bv.w;
        uint2 p;
        p.x = pack_bf16x2(y0, y1); p.y = pack_bf16x2(y2, y3);
        *(uint2*)&yo[(size_t)row * DIM + c] = p;
    }
}

// ---------------- bf16 wmma GEMM, 128x96 tile, 8 warps (32x48 each) ----------
template<bool RESID, bool OUTBF>
__global__ void __launch_bounds__(256, 2) gemm_bf16_kernel(
        const bf16* __restrict__ A, const bf16* __restrict__ W,
        const float* __restrict__ bias, const float* __restrict__ resid,
        void* __restrict__ Cout, int M, int N, int K)
{
    constexpr int BM = 128, BN = 96, BK = 32;
    constexpr int AP = 40, BP = 104, CP = 100;
    extern __shared__ __align__(16) char sraw[];
    bf16* As = (bf16*)sraw;
    bf16* Bs = (bf16*)(sraw + 2 * BM * AP * (int)sizeof(bf16));
    float* Cs = (float*)sraw;

    int tid = threadIdx.x;
    int wid = tid >> 5, wm = wid & 3, wn = wid >> 2;
    int row0 = blockIdx.y * BM, col0 = blockIdx.x * BN;

    const int arow = tid >> 2, acq = (tid & 3) * 8;
    const int br0 = tid / 12,  bc0 = (tid % 12) * 8;
    const int idx2 = tid + 256;
    const int br1 = idx2 / 12, bc1 = (idx2 % 12) * 8;
    const bool haveB1 = (tid < 128);
    const uint4 z4 = make_uint4(0, 0, 0, 0);

    uint4 ra0, ra1, rb0, rb1;
    #define LDG_TILE(K0) do { \
        int r0_ = row0 + arow, r1_ = row0 + arow + 64; \
        ra0 = (r0_ < M) ? *(const uint4*)&A[(size_t)r0_ * K + (K0) + acq] : z4; \
        ra1 = (r1_ < M) ? *(const uint4*)&A[(size_t)r1_ * K + (K0) + acq] : z4; \
        rb0 = *(const uint4*)&W[(size_t)((K0) + br0) * N + col0 + bc0]; \
        if (haveB1) rb1 = *(const uint4*)&W[(size_t)((K0) + br1) * N + col0 + bc1]; \
    } while (0)
    #define STS_TILE(BUF) do { \
        *(uint4*)&As[(BUF) * BM * AP + arow * AP + acq]        = ra0; \
        *(uint4*)&As[(BUF) * BM * AP + (arow + 64) * AP + acq] = ra1; \
        *(uint4*)&Bs[(BUF) * BK * BP + br0 * BP + bc0]         = rb0; \
        if (haveB1) *(uint4*)&Bs[(BUF) * BK * BP + br1 * BP + bc1] = rb1; \
    } while (0)

    wmma::fragment<wmma::accumulator, 16, 16, 16, float> acc[2][3];
    #pragma unroll
    for (int i = 0; i < 2; i++)
        #pragma unroll
        for (int j = 0; j < 3; j++)
            wmma::fill_fragment(acc[i][j], 0.f);

    const int nk = K / BK;
    LDG_TILE(0);
    STS_TILE(0);
    __syncthreads();

    for (int t = 0; t < nk; t++) {
        if (t + 1 < nk) LDG_TILE((t + 1) * BK);
        const bf16* Ab = As + (t & 1) * BM * AP;
        const bf16* Bb = Bs + (t & 1) * BK * BP;
        #pragma unroll
        for (int ks = 0; ks < 2; ks++) {
            wmma::fragment<wmma::matrix_a, 16, 16, 16, bf16, wmma::row_major> fa[2];
            wmma::fragment<wmma::matrix_b, 16, 16, 16, bf16, wmma::row_major> fb[3];
            #pragma unroll
            for (int i = 0; i < 2; i++)
                wmma::load_matrix_sync(fa[i], &Ab[(wm * 32 + i * 16) * AP + ks * 16], AP);
            #pragma unroll
            for (int j = 0; j < 3; j++)
                wmma::load_matrix_sync(fb[j], &Bb[(ks * 16) * BP + wn * 48 + j * 16], BP);
            #pragma unroll
            for (int i = 0; i < 2; i++)
                #pragma unroll
                for (int j = 0; j < 3; j++)
                    wmma::mma_sync(acc[i][j], fa[i], fb[j], acc[i][j]);
        }
        if (t + 1 < nk) STS_TILE((t + 1) & 1);
        __syncthreads();
    }

    #pragma unroll
    for (int i = 0; i < 2; i++)
        #pragma unroll
        for (int j = 0; j < 3; j++)
            wmma::store_matrix_sync(&Cs[(wm * 32 + i * 16) * CP + wn * 48 + j * 16],
                                    acc[i][j], CP, wmma::mem_row_major);
    __syncthreads();
    #pragma unroll
    for (int it = 0; it < 12; it++) {
        int idx = tid + it * 256;
        int r = idx / 24, cq = (idx % 24) * 4;
        int gr = row0 + r, gc = col0 + cq;
        if (gr < M) {
            float4 v = *(const float4*)&Cs[r * CP + cq];
            float4 bv = *(const float4*)&bias[gc];
            v.x += bv.x; v.y += bv.y; v.z += bv.z; v.w += bv.w;
            if (RESID) {
                float4 rv = *(const float4*)&resid[(size_t)gr * N + gc];
                v.x += rv.x; v.y += rv.y; v.z += rv.z; v.w += rv.w;
            }
            if (OUTBF) {
                uint2 p;
                p.x = pack_bf16x2(v.x, v.y);
                p.y = pack_bf16x2(v.z, v.w);
                *(uint2*)((bf16*)Cout + (size_t)gr * N + gc) = p;
            } else {
                *(float4*)((float*)Cout + (size_t)gr * N + gc) = v;
            }
        }
    }
    #undef LDG_TILE
    #undef STS_TILE
}
#define GEMM_SMEM 51200

// ---------------- deformable sampling v6: fused lane-parallel softmax,
// packed shfl payload, corner-parallel uint4 gathers -------------------------
__global__ void deform_kernel(const float* __restrict__ offaw,
                              const bf16* __restrict__ value, bf16* __restrict__ out)
{
    const unsigned FULL = 0xffffffffu;
    int gw   = (blockIdx.x * blockDim.x + threadIdx.x) >> 5;
    int lane = threadIdx.x & 31;
    if (gw >= MROWS * HEADS) return;
    int h  = gw % HEADS;
    int bq = gw / HEADS;
    int q  = bq % NTOK;
    int b  = bq / NTOK;

    // reference point (order d,x,y)
    float rd, rx, ry;
    {
        int S, loc;
        if (q < NHIGH)        { S = 24; loc = q; }
        else if (q < NMIDEND) { S = 12; loc = q - NHIGH; }
        else                  { S = 6;  loc = q - NMIDEND; }
        int d = loc / (S * S), y = (loc / S) % S, x = loc % S;
        float inv = 1.f / (float)S;
        rd = (d + 0.5f) * inv; ry = (y + 0.5f) * inv; rx = (x + 0.5f) * inv;
    }

    // ---- phase 1: lane pp handles point pp; softmax fused (1 expf/lane) ----
    float wDY00, wDY01, wDY10, wDY11, wX0, wX1;
    int   ipack0, ipack1, cpack;
    {
        int pp = (lane < 12) ? lane : 0;
        // lane-parallel softmax over the 12 logits
        float logit = offaw[(size_t)bq * 288 + 216 + h * 12 + pp];
        float lm = (lane < 12) ? logit : -1e30f;
        #pragma unroll
        for (int o = 16; o > 0; o >>= 1) lm = fmaxf(lm, __shfl_xor_sync(FULL, lm, o));
        float e = expf(logit - lm);
        float es = (lane < 12) ? e : 0.f;
        #pragma unroll
        for (int o = 16; o > 0; o >>= 1) es += __shfl_xor_sync(FULL, es, o);
        float a = e / es;                 // valid for lanes 0..11

        int l = pp >> 2;
        int S  = (l == 0) ? 24 : ((l == 1) ? 12 : 6);
        int st = (l == 0) ? 0  : ((l == 1) ? NHIGH : NMIDEND);
        const float* o = offaw + (size_t)bq * 288 + h * 36 + pp * 3;
        float pd = rd * S + o[0] - 0.5f;
        float px = rx * S + o[1] - 0.5f;
        float py = ry * S + o[2] - 0.5f;
        float fd = floorf(pd), fx = floorf(px), fy = floorf(py);
        int d0 = (int)fd, x0 = (int)fx, y0 = (int)fy;
        int d1 = d0 + 1, x1 = x0 + 1, y1 = y0 + 1;
        float wd1 = pd - fd, wx1 = px - fx, wy1 = py - fy;
        float wD0 = a * (1.f - wd1) * ((d0 >= 0 && d0 < S) ? 1.f : 0.f);
        float wD1 = a * wd1        * ((d1 >= 0 && d1 < S) ? 1.f : 0.f);
        float wY0 = (1.f - wy1) * ((y0 >= 0 && y0 < S) ? 1.f : 0.f);
        float wY1 = wy1         * ((y1 >= 0 && y1 < S) ? 1.f : 0.f);
        wX0 = (1.f - wx1) * ((x0 >= 0 && x0 < S) ? 1.f : 0.f);
        wX1 = wx1         * ((x1 >= 0 && x1 < S) ? 1.f : 0.f);
        int cd0 = min(max(d0, 0), S - 1), cd1 = min(max(d1, 0), S - 1);
        int cy0 = min(max(y0, 0), S - 1), cy1 = min(max(y1, 0), S - 1);
        int cx0 = min(max(x0, 0), S - 1);
        int cx1 = min(max(x1, 0), S - 1);
        int bD0 = st + cd0 * S * S, bD1 = st + cd1 * S * S;
        int rY0 = cy0 * S, rY1 = cy1 * S;
        wDY00 = wD0 * wY0; wDY01 = wD0 * wY1;
        wDY10 = wD1 * wY0; wDY11 = wD1 * wY1;
        // all indices < 16384 -> pack pairs into one int each
        ipack0 = (bD0 + rY0) | ((bD0 + rY1) << 16);
        ipack1 = (bD1 + rY0) | ((bD1 + rY1) << 16);
        cpack  = cx0 | (cx1 << 16);
    }

    // ---- phase 2: broadcast (9 shfls/point) + corner-parallel gather ----
    const int cg  = lane >> 3;             // 0..3 = (d,y) corner combo
    const int ch8 = (lane & 7) * 8;        // 8 channels per lane
    const bf16* vb = value + (size_t)b * NTOK * DIM + h * HDIM + ch8;

    float a0 = 0.f, a1 = 0.f, a2 = 0.f, a3 = 0.f;
    float a4 = 0.f, a5 = 0.f, a6 = 0.f, a7 = 0.f;
    #pragma unroll
    for (int p = 0; p < 12; p++) {
        float w00 = __shfl_sync(FULL, wDY00, p);
        float w01 = __shfl_sync(FULL, wDY01, p);
        float w10 = __shfl_sync(FULL, wDY10, p);
        float w11 = __shfl_sync(FULL, wDY11, p);
        float wx0 = __shfl_sync(FULL, wX0, p);
        float wx1 = __shfl_sync(FULL, wX1, p);
        int ip0 = __shfl_sync(FULL, ipack0, p);
        int ip1 = __shfl_sync(FULL, ipack1, p);
        int cp  = __shfl_sync(FULL, cpack, p);
        int c0 = cp & 0xffff, c1 = cp >> 16;
        // per-lane corner select
        float wcg = (cg & 2) ? ((cg & 1) ? w11 : w10) : ((cg & 1) ? w01 : w00);
        int   ip  = (cg & 2) ? ip1 : ip0;
        int   icg = (cg & 1) ? (ip >> 16) : (ip & 0xffff);

        {   // x = 0 parity
            uint4 raw = *(const uint4*)(vb + (size_t)(icg + c0) * DIM);
            float w = wcg * wx0;
            float2 va = __bfloat1622float2(*(const __nv_bfloat162*)&raw.x);
            float2 vb2 = __bfloat1622float2(*(const __nv_bfloat162*)&raw.y);
            float2 vc = __bfloat1622float2(*(const __nv_bfloat162*)&raw.z);
            float2 vd = __bfloat1622float2(*(const __nv_bfloat162*)&raw.w);
            a0 += w * va.x;  a1 += w * va.y;
            a2 += w * vb2.x; a3 += w * vb2.y;
            a4 += w * vc.x;  a5 += w * vc.y;
            a6 += w * vd.x;  a7 += w * vd.y;
        }
        {   // x = 1 parity
            uint4 raw = *(const uint4*)(vb + (size_t)(icg + c1) * DIM);
            float w = wcg * wx1;
            float2 va = __bfloat1622float2(*(const __nv_bfloat162*)&raw.x);
            float2 vb2 = __bfloat1622float2(*(const __nv_bfloat162*)&raw.y);
            float2 vc = __bfloat1622float2(*(const __nv_bfloat162*)&raw.z);
            float2 vd = __bfloat1622float2(*(const __nv_bfloat162*)&raw.w);
            a0 += w * va.x;  a1 += w * va.y;
            a2 += w * vb2.x; a3 += w * vb2.y;
            a4 += w * vc.x;  a5 += w * vc.y;
            a6 += w * vd.x;  a7 += w * vd.y;
        }
    }
    // reduce across the 4 corner groups: lanes l, l+8, l+16, l+24 share channels
    #pragma unroll
    for (int o = 16; o >= 8; o >>= 1) {
        a0 += __shfl_down_sync(FULL, a0, o);
        a1 += __shfl_down_sync(FULL, a1, o);
        a2 += __shfl_down_sync(FULL, a2, o);
        a3 += __shfl_down_sync(FULL, a3, o);
        a4 += __shfl_down_sync(FULL, a4, o);
        a5 += __shfl_down_sync(FULL, a5, o);
        a6 += __shfl_down_sync(FULL, a6, o);
        a7 += __shfl_down_sync(FULL, a7, o);
    }
    if (lane < 8) {
        uint4 pkt;
        pkt.x = pack_bf16x2(a0, a1);
        pkt.y = pack_bf16x2(a2, a3);
        pkt.z = pack_bf16x2(a4, a5);
        pkt.w = pack_bf16x2(a6, a7);
        *(uint4*)(out + (size_t)bq * DIM + h * HDIM + ch8) = pkt;
    }
}

// ---------------- depthwise 3x3x3 conv + GELU: 48 voxels/block, 8ch/thread ----
__global__ void __launch_bounds__(576) dwconv_gelu_kernel(
        const bf16* __restrict__ x, const float* __restrict__ w,
        const float* __restrict__ bias, bf16* __restrict__ y)
{
    __shared__ float sw[27 * HID];
    int tid = threadIdx.x;                 // 576
    for (int i = tid; i < 27 * HID; i += 576) sw[i] = w[i];
    __syncthreads();

    int c8  = (tid % 12) * 8;              // channel group (8 channels)
    int vox = tid / 12;                    // 0..47
    int vlin = blockIdx.x * 48 + vox;
    int b = vlin / NTOK, v = vlin % NTOK;

    int S, base;
    if (v < NHIGH)        { S = 24; base = 0; }
    else if (v < NMIDEND) { S = 12; base = NHIGH; }
    else                  { S = 6;  base = NMIDEND; }
    int loc = v - base;
    int d = loc / (S * S), yy = (loc / S) % S, xx = loc % S;

    const bf16* xb = x + ((size_t)b * NTOK + base) * HID + c8;
    float4 bv0 = *(const float4*)&bias[c8];
    float4 bv1 = *(const float4*)&bias[c8 + 4];
    float a0 = bv0.x, a1 = bv0.y, a2 = bv0.z, a3 = bv0.w;
    float a4 = bv1.x, a5 = bv1.y, a6 = bv1.z, a7 = bv1.w;
    #pragma unroll
    for (int kd = 0; kd < 3; kd++) {
        int di = d + kd - 1;
        if (di < 0 || di >= S) continue;
        #pragma unroll
        for (int kh = 0; kh < 3; kh++) {
            int yi = yy + kh - 1;
            if (yi < 0 || yi >= S) continue;
            #pragma unroll
            for (int kw = 0; kw < 3; kw++) {
                int xi = xx + kw - 1;
                if (xi < 0 || xi >= S) continue;
                uint4 raw = *(const uint4*)(xb + (size_t)((di * S + yi) * S + xi) * HID);
                float2 va = __bfloat1622float2(*(const __nv_bfloat162*)&raw.x);
                float2 vb2 = __bfloat1622float2(*(const __nv_bfloat162*)&raw.y);
                float2 vc = __bfloat1622float2(*(const __nv_bfloat162*)&raw.z);
                float2 vd = __bfloat1622float2(*(const __nv_bfloat162*)&raw.w);
                const float* wp = &sw[((kd * 3 + kh) * 3 + kw) * HID + c8];
                float4 wv0 = *(const float4*)wp;
                float4 wv1 = *(const float4*)(wp + 4);
                a0 += wv0.x * va.x;  a1 += wv0.y * va.y;
                a2 += wv0.z * vb2.x; a3 += wv0.w * vb2.y;
                a4 += wv1.x * vc.x;  a5 += wv1.y * vc.y;
                a6 += wv1.z * vd.x;  a7 += wv1.w * vd.y;
            }
        }
    }
    const float ISQ2 = 0.70710678118654752f;
    float g0 = 0.5f * a0 * (1.f + erff(a0 * ISQ2));
    float g1 = 0.5f * a1 * (1.f + erff(a1 * ISQ2));
    float g2 = 0.5f * a2 * (1.f + erff(a2 * ISQ2));
    float g3 = 0.5f * a3 * (1.f + erff(a3 * ISQ2));
    float g4 = 0.5f * a4 * (1.f + erff(a4 * ISQ2));
    float g5 = 0.5f * a5 * (1.f + erff(a5 * ISQ2));
    float g6 = 0.5f * a6 * (1.f + erff(a6 * ISQ2));
    float g7 = 0.5f * a7 * (1.f + erff(a7 * ISQ2));
    uint4 pkt;
    pkt.x = pack_bf16x2(g0, g1);
    pkt.y = pack_bf16x2(g2, g3);
    pkt.z = pack_bf16x2(g4, g5);
    pkt.w = pack_bf16x2(g6, g7);
    *(uint4*)(y + ((size_t)b * NTOK + v) * HID + c8) = pkt;
}

// ---------------- launch ----------------
static void* sym_addr(const void* sym) {
    void* p = nullptr;
    cudaGetSymbolAddress(&p, sym);
    return p;
}

extern "C" void kernel_launch(void* const* d_in, const int* in_sizes, int n_in,
                              void* d_out, int out_size)
{
    const float* query = (const float*)d_in[0];
    const float* feat  = (const float*)d_in[2];
    int wb = n_in - 24;
    const float* qnorm_w    = (const float*)d_in[wb + 0];
    const float* qnorm_b    = (const float*)d_in[wb + 1];
    const float* fnorm_w    = (const float*)d_in[wb + 2];
    const float* fnorm_b    = (const float*)d_in[wb + 3];
    const float* ext_qnorm_w= (const float*)d_in[wb + 4];
    const float* ext_qnorm_b= (const float*)d_in[wb + 5];
    const float* ext_fnorm_w= (const float*)d_in[wb + 6];
    const float* ext_fnorm_b= (const float*)d_in[wb + 7];
    const float* ffn_norm_w = (const float*)d_in[wb + 8];
    const float* ffn_norm_b = (const float*)d_in[wb + 9];
    const float* off_w      = (const float*)d_in[wb + 10];
    const float* off_b      = (const float*)d_in[wb + 11];
    const float* aw_w       = (const float*)d_in[wb + 12];
    const float* aw_b       = (const float*)d_in[wb + 13];
    const float* val_w      = (const float*)d_in[wb + 14];
    const float* val_b      = (const float*)d_in[wb + 15];
    const float* out_w      = (const float*)d_in[wb + 16];
    const float* out_b      = (const float*)d_in[wb + 17];
    const float* fc1_w      = (const float*)d_in[wb + 18];
    const float* fc1_b      = (const float*)d_in[wb + 19];
    const float* dw_w       = (const float*)d_in[wb + 20];
    const float* dw_b       = (const float*)d_in[wb + 21];
    const float* fc2_w      = (const float*)d_in[wb + 22];
    const float* fc2_b      = (const float*)d_in[wb + 23];

    float* qn    = (float*)sym_addr(g_qn);
    float* out1  = (float*)sym_addr(g_out1);
    float* offaw = (float*)sym_addr(g_offaw);
    bf16* aqb    = (bf16*)sym_addr(g_aq_b);
    bf16* afb    = (bf16*)sym_addr(g_af_b);
    bf16* valb   = (bf16*)sym_addr(g_val_b);
    bf16* doutb  = (bf16*)sym_addr(g_dout_b);
    bf16* xfb    = (bf16*)sym_addr(g_xf_b);
    bf16* xgb    = (bf16*)sym_addr(g_xg_b);
    bf16* wbf    = (bf16*)sym_addr(g_wb);
    float* outp  = (float*)d_out;

    cudaFuncSetAttribute(gemm_bf16_kernel<false, true>,  cudaFuncAttributeMaxDynamicSharedMemorySize, GEMM_SMEM);
    cudaFuncSetAttribute(gemm_bf16_kernel<false, false>, cudaFuncAttributeMaxDynamicSharedMemorySize, GEMM_SMEM);
    cudaFuncSetAttribute(gemm_bf16_kernel<true,  false>, cudaFuncAttributeMaxDynamicSharedMemorySize, GEMM_SMEM);

    const int M = MROWS;
    int gy = (M + 127) / 128;
    int grow = (M + 7) / 8;

    // 0) weights -> bf16 (+ interleave off/aw)
    cvt_weights_kernel<<<468, 256>>>(val_w, off_w, aw_w, out_w, fc1_w, fc2_w, wbf);
    // 0b) combined [off|aw] bias staged in out1[0:288] (overwritten by GEMM 5 later)
    cudaMemcpyAsync(out1,       off_b, 216 * sizeof(float), cudaMemcpyDeviceToDevice);
    cudaMemcpyAsync(out1 + 216, aw_b,   72 * sizeof(float), cudaMemcpyDeviceToDevice);
    // 1) q build + LN chain (warp per row)
    prep_kernel<<<grow, 256>>>(query, feat, qnorm_w, qnorm_b, fnorm_w, fnorm_b,
                               ext_qnorm_w, ext_qnorm_b, ext_fnorm_w, ext_fnorm_b,
                               qn, aqb, afb);
    // 2) value = af @ val_w + val_b   (bf16 out)
    gemm_bf16_kernel<false, true><<<dim3(4, gy), 256, GEMM_SMEM>>>(afb, wbf + WOFF_VAL, val_b, nullptr, valb, M, 384, 384);
    // 3) offsets+logits = aq @ [off|aw]_w + bias  (fp32 out, N=288)
    gemm_bf16_kernel<false, false><<<dim3(3, gy), 256, GEMM_SMEM>>>(aqb, wbf + WOFF_OFFAW, out1, nullptr, offaw, M, 288, 384);
    // 4) deformable sampling (softmax fused)
    {
        int warps = MROWS * HEADS;
        int blocks = (warps + 7) / 8;
        deform_kernel<<<blocks, 256>>>(offaw, valb, doutb);
    }
    // 5) out1 = qn + dout @ out_w + out_b (fp32)
    gemm_bf16_kernel<true, false><<<dim3(4, gy), 256, GEMM_SMEM>>>(doutb, wbf + WOFF_OUT, out_b, qn, out1, M, 384, 384);
    // 6) t = LN(out1, ffn_norm) -> bf16
    ln_kernel<<<grow, 256>>>(out1, ffn_norm_w, ffn_norm_b, aqb);
    // 7) x = t @ fc1_w + fc1_b  (bf16 out)
    gemm_bf16_kernel<false, true><<<dim3(1, gy), 256, GEMM_SMEM>>>(aqb, wbf + WOFF_FC1, fc1_b, nullptr, xfb, M, 96, 384);
    // 8) depthwise conv + GELU (bf16 out, 48 voxels/block)
    dwconv_gelu_kernel<<<MROWS / 48, 576>>>(xfb, dw_w, dw_b, xgb);
    // 9) out = out1 + xg @ fc2_w + fc2_b (fp32)
    gemm_bf16_kernel<true, false><<<dim3(4, gy), 256, GEMM_SMEM>>>(xgb, wbf + WOFF_FC2, fc2_b, out1, outp, M, 384, 96);
}

// round 13
// speedup vs baseline: 3.5202x; 1.0289x over previous
#include <cstdint>
#include <cstddef>
#include <cuda_runtime.h>
#include <cuda_bf16.h>
#include <mma.h>
#include <math.h>

using namespace nvcuda;
typedef __nv_bfloat16 bf16;

// ---------------- problem constants ----------------
#define DIM     384
#define HEADS   6
#define HDIM    64
#define HID     96
#define BB      2
#define NMID    1728
#define NTOK    15768
#define NHIGH   13824
#define NMIDEND 15552
#define MROWS   (BB*NTOK)         // 31536

// weight arena offsets (bf16 elements), [K,N] layout (off+aw interleaved to N=288)
#define WOFF_VAL   0
#define WOFF_OFFAW 147456
#define WOFF_OUT   258048
#define WOFF_FC1   405504
#define WOFF_FC2   442368
#define WTOTAL     479232

// ---------------- scratch (device globals) ----------------
__device__ float g_qn   [(size_t)MROWS*DIM];
__device__ float g_out1 [(size_t)MROWS*DIM];
__device__ float g_offaw[(size_t)MROWS*288];
__device__ float g_bias288[288];
__device__ bf16  g_aq_b [(size_t)MROWS*DIM];
__device__ bf16  g_af_b [(size_t)MROWS*DIM];
__device__ bf16  g_val_b[(size_t)MROWS*DIM];
__device__ bf16  g_dout_b[(size_t)MROWS*DIM];
__device__ bf16  g_xf_b [(size_t)MROWS*HID];
__device__ bf16  g_xg_b [(size_t)MROWS*HID];
__device__ bf16  g_wb   [WTOTAL];

// ---------------- weight convert (+ combined bias build) ----------------
__global__ void cvt_weights_kernel(const float* __restrict__ vw, const float* __restrict__ ow,
                                   const float* __restrict__ aww, const float* __restrict__ outw,
                                   const float* __restrict__ f1w, const float* __restrict__ f2w,
                                   const float* __restrict__ offb, const float* __restrict__ awb,
                                   bf16* __restrict__ dst, float* __restrict__ bias288)
{
    int i0 = blockIdx.x * blockDim.x + threadIdx.x;
    if (i0 < 288) bias288[i0] = (i0 < 216) ? offb[i0] : awb[i0 - 216];
    int stride = gridDim.x * blockDim.x;
    for (int i = i0; i < WTOTAL; i += stride) {
        float v;
        if      (i < WOFF_OFFAW) v = vw[i];
        else if (i < WOFF_OUT) {
            int rel = i - WOFF_OFFAW;
            int k = rel / 288, j = rel % 288;
            v = (j < 216) ? ow[k * 216 + j] : aww[k * 72 + (j - 216)];
        }
        else if (i < WOFF_FC1) v = outw[i - WOFF_OUT];
        else if (i < WOFF_FC2) v = f1w[i - WOFF_FC1];
        else                   v = f2w[i - WOFF_FC2];
        dst[i] = __float2bfloat16(v);
    }
}

// ---------------- helpers ----------------
__device__ __forceinline__ float2 warp_sum2(float a, float b) {
    #pragma unroll
    for (int o = 16; o > 0; o >>= 1) {
        a += __shfl_xor_sync(0xffffffffu, a, o);
        b += __shfl_xor_sync(0xffffffffu, b, o);
    }
    return make_float2(a, b);
}
__device__ __forceinline__ uint32_t pack_bf16x2(float a, float b) {
    __nv_bfloat162 p = __floats2bfloat162_rn(a, b);
    return *reinterpret_cast<uint32_t*>(&p);
}

// ---------------- K1: build q (+feat), fused LN chain — warp per row, float4 ----
__global__ void __launch_bounds__(256) prep_kernel(
        const float* __restrict__ query, const float* __restrict__ feat,
        const float* __restrict__ qw, const float* __restrict__ qb,
        const float* __restrict__ fw, const float* __restrict__ fb,
        const float* __restrict__ eqw, const float* __restrict__ eqb,
        const float* __restrict__ efw, const float* __restrict__ efb,
        float* __restrict__ qn_o, bf16* __restrict__ aq_o, bf16* __restrict__ af_o)
{
    int row = blockIdx.x * 8 + (threadIdx.x >> 5);
    if (row >= MROWS) return;
    int lane = threadIdx.x & 31;
    int b = row / NTOK, t = row % NTOK;

    float x[12];
    float s = 0.f, ss = 0.f;
    const bool addf = (t >= NHIGH && t < NMIDEND);
    const float* qrow = query + (size_t)row * DIM;
    const float* frow = addf ? feat + ((size_t)b * NMID + (t - NHIGH)) * DIM : nullptr;
    #pragma unroll
    for (int i = 0; i < 3; i++) {
        int c = (lane + i * 32) * 4;
        float4 v = *(const float4*)&qrow[c];
        if (addf) {
            float4 f = *(const float4*)&frow[c];
            v.x += f.x; v.y += f.y; v.z += f.z; v.w += f.w;
        }
        x[i*4+0] = v.x; x[i*4+1] = v.y; x[i*4+2] = v.z; x[i*4+3] = v.w;
        s += v.x + v.y + v.z + v.w;
        ss += v.x*v.x + v.y*v.y + v.z*v.z + v.w*v.w;
    }
    float2 r = warp_sum2(s, ss);
    float m  = r.x * (1.f / DIM);
    float rs = rsqrtf(r.y * (1.f / DIM) - m * m + 1e-6f);

    float qv[12], fv[12];
    float s1 = 0.f, ss1 = 0.f, s2 = 0.f, ss2 = 0.f;
    #pragma unroll
    for (int i = 0; i < 3; i++) {
        int c = (lane + i * 32) * 4;
        float4 qwv = *(const float4*)&qw[c];
        float4 qbv = *(const float4*)&qb[c];
        float4 fwv = *(const float4*)&fw[c];
        float4 fbv = *(const float4*)&fb[c];
        float4 o;
        #pragma unroll
        for (int j = 0; j < 4; j++) {
            float xn = (x[i*4+j] - m) * rs;
            float qq = xn * ((&qwv.x)[j]) + ((&qbv.x)[j]);
            float ff = xn * ((&fwv.x)[j]) + ((&fbv.x)[j]);
            qv[i*4+j] = qq; fv[i*4+j] = ff;
            (&o.x)[j] = qq;
            s1 += qq; ss1 += qq*qq;
            s2 += ff; ss2 += ff*ff;
        }
        *(float4*)&qn_o[(size_t)row * DIM + c] = o;
    }
    float2 r1 = warp_sum2(s1, ss1);
    float m1  = r1.x * (1.f / DIM);
    float rs1 = rsqrtf(r1.y * (1.f / DIM) - m1 * m1 + 1e-6f);
    float2 r2 = warp_sum2(s2, ss2);
    float m2  = r2.x * (1.f / DIM);
    float rs2 = rsqrtf(r2.y * (1.f / DIM) - m2 * m2 + 1e-6f);
    #pragma unroll
    for (int i = 0; i < 3; i++) {
        int c = (lane + i * 32) * 4;
        float4 ewv = *(const float4*)&eqw[c];
        float4 ebv = *(const float4*)&eqb[c];
        float4 fwv = *(const float4*)&efw[c];
        float4 fbv = *(const float4*)&efb[c];
        float aqv[4], afv[4];
        #pragma unroll
        for (int j = 0; j < 4; j++) {
            aqv[j] = (qv[i*4+j] - m1) * rs1 * ((&ewv.x)[j]) + ((&ebv.x)[j]);
            afv[j] = (fv[i*4+j] - m2) * rs2 * ((&fwv.x)[j]) + ((&fbv.x)[j]);
        }
        uint2 pa, pf;
        pa.x = pack_bf16x2(aqv[0], aqv[1]); pa.y = pack_bf16x2(aqv[2], aqv[3]);
        pf.x = pack_bf16x2(afv[0], afv[1]); pf.y = pack_bf16x2(afv[2], afv[3]);
        *(uint2*)&aq_o[(size_t)row * DIM + c] = pa;
        *(uint2*)&af_o[(size_t)row * DIM + c] = pf;
    }
}

// ---------------- generic LN (fp32 in -> bf16 out) — warp per row, float4 -----
__global__ void __launch_bounds__(256) ln_kernel(
        const float* __restrict__ xin, const float* __restrict__ w,
        const float* __restrict__ bws, bf16* __restrict__ yo)
{
    int row = blockIdx.x * 8 + (threadIdx.x >> 5);
    if (row >= MROWS) return;
    int lane = threadIdx.x & 31;
    float x[12]; float s = 0.f, ss = 0.f;
    const float* xr = xin + (size_t)row * DIM;
    #pragma unroll
    for (int i = 0; i < 3; i++) {
        int c = (lane + i * 32) * 4;
        float4 v = *(const float4*)&xr[c];
        x[i*4+0] = v.x; x[i*4+1] = v.y; x[i*4+2] = v.z; x[i*4+3] = v.w;
        s += v.x + v.y + v.z + v.w;
        ss += v.x*v.x + v.y*v.y + v.z*v.z + v.w*v.w;
    }
    float2 r = warp_sum2(s, ss);
    float m  = r.x * (1.f / DIM);
    float rs = rsqrtf(r.y * (1.f / DIM) - m * m + 1e-6f);
    #pragma unroll
    for (int i = 0; i < 3; i++) {
        int c = (lane + i * 32) * 4;
        float4 wv = *(const float4*)&w[c];
        float4 bv = *(const float4*)&bws[c];
        float y0 = (x[i*4+0] - m) * rs * wv.x + bv.x;
        float y1 = (x[i*4+1] - m) * rs * wv.y + bv.y;
        float y2 = (x[i*4+2] - m) * rs * wv.z + bv.z;
        float y3 = (x[i*4+3] - m) * rs * wv.w + bv.w;
        uint2 p;
        p.x = pack_bf16x2(y0, y1); p.y = pack_bf16x2(y2, y3);
        *(uint2*)&yo[(size_t)row * DIM + c] = p;
    }
}

// ---------------- bf16 wmma GEMM core, 128x96 tile, 8 warps (32x48 each) ------
template<bool RESID>
__device__ __forceinline__ void gemm_core(
        const bf16* __restrict__ A, const bf16* __restrict__ W,
        const float* __restrict__ bias, const float* __restrict__ resid,
        void* __restrict__ Cout, int M, int N, int K,
        int row0, int col0, bool outbf, char* sraw)
{
    constexpr int BM = 128, BK = 32;
    constexpr int AP = 40, BP = 104, CP = 100;
    bf16* As = (bf16*)sraw;
    bf16* Bs = (bf16*)(sraw + 2 * BM * AP * (int)sizeof(bf16));
    float* Cs = (float*)sraw;

    int tid = threadIdx.x;
    int wid = tid >> 5, wm = wid & 3, wn = wid >> 2;

    const int arow = tid >> 2, acq = (tid & 3) * 8;
    const int br0 = tid / 12,  bc0 = (tid % 12) * 8;
    const int idx2 = tid + 256;
    const int br1 = idx2 / 12, bc1 = (idx2 % 12) * 8;
    const bool haveB1 = (tid < 128);
    const uint4 z4 = make_uint4(0, 0, 0, 0);

    uint4 ra0, ra1, rb0, rb1;
    #define LDG_TILE(K0) do { \
        int r0_ = row0 + arow, r1_ = row0 + arow + 64; \
        ra0 = (r0_ < M) ? *(const uint4*)&A[(size_t)r0_ * K + (K0) + acq] : z4; \
        ra1 = (r1_ < M) ? *(const uint4*)&A[(size_t)r1_ * K + (K0) + acq] : z4; \
        rb0 = *(const uint4*)&W[(size_t)((K0) + br0) * N + col0 + bc0]; \
        if (haveB1) rb1 = *(const uint4*)&W[(size_t)((K0) + br1) * N + col0 + bc1]; \
    } while (0)
    #define STS_TILE(BUF) do { \
        *(uint4*)&As[(BUF) * BM * AP + arow * AP + acq]        = ra0; \
        *(uint4*)&As[(BUF) * BM * AP + (arow + 64) * AP + acq] = ra1; \
        *(uint4*)&Bs[(BUF) * BK * BP + br0 * BP + bc0]         = rb0; \
        if (haveB1) *(uint4*)&Bs[(BUF) * BK * BP + br1 * BP + bc1] = rb1; \
    } while (0)

    wmma::fragment<wmma::accumulator, 16, 16, 16, float> acc[2][3];
    #pragma unroll
    for (int i = 0; i < 2; i++)
        #pragma unroll
        for (int j = 0; j < 3; j++)
            wmma::fill_fragment(acc[i][j], 0.f);

    const int nk = K / BK;
    LDG_TILE(0);
    STS_TILE(0);
    __syncthreads();

    for (int t = 0; t < nk; t++) {
        if (t + 1 < nk) LDG_TILE((t + 1) * BK);
        const bf16* Ab = As + (t & 1) * BM * AP;
        const bf16* Bb = Bs + (t & 1) * BK * BP;
        #pragma unroll
        for (int ks = 0; ks < 2; ks++) {
            wmma::fragment<wmma::matrix_a, 16, 16, 16, bf16, wmma::row_major> fa[2];
            wmma::fragment<wmma::matrix_b, 16, 16, 16, bf16, wmma::row_major> fb[3];
            #pragma unroll
            for (int i = 0; i < 2; i++)
                wmma::load_matrix_sync(fa[i], &Ab[(wm * 32 + i * 16) * AP + ks * 16], AP);
            #pragma unroll
            for (int j = 0; j < 3; j++)
                wmma::load_matrix_sync(fb[j], &Bb[(ks * 16) * BP + wn * 48 + j * 16], BP);
            #pragma unroll
            for (int i = 0; i < 2; i++)
                #pragma unroll
                for (int j = 0; j < 3; j++)
                    wmma::mma_sync(acc[i][j], fa[i], fb[j], acc[i][j]);
        }
        if (t + 1 < nk) STS_TILE((t + 1) & 1);
        __syncthreads();
    }

    #pragma unroll
    for (int i = 0; i < 2; i++)
        #pragma unroll
        for (int j = 0; j < 3; j++)
            wmma::store_matrix_sync(&Cs[(wm * 32 + i * 16) * CP + wn * 48 + j * 16],
                                    acc[i][j], CP, wmma::mem_row_major);
    __syncthreads();
    #pragma unroll
    for (int it = 0; it < 12; it++) {
        int idx = tid + it * 256;
        int r = idx / 24, cq = (idx % 24) * 4;
        int gr = row0 + r, gc = col0 + cq;
        if (gr < M) {
            float4 v = *(const float4*)&Cs[r * CP + cq];
            float4 bv = *(const float4*)&bias[gc];
            v.x += bv.x; v.y += bv.y; v.z += bv.z; v.w += bv.w;
            if (RESID) {
                float4 rv = *(const float4*)&resid[(size_t)gr * N + gc];
                v.x += rv.x; v.y += rv.y; v.z += rv.z; v.w += rv.w;
            }
            if (outbf) {
                uint2 p;
                p.x = pack_bf16x2(v.x, v.y);
                p.y = pack_bf16x2(v.z, v.w);
                *(uint2*)((bf16*)Cout + (size_t)gr * N + gc) = p;
            } else {
                *(float4*)((float*)Cout + (size_t)gr * N + gc) = v;
            }
        }
    }
    #undef LDG_TILE
    #undef STS_TILE
}
#define GEMM_SMEM 51200

template<bool RESID, bool OUTBF>
__global__ void __launch_bounds__(256, 2) gemm_bf16_kernel(
        const bf16* __restrict__ A, const bf16* __restrict__ W,
        const float* __restrict__ bias, const float* __restrict__ resid,
        void* __restrict__ Cout, int M, int N, int K)
{
    extern __shared__ __align__(16) char sraw[];
    gemm_core<RESID>(A, W, bias, resid, Cout, M, N, K,
                     blockIdx.y * 128, blockIdx.x * 96, OUTBF, sraw);
}

// dual-problem GEMM: blockIdx.x < split -> problem 0 (bf16 out), else problem 1 (fp32 out)
__global__ void __launch_bounds__(256, 2) gemm_dual_kernel(
        const bf16* __restrict__ A0, const bf16* __restrict__ W0,
        const float* __restrict__ b0, void* __restrict__ C0, int N0,
        const bf16* __restrict__ A1, const bf16* __restrict__ W1,
        const float* __restrict__ b1, void* __restrict__ C1, int N1,
        int M, int K, int split)
{
    extern __shared__ __align__(16) char sraw[];
    if ((int)blockIdx.x < split)
        gemm_core<false>(A0, W0, b0, nullptr, C0, M, N0, K,
                         blockIdx.y * 128, blockIdx.x * 96, true, sraw);
    else
        gemm_core<false>(A1, W1, b1, nullptr, C1, M, N1, K,
                         blockIdx.y * 128, (blockIdx.x - split) * 96, false, sraw);
}

// ---------------- deformable sampling v6 (unchanged from R12) ----------------
__global__ void deform_kernel(const float* __restrict__ offaw,
                              const bf16* __restrict__ value, bf16* __restrict__ out)
{
    const unsigned FULL = 0xffffffffu;
    int gw   = (blockIdx.x * blockDim.x + threadIdx.x) >> 5;
    int lane = threadIdx.x & 31;
    if (gw >= MROWS * HEADS) return;
    int h  = gw % HEADS;
    int bq = gw / HEADS;
    int q  = bq % NTOK;
    int b  = bq / NTOK;

    float rd, rx, ry;
    {
        int S, loc;
        if (q < NHIGH)        { S = 24; loc = q; }
        else if (q < NMIDEND) { S = 12; loc = q - NHIGH; }
        else                  { S = 6;  loc = q - NMIDEND; }
        int d = loc / (S * S), y = (loc / S) % S, x = loc % S;
        float inv = 1.f / (float)S;
        rd = (d + 0.5f) * inv; ry = (y + 0.5f) * inv; rx = (x + 0.5f) * inv;
    }

    float wDY00, wDY01, wDY10, wDY11, wX0, wX1;
    int   ipack0, ipack1, cpack;
    {
        int pp = (lane < 12) ? lane : 0;
        float logit = offaw[(size_t)bq * 288 + 216 + h * 12 + pp];
        float lm = (lane < 12) ? logit : -1e30f;
        #pragma unroll
        for (int o = 16; o > 0; o >>= 1) lm = fmaxf(lm, __shfl_xor_sync(FULL, lm, o));
        float e = expf(logit - lm);
        float es = (lane < 12) ? e : 0.f;
        #pragma unroll
        for (int o = 16; o > 0; o >>= 1) es += __shfl_xor_sync(FULL, es, o);
        float a = e / es;

        int l = pp >> 2;
        int S  = (l == 0) ? 24 : ((l == 1) ? 12 : 6);
        int st = (l == 0) ? 0  : ((l == 1) ? NHIGH : NMIDEND);
        const float* o = offaw + (size_t)bq * 288 + h * 36 + pp * 3;
        float pd = rd * S + o[0] - 0.5f;
        float px = rx * S + o[1] - 0.5f;
        float py = ry * S + o[2] - 0.5f;
        float fd = floorf(pd), fx = floorf(px), fy = floorf(py);
        int d0 = (int)fd, x0 = (int)fx, y0 = (int)fy;
        int d1 = d0 + 1, x1 = x0 + 1, y1 = y0 + 1;
        float wd1 = pd - fd, wx1 = px - fx, wy1 = py - fy;
        float wD0 = a * (1.f - wd1) * ((d0 >= 0 && d0 < S) ? 1.f : 0.f);
        float wD1 = a * wd1        * ((d1 >= 0 && d1 < S) ? 1.f : 0.f);
        float wY0 = (1.f - wy1) * ((y0 >= 0 && y0 < S) ? 1.f : 0.f);
        float wY1 = wy1         * ((y1 >= 0 && y1 < S) ? 1.f : 0.f);
        wX0 = (1.f - wx1) * ((x0 >= 0 && x0 < S) ? 1.f : 0.f);
        wX1 = wx1         * ((x1 >= 0 && x1 < S) ? 1.f : 0.f);
        int cd0 = min(max(d0, 0), S - 1), cd1 = min(max(d1, 0), S - 1);
        int cy0 = min(max(y0, 0), S - 1), cy1 = min(max(y1, 0), S - 1);
        int cx0 = min(max(x0, 0), S - 1);
        int cx1 = min(max(x1, 0), S - 1);
        int bD0 = st + cd0 * S * S, bD1 = st + cd1 * S * S;
        int rY0 = cy0 * S, rY1 = cy1 * S;
        wDY00 = wD0 * wY0; wDY01 = wD0 * wY1;
        wDY10 = wD1 * wY0; wDY11 = wD1 * wY1;
        ipack0 = (bD0 + rY0) | ((bD0 + rY1) << 16);
        ipack1 = (bD1 + rY0) | ((bD1 + rY1) << 16);
        cpack  = cx0 | (cx1 << 16);
    }

    const int cg  = lane >> 3;
    const int ch8 = (lane & 7) * 8;
    const bf16* vb = value + (size_t)b * NTOK * DIM + h * HDIM + ch8;

    float a0 = 0.f, a1 = 0.f, a2 = 0.f, a3 = 0.f;
    float a4 = 0.f, a5 = 0.f, a6 = 0.f, a7 = 0.f;
    #pragma unroll
    for (int p = 0; p < 12; p++) {
        float w00 = __shfl_sync(FULL, wDY00, p);
        float w01 = __shfl_sync(FULL, wDY01, p);
        float w10 = __shfl_sync(FULL, wDY10, p);
        float w11 = __shfl_sync(FULL, wDY11, p);
        float wx0 = __shfl_sync(FULL, wX0, p);
        float wx1 = __shfl_sync(FULL, wX1, p);
        int ip0 = __shfl_sync(FULL, ipack0, p);
        int ip1 = __shfl_sync(FULL, ipack1, p);
        int cp  = __shfl_sync(FULL, cpack, p);
        int c0 = cp & 0xffff, c1 = cp >> 16;
        float wcg = (cg & 2) ? ((cg & 1) ? w11 : w10) : ((cg & 1) ? w01 : w00);
        int   ip  = (cg & 2) ? ip1 : ip0;
        int   icg = (cg & 1) ? (ip >> 16) : (ip & 0xffff);

        {
            uint4 raw = *(const uint4*)(vb + (size_t)(icg + c0) * DIM);
            float w = wcg * wx0;
            float2 va = __bfloat1622float2(*(const __nv_bfloat162*)&raw.x);
            float2 vb2 = __bfloat1622float2(*(const __nv_bfloat162*)&raw.y);
            float2 vc = __bfloat1622float2(*(const __nv_bfloat162*)&raw.z);
            float2 vd = __bfloat1622float2(*(const __nv_bfloat162*)&raw.w);
            a0 += w * va.x;  a1 += w * va.y;
            a2 += w * vb2.x; a3 += w * vb2.y;
            a4 += w * vc.x;  a5 += w * vc.y;
            a6 += w * vd.x;  a7 += w * vd.y;
        }
        {
            uint4 raw = *(const uint4*)(vb + (size_t)(icg + c1) * DIM);
            float w = wcg * wx1;
            float2 va = __bfloat1622float2(*(const __nv_bfloat162*)&raw.x);
            float2 vb2 = __bfloat1622float2(*(const __nv_bfloat162*)&raw.y);
            float2 vc = __bfloat1622float2(*(const __nv_bfloat162*)&raw.z);
            float2 vd = __bfloat1622float2(*(const __nv_bfloat162*)&raw.w);
            a0 += w * va.x;  a1 += w * va.y;
            a2 += w * vb2.x; a3 += w * vb2.y;
            a4 += w * vc.x;  a5 += w * vc.y;
            a6 += w * vd.x;  a7 += w * vd.y;
        }
    }
    #pragma unroll
    for (int o = 16; o >= 8; o >>= 1) {
        a0 += __shfl_down_sync(FULL, a0, o);
        a1 += __shfl_down_sync(FULL, a1, o);
        a2 += __shfl_down_sync(FULL, a2, o);
        a3 += __shfl_down_sync(FULL, a3, o);
        a4 += __shfl_down_sync(FULL, a4, o);
        a5 += __shfl_down_sync(FULL, a5, o);
        a6 += __shfl_down_sync(FULL, a6, o);
        a7 += __shfl_down_sync(FULL, a7, o);
    }
    if (lane < 8) {
        uint4 pkt;
        pkt.x = pack_bf16x2(a0, a1);
        pkt.y = pack_bf16x2(a2, a3);
        pkt.z = pack_bf16x2(a4, a5);
        pkt.w = pack_bf16x2(a6, a7);
        *(uint4*)(out + (size_t)bq * DIM + h * HDIM + ch8) = pkt;
    }
}

// ---------------- depthwise 3x3x3 conv + GELU: 48 voxels/block, 8ch/thread ----
__global__ void __launch_bounds__(576) dwconv_gelu_kernel(
        const bf16* __restrict__ x, const float* __restrict__ w,
        const float* __restrict__ bias, bf16* __restrict__ y)
{
    __shared__ float sw[27 * HID];
    int tid = threadIdx.x;                 // 576
    for (int i = tid; i < 27 * HID; i += 576) sw[i] = w[i];
    __syncthreads();

    int c8  = (tid % 12) * 8;
    int vox = tid / 12;
    int vlin = blockIdx.x * 48 + vox;
    int b = vlin / NTOK, v = vlin % NTOK;

    int S, base;
    if (v < NHIGH)        { S = 24; base = 0; }
    else if (v < NMIDEND) { S = 12; base = NHIGH; }
    else                  { S = 6;  base = NMIDEND; }
    int loc = v - base;
    int d = loc / (S * S), yy = (loc / S) % S, xx = loc % S;

    const bf16* xb = x + ((size_t)b * NTOK + base) * HID + c8;
    float4 bv0 = *(const float4*)&bias[c8];
    float4 bv1 = *(const float4*)&bias[c8 + 4];
    float a0 = bv0.x, a1 = bv0.y, a2 = bv0.z, a3 = bv0.w;
    float a4 = bv1.x, a5 = bv1.y, a6 = bv1.z, a7 = bv1.w;
    #pragma unroll
    for (int kd = 0; kd < 3; kd++) {
        int di = d + kd - 1;
        if (di < 0 || di >= S) continue;
        #pragma unroll
        for (int kh = 0; kh < 3; kh++) {
            int yi = yy + kh - 1;
            if (yi < 0 || yi >= S) continue;
            #pragma unroll
            for (int kw = 0; kw < 3; kw++) {
                int xi = xx + kw - 1;
                if (xi < 0 || xi >= S) continue;
                uint4 raw = *(const uint4*)(xb + (size_t)((di * S + yi) * S + xi) * HID);
                float2 va = __bfloat1622float2(*(const __nv_bfloat162*)&raw.x);
                float2 vb2 = __bfloat1622float2(*(const __nv_bfloat162*)&raw.y);
                float2 vc = __bfloat1622float2(*(const __nv_bfloat162*)&raw.z);
                float2 vd = __bfloat1622float2(*(const __nv_bfloat162*)&raw.w);
                const float* wp = &sw[((kd * 3 + kh) * 3 + kw) * HID + c8];
                float4 wv0 = *(const float4*)wp;
                float4 wv1 = *(const float4*)(wp + 4);
                a0 += wv0.x * va.x;  a1 += wv0.y * va.y;
                a2 += wv0.z * vb2.x; a3 += wv0.w * vb2.y;
                a4 += wv1.x * vc.x;  a5 += wv1.y * vc.y;
                a6 += wv1.z * vd.x;  a7 += wv1.w * vd.y;
            }
        }
    }
    const float ISQ2 = 0.70710678118654752f;
    float g0 = 0.5f * a0 * (1.f + erff(a0 * ISQ2));
    float g1 = 0.5f * a1 * (1.f + erff(a1 * ISQ2));
    float g2 = 0.5f * a2 * (1.f + erff(a2 * ISQ2));
    float g3 = 0.5f * a3 * (1.f + erff(a3 * ISQ2));
    float g4 = 0.5f * a4 * (1.f + erff(a4 * ISQ2));
    float g5 = 0.5f * a5 * (1.f + erff(a5 * ISQ2));
    float g6 = 0.5f * a6 * (1.f + erff(a6 * ISQ2));
    float g7 = 0.5f * a7 * (1.f + erff(a7 * ISQ2));
    uint4 pkt;
    pkt.x = pack_bf16x2(g0, g1);
    pkt.y = pack_bf16x2(g2, g3);
    pkt.z = pack_bf16x2(g4, g5);
    pkt.w = pack_bf16x2(g6, g7);
    *(uint4*)(y + ((size_t)b * NTOK + v) * HID + c8) = pkt;
}

// ---------------- launch ----------------
static void* sym_addr(const void* sym) {
    void* p = nullptr;
    cudaGetSymbolAddress(&p, sym);
    return p;
}

extern "C" void kernel_launch(void* const* d_in, const int* in_sizes, int n_in,
                              void* d_out, int out_size)
{
    const float* query = (const float*)d_in[0];
    const float* feat  = (const float*)d_in[2];
    int wb = n_in - 24;
    const float* qnorm_w    = (const float*)d_in[wb + 0];
    const float* qnorm_b    = (const float*)d_in[wb + 1];
    const float* fnorm_w    = (const float*)d_in[wb + 2];
    const float* fnorm_b    = (const float*)d_in[wb + 3];
    const float* ext_qnorm_w= (const float*)d_in[wb + 4];
    const float* ext_qnorm_b= (const float*)d_in[wb + 5];
    const float* ext_fnorm_w= (const float*)d_in[wb + 6];
    const float* ext_fnorm_b= (const float*)d_in[wb + 7];
    const float* ffn_norm_w = (const float*)d_in[wb + 8];
    const float* ffn_norm_b = (const float*)d_in[wb + 9];
    const float* off_w      = (const float*)d_in[wb + 10];
    const float* off_b      = (const float*)d_in[wb + 11];
    const float* aw_w       = (const float*)d_in[wb + 12];
    const float* aw_b       = (const float*)d_in[wb + 13];
    const float* val_w      = (const float*)d_in[wb + 14];
    const float* val_b      = (const float*)d_in[wb + 15];
    const float* out_w      = (const float*)d_in[wb + 16];
    const float* out_b      = (const float*)d_in[wb + 17];
    const float* fc1_w      = (const float*)d_in[wb + 18];
    const float* fc1_b      = (const float*)d_in[wb + 19];
    const float* dw_w       = (const float*)d_in[wb + 20];
    const float* dw_b       = (const float*)d_in[wb + 21];
    const float* fc2_w      = (const float*)d_in[wb + 22];
    const float* fc2_b      = (const float*)d_in[wb + 23];

    float* qn    = (float*)sym_addr(g_qn);
    float* out1  = (float*)sym_addr(g_out1);
    float* offaw = (float*)sym_addr(g_offaw);
    float* bias288 = (float*)sym_addr(g_bias288);
    bf16* aqb    = (bf16*)sym_addr(g_aq_b);
    bf16* afb    = (bf16*)sym_addr(g_af_b);
    bf16* valb   = (bf16*)sym_addr(g_val_b);
    bf16* doutb  = (bf16*)sym_addr(g_dout_b);
    bf16* xfb    = (bf16*)sym_addr(g_xf_b);
    bf16* xgb    = (bf16*)sym_addr(g_xg_b);
    bf16* wbf    = (bf16*)sym_addr(g_wb);
    float* outp  = (float*)d_out;

    cudaFuncSetAttribute(gemm_bf16_kernel<false, true>,  cudaFuncAttributeMaxDynamicSharedMemorySize, GEMM_SMEM);
    cudaFuncSetAttribute(gemm_bf16_kernel<false, false>, cudaFuncAttributeMaxDynamicSharedMemorySize, GEMM_SMEM);
    cudaFuncSetAttribute(gemm_bf16_kernel<true,  false>, cudaFuncAttributeMaxDynamicSharedMemorySize, GEMM_SMEM);
    cudaFuncSetAttribute(gemm_dual_kernel, cudaFuncAttributeMaxDynamicSharedMemorySize, GEMM_SMEM);

    const int M = MROWS;
    int gy = (M + 127) / 128;
    int grow = (M + 7) / 8;

    // 0) weights -> bf16 (+ interleave off/aw, + combined bias build)
    cvt_weights_kernel<<<468, 256>>>(val_w, off_w, aw_w, out_w, fc1_w, fc2_w,
                                     off_b, aw_b, wbf, bias288);
    // 1) q build + LN chain (warp per row)
    prep_kernel<<<grow, 256>>>(query, feat, qnorm_w, qnorm_b, fnorm_w, fnorm_b,
                               ext_qnorm_w, ext_qnorm_b, ext_fnorm_w, ext_fnorm_b,
                               qn, aqb, afb);
    // 2+3) fused: value = af @ val_w + val_b (bf16) AND offaw = aq @ [off|aw]_w + bias (fp32)
    gemm_dual_kernel<<<dim3(7, gy), 256, GEMM_SMEM>>>(
        afb, wbf + WOFF_VAL, val_b, valb, 384,
        aqb, wbf + WOFF_OFFAW, bias288, offaw, 288,
        M, 384, 4);
    // 4) deformable sampling (softmax fused)
    {
        int warps = MROWS * HEADS;
        int blocks = (warps + 7) / 8;
        deform_kernel<<<blocks, 256>>>(offaw, valb, doutb);
    }
    // 5) out1 = qn + dout @ out_w + out_b (fp32)
    gemm_bf16_kernel<true, false><<<dim3(4, gy), 256, GEMM_SMEM>>>(doutb, wbf + WOFF_OUT, out_b, qn, out1, M, 384, 384);
    // 6) t = LN(out1, ffn_norm) -> bf16
    ln_kernel<<<grow, 256>>>(out1, ffn_norm_w, ffn_norm_b, aqb);
    // 7) x = t @ fc1_w + fc1_b  (bf16 out)
    gemm_bf16_kernel<false, true><<<dim3(1, gy), 256, GEMM_SMEM>>>(aqb, wbf + WOFF_FC1, fc1_b, nullptr, xfb, M, 96, 384);
    // 8) depthwise conv + GELU (bf16 out, 48 voxels/block)
    dwconv_gelu_kernel<<<MROWS / 48, 576>>>(xfb, dw_w, dw_b, xgb);
    // 9) out = out1 + xg @ fc2_w + fc2_b (fp32)
    gemm_bf16_kernel<true, false><<<dim3(4, gy), 256, GEMM_SMEM>>>(xgb, wbf + WOFF_FC2, fc2_b, out1, outp, M, 384, 96);
}

// round 14
// speedup vs baseline: 3.7843x; 1.0750x over previous
#include <cstdint>
#include <cstddef>
#include <cuda_runtime.h>
#include <cuda_bf16.h>
#include <mma.h>
#include <math.h>

using namespace nvcuda;
typedef __nv_bfloat16 bf16;

// ---------------- problem constants ----------------
#define DIM     384
#define HEADS   6
#define HDIM    64
#define HID     96
#define BB      2
#define NMID    1728
#define NTOK    15768
#define NHIGH   13824
#define NMIDEND 15552
#define MROWS   (BB*NTOK)         // 31536

// weight arena offsets (bf16 elements), [K,N] layout (off+aw interleaved to N=288)
#define WOFF_VAL   0
#define WOFF_OFFAW 147456
#define WOFF_OUT   258048
#define WOFF_FC1   405504
#define WOFF_FC2   442368
#define WTOTAL     479232

// ---------------- scratch (device globals) ----------------
__device__ float g_qn   [(size_t)MROWS*DIM];
__device__ float g_out1 [(size_t)MROWS*DIM];
__device__ float g_offaw[(size_t)MROWS*288];
__device__ float g_bias288[288];
__device__ bf16  g_aq_b [(size_t)MROWS*DIM];
__device__ bf16  g_af_b [(size_t)MROWS*DIM];
__device__ bf16  g_val_b[(size_t)MROWS*DIM];
__device__ bf16  g_dout_b[(size_t)MROWS*DIM];
__device__ bf16  g_xf_b [(size_t)MROWS*HID];
__device__ bf16  g_xg_b [(size_t)MROWS*HID];
__device__ bf16  g_wb   [WTOTAL];

// ---------------- weight convert (+ combined bias build) ----------------
__global__ void cvt_weights_kernel(const float* __restrict__ vw, const float* __restrict__ ow,
                                   const float* __restrict__ aww, const float* __restrict__ outw,
                                   const float* __restrict__ f1w, const float* __restrict__ f2w,
                                   const float* __restrict__ offb, const float* __restrict__ awb,
                                   bf16* __restrict__ dst, float* __restrict__ bias288)
{
    int i0 = blockIdx.x * blockDim.x + threadIdx.x;
    if (i0 < 288) bias288[i0] = (i0 < 216) ? offb[i0] : awb[i0 - 216];
    int stride = gridDim.x * blockDim.x;
    for (int i = i0; i < WTOTAL; i += stride) {
        float v;
        if      (i < WOFF_OFFAW) v = vw[i];
        else if (i < WOFF_OUT) {
            int rel = i - WOFF_OFFAW;
            int k = rel / 288, j = rel % 288;
            v = (j < 216) ? ow[k * 216 + j] : aww[k * 72 + (j - 216)];
        }
        else if (i < WOFF_FC1) v = outw[i - WOFF_OUT];
        else if (i < WOFF_FC2) v = f1w[i - WOFF_FC1];
        else                   v = f2w[i - WOFF_FC2];
        dst[i] = __float2bfloat16(v);
    }
}

// ---------------- helpers ----------------
__device__ __forceinline__ float2 warp_sum2(float a, float b) {
    #pragma unroll
    for (int o = 16; o > 0; o >>= 1) {
        a += __shfl_xor_sync(0xffffffffu, a, o);
        b += __shfl_xor_sync(0xffffffffu, b, o);
    }
    return make_float2(a, b);
}
__device__ __forceinline__ uint32_t pack_bf16x2(float a, float b) {
    __nv_bfloat162 p = __floats2bfloat162_rn(a, b);
    return *reinterpret_cast<uint32_t*>(&p);
}

// ---------------- K1: build q (+feat), fused LN chain — warp per row, float4 ----
__global__ void __launch_bounds__(256) prep_kernel(
        const float* __restrict__ query, const float* __restrict__ feat,
        const float* __restrict__ qw, const float* __restrict__ qb,
        const float* __restrict__ fw, const float* __restrict__ fb,
        const float* __restrict__ eqw, const float* __restrict__ eqb,
        const float* __restrict__ efw, const float* __restrict__ efb,
        float* __restrict__ qn_o, bf16* __restrict__ aq_o, bf16* __restrict__ af_o)
{
    int row = blockIdx.x * 8 + (threadIdx.x >> 5);
    if (row >= MROWS) return;
    int lane = threadIdx.x & 31;
    int b = row / NTOK, t = row % NTOK;

    float x[12];
    float s = 0.f, ss = 0.f;
    const bool addf = (t >= NHIGH && t < NMIDEND);
    const float* qrow = query + (size_t)row * DIM;
    const float* frow = addf ? feat + ((size_t)b * NMID + (t - NHIGH)) * DIM : nullptr;
    #pragma unroll
    for (int i = 0; i < 3; i++) {
        int c = (lane + i * 32) * 4;
        float4 v = *(const float4*)&qrow[c];
        if (addf) {
            float4 f = *(const float4*)&frow[c];
            v.x += f.x; v.y += f.y; v.z += f.z; v.w += f.w;
        }
        x[i*4+0] = v.x; x[i*4+1] = v.y; x[i*4+2] = v.z; x[i*4+3] = v.w;
        s += v.x + v.y + v.z + v.w;
        ss += v.x*v.x + v.y*v.y + v.z*v.z + v.w*v.w;
    }
    float2 r = warp_sum2(s, ss);
    float m  = r.x * (1.f / DIM);
    float rs = rsqrtf(r.y * (1.f / DIM) - m * m + 1e-6f);

    float qv[12], fv[12];
    float s1 = 0.f, ss1 = 0.f, s2 = 0.f, ss2 = 0.f;
    #pragma unroll
    for (int i = 0; i < 3; i++) {
        int c = (lane + i * 32) * 4;
        float4 qwv = *(const float4*)&qw[c];
        float4 qbv = *(const float4*)&qb[c];
        float4 fwv = *(const float4*)&fw[c];
        float4 fbv = *(const float4*)&fb[c];
        float4 o;
        #pragma unroll
        for (int j = 0; j < 4; j++) {
            float xn = (x[i*4+j] - m) * rs;
            float qq = xn * ((&qwv.x)[j]) + ((&qbv.x)[j]);
            float ff = xn * ((&fwv.x)[j]) + ((&fbv.x)[j]);
            qv[i*4+j] = qq; fv[i*4+j] = ff;
            (&o.x)[j] = qq;
            s1 += qq; ss1 += qq*qq;
            s2 += ff; ss2 += ff*ff;
        }
        *(float4*)&qn_o[(size_t)row * DIM + c] = o;
    }
    float2 r1 = warp_sum2(s1, ss1);
    float m1  = r1.x * (1.f / DIM);
    float rs1 = rsqrtf(r1.y * (1.f / DIM) - m1 * m1 + 1e-6f);
    float2 r2 = warp_sum2(s2, ss2);
    float m2  = r2.x * (1.f / DIM);
    float rs2 = rsqrtf(r2.y * (1.f / DIM) - m2 * m2 + 1e-6f);
    #pragma unroll
    for (int i = 0; i < 3; i++) {
        int c = (lane + i * 32) * 4;
        float4 ewv = *(const float4*)&eqw[c];
        float4 ebv = *(const float4*)&eqb[c];
        float4 fwv = *(const float4*)&efw[c];
        float4 fbv = *(const float4*)&efb[c];
        float aqv[4], afv[4];
        #pragma unroll
        for (int j = 0; j < 4; j++) {
            aqv[j] = (qv[i*4+j] - m1) * rs1 * ((&ewv.x)[j]) + ((&ebv.x)[j]);
            afv[j] = (fv[i*4+j] - m2) * rs2 * ((&fwv.x)[j]) + ((&fbv.x)[j]);
        }
        uint2 pa, pf;
        pa.x = pack_bf16x2(aqv[0], aqv[1]); pa.y = pack_bf16x2(aqv[2], aqv[3]);
        pf.x = pack_bf16x2(afv[0], afv[1]); pf.y = pack_bf16x2(afv[2], afv[3]);
        *(uint2*)&aq_o[(size_t)row * DIM + c] = pa;
        *(uint2*)&af_o[(size_t)row * DIM + c] = pf;
    }
}

// ---------------- generic LN (fp32 in -> bf16 out) — warp per row, float4 -----
__global__ void __launch_bounds__(256) ln_kernel(
        const float* __restrict__ xin, const float* __restrict__ w,
        const float* __restrict__ bws, bf16* __restrict__ yo)
{
    int row = blockIdx.x * 8 + (threadIdx.x >> 5);
    if (row >= MROWS) return;
    int lane = threadIdx.x & 31;
    float x[12]; float s = 0.f, ss = 0.f;
    const float* xr = xin + (size_t)row * DIM;
    #pragma unroll
    for (int i = 0; i < 3; i++) {
        int c = (lane + i * 32) * 4;
        float4 v = *(const float4*)&xr[c];
        x[i*4+0] = v.x; x[i*4+1] = v.y; x[i*4+2] = v.z; x[i*4+3] = v.w;
        s += v.x + v.y + v.z + v.w;
        ss += v.x*v.x + v.y*v.y + v.z*v.z + v.w*v.w;
    }
    float2 r = warp_sum2(s, ss);
    float m  = r.x * (1.f / DIM);
    float rs = rsqrtf(r.y * (1.f / DIM) - m * m + 1e-6f);
    #pragma unroll
    for (int i = 0; i < 3; i++) {
        int c = (lane + i * 32) * 4;
        float4 wv = *(const float4*)&w[c];
        float4 bv = *(const float4*)&bws[c];
        float y0 = (x[i*4+0] - m) * rs * wv.x + bv.x;
        float y1 = (x[i*4+1] - m) * rs * wv.y + bv.y;
        float y2 = (x[i*4+2] - m) * rs * wv.z + bv.z;
        float y3 = (x[i*4+3] - m) * rs * wv.w + bv.w;
        uint2 p;
        p.x = pack_bf16x2(y0, y1); p.y = pack_bf16x2(y2, y3);
        *(uint2*)&yo[(size_t)row * DIM + c] = p;
    }
}

// ---------------- bf16 wmma GEMM core, 128x96 tile, 8 warps (32x48 each) ------
template<bool RESID>
__device__ __forceinline__ void gemm_core(
        const bf16* __restrict__ A, const bf16* __restrict__ W,
        const float* __restrict__ bias, const float* __restrict__ resid,
        void* __restrict__ Cout, int M, int N, int K,
        int row0, int col0, bool outbf, char* sraw)
{
    constexpr int BM = 128, BK = 32;
    constexpr int AP = 40, BP = 104, CP = 100;
    bf16* As = (bf16*)sraw;
    bf16* Bs = (bf16*)(sraw + 2 * BM * AP * (int)sizeof(bf16));
    float* Cs = (float*)sraw;

    int tid = threadIdx.x;
    int wid = tid >> 5, wm = wid & 3, wn = wid >> 2;

    const int arow = tid >> 2, acq = (tid & 3) * 8;
    const int br0 = tid / 12,  bc0 = (tid % 12) * 8;
    const int idx2 = tid + 256;
    const int br1 = idx2 / 12, bc1 = (idx2 % 12) * 8;
    const bool haveB1 = (tid < 128);
    const uint4 z4 = make_uint4(0, 0, 0, 0);

    uint4 ra0, ra1, rb0, rb1;
    #define LDG_TILE(K0) do { \
        int r0_ = row0 + arow, r1_ = row0 + arow + 64; \
        ra0 = (r0_ < M) ? *(const uint4*)&A[(size_t)r0_ * K + (K0) + acq] : z4; \
        ra1 = (r1_ < M) ? *(const uint4*)&A[(size_t)r1_ * K + (K0) + acq] : z4; \
        rb0 = *(const uint4*)&W[(size_t)((K0) + br0) * N + col0 + bc0]; \
        if (haveB1) rb1 = *(const uint4*)&W[(size_t)((K0) + br1) * N + col0 + bc1]; \
    } while (0)
    #define STS_TILE(BUF) do { \
        *(uint4*)&As[(BUF) * BM * AP + arow * AP + acq]        = ra0; \
        *(uint4*)&As[(BUF) * BM * AP + (arow + 64) * AP + acq] = ra1; \
        *(uint4*)&Bs[(BUF) * BK * BP + br0 * BP + bc0]         = rb0; \
        if (haveB1) *(uint4*)&Bs[(BUF) * BK * BP + br1 * BP + bc1] = rb1; \
    } while (0)

    wmma::fragment<wmma::accumulator, 16, 16, 16, float> acc[2][3];
    #pragma unroll
    for (int i = 0; i < 2; i++)
        #pragma unroll
        for (int j = 0; j < 3; j++)
            wmma::fill_fragment(acc[i][j], 0.f);

    const int nk = K / BK;
    LDG_TILE(0);
    STS_TILE(0);
    __syncthreads();

    for (int t = 0; t < nk; t++) {
        if (t + 1 < nk) LDG_TILE((t + 1) * BK);
        const bf16* Ab = As + (t & 1) * BM * AP;
        const bf16* Bb = Bs + (t & 1) * BK * BP;
        #pragma unroll
        for (int ks = 0; ks < 2; ks++) {
            wmma::fragment<wmma::matrix_a, 16, 16, 16, bf16, wmma::row_major> fa[2];
            wmma::fragment<wmma::matrix_b, 16, 16, 16, bf16, wmma::row_major> fb[3];
            #pragma unroll
            for (int i = 0; i < 2; i++)
                wmma::load_matrix_sync(fa[i], &Ab[(wm * 32 + i * 16) * AP + ks * 16], AP);
            #pragma unroll
            for (int j = 0; j < 3; j++)
                wmma::load_matrix_sync(fb[j], &Bb[(ks * 16) * BP + wn * 48 + j * 16], BP);
            #pragma unroll
            for (int i = 0; i < 2; i++)
                #pragma unroll
                for (int j = 0; j < 3; j++)
                    wmma::mma_sync(acc[i][j], fa[i], fb[j], acc[i][j]);
        }
        if (t + 1 < nk) STS_TILE((t + 1) & 1);
        __syncthreads();
    }

    #pragma unroll
    for (int i = 0; i < 2; i++)
        #pragma unroll
        for (int j = 0; j < 3; j++)
            wmma::store_matrix_sync(&Cs[(wm * 32 + i * 16) * CP + wn * 48 + j * 16],
                                    acc[i][j], CP, wmma::mem_row_major);
    __syncthreads();
    #pragma unroll
    for (int it = 0; it < 12; it++) {
        int idx = tid + it * 256;
        int r = idx / 24, cq = (idx % 24) * 4;
        int gr = row0 + r, gc = col0 + cq;
        if (gr < M) {
            float4 v = *(const float4*)&Cs[r * CP + cq];
            float4 bv = *(const float4*)&bias[gc];
            v.x += bv.x; v.y += bv.y; v.z += bv.z; v.w += bv.w;
            if (RESID) {
                float4 rv = *(const float4*)&resid[(size_t)gr * N + gc];
                v.x += rv.x; v.y += rv.y; v.z += rv.z; v.w += rv.w;
            }
            if (outbf) {
                uint2 p;
                p.x = pack_bf16x2(v.x, v.y);
                p.y = pack_bf16x2(v.z, v.w);
                *(uint2*)((bf16*)Cout + (size_t)gr * N + gc) = p;
            } else {
                *(float4*)((float*)Cout + (size_t)gr * N + gc) = v;
            }
        }
    }
    #undef LDG_TILE
    #undef STS_TILE
}
#define GEMM_SMEM 51200

template<bool RESID, bool OUTBF>
__global__ void __launch_bounds__(256, 2) gemm_bf16_kernel(
        const bf16* __restrict__ A, const bf16* __restrict__ W,
        const float* __restrict__ bias, const float* __restrict__ resid,
        void* __restrict__ Cout, int M, int N, int K)
{
    extern __shared__ __align__(16) char sraw[];
    gemm_core<RESID>(A, W, bias, resid, Cout, M, N, K,
                     blockIdx.y * 128, blockIdx.x * 96, OUTBF, sraw);
}

// dual-problem GEMM: blockIdx.x < split -> problem 0 (bf16 out), else problem 1 (fp32 out)
__global__ void __launch_bounds__(256, 2) gemm_dual_kernel(
        const bf16* __restrict__ A0, const bf16* __restrict__ W0,
        const float* __restrict__ b0, void* __restrict__ C0, int N0,
        const bf16* __restrict__ A1, const bf16* __restrict__ W1,
        const float* __restrict__ b1, void* __restrict__ C1, int N1,
        int M, int K, int split)
{
    extern __shared__ __align__(16) char sraw[];
    if ((int)blockIdx.x < split)
        gemm_core<false>(A0, W0, b0, nullptr, C0, M, N0, K,
                         blockIdx.y * 128, blockIdx.x * 96, true, sraw);
    else
        gemm_core<false>(A1, W1, b1, nullptr, C1, M, N1, K,
                         blockIdx.y * 128, (blockIdx.x - split) * 96, false, sraw);
}

// ---------------- deformable sampling v7: smem param tables, no inner shfl ----
// warp = (bq,h). phase 1: lane p<12 builds 4 precombined 16B entries
// {w0, w1, byteoff0, byteoff1} per (point, corner-group). phase 2: per point
// ONE LDS.128 + 2 LDG.128, weights premultiplied, offsets prescaled to bytes.
__global__ void __launch_bounds__(256) deform_kernel(
        const float* __restrict__ offaw,
        const bf16* __restrict__ value, bf16* __restrict__ out)
{
    const unsigned FULL = 0xffffffffu;
    __shared__ __align__(16) float4 s_pt[8][12][4];   // 6 KB
    int wslot = threadIdx.x >> 5;
    int gw   = (blockIdx.x * blockDim.x + threadIdx.x) >> 5;
    int lane = threadIdx.x & 31;
    if (gw >= MROWS * HEADS) return;
    int h  = gw % HEADS;
    int bq = gw / HEADS;
    int q  = bq % NTOK;
    int b  = bq / NTOK;

    // reference point (order d,x,y)
    float rd, rx, ry;
    {
        int S, loc;
        if (q < NHIGH)        { S = 24; loc = q; }
        else if (q < NMIDEND) { S = 12; loc = q - NHIGH; }
        else                  { S = 6;  loc = q - NMIDEND; }
        int d = loc / (S * S), y = (loc / S) % S, x = loc % S;
        float inv = 1.f / (float)S;
        rd = (d + 0.5f) * inv; ry = (y + 0.5f) * inv; rx = (x + 0.5f) * inv;
    }

    // ---- phase 1: lane pp handles point pp; softmax fused; build smem table ----
    {
        int pp = (lane < 12) ? lane : 0;
        float logit = offaw[(size_t)bq * 288 + 216 + h * 12 + pp];
        float lm = (lane < 12) ? logit : -1e30f;
        #pragma unroll
        for (int o = 16; o > 0; o >>= 1) lm = fmaxf(lm, __shfl_xor_sync(FULL, lm, o));
        float e = expf(logit - lm);
        float es = (lane < 12) ? e : 0.f;
        #pragma unroll
        for (int o = 16; o > 0; o >>= 1) es += __shfl_xor_sync(FULL, es, o);
        float a = e / es;

        if (lane < 12) {
            int l = pp >> 2;
            int S  = (l == 0) ? 24 : ((l == 1) ? 12 : 6);
            int st = (l == 0) ? 0  : ((l == 1) ? NHIGH : NMIDEND);
            const float* o = offaw + (size_t)bq * 288 + h * 36 + pp * 3;
            float pd = rd * S + o[0] - 0.5f;
            float px = rx * S + o[1] - 0.5f;
            float py = ry * S + o[2] - 0.5f;
            float fd = floorf(pd), fx = floorf(px), fy = floorf(py);
            int d0 = (int)fd, x0 = (int)fx, y0 = (int)fy;
            int d1 = d0 + 1, x1 = x0 + 1, y1 = y0 + 1;
            float wd1 = pd - fd, wx1 = px - fx, wy1 = py - fy;
            float wD0 = a * (1.f - wd1) * ((d0 >= 0 && d0 < S) ? 1.f : 0.f);
            float wD1 = a * wd1        * ((d1 >= 0 && d1 < S) ? 1.f : 0.f);
            float wY0 = (1.f - wy1) * ((y0 >= 0 && y0 < S) ? 1.f : 0.f);
            float wY1 = wy1         * ((y1 >= 0 && y1 < S) ? 1.f : 0.f);
            float wX0 = (1.f - wx1) * ((x0 >= 0 && x0 < S) ? 1.f : 0.f);
            float wX1 = wx1         * ((x1 >= 0 && x1 < S) ? 1.f : 0.f);
            int cd0 = min(max(d0, 0), S - 1), cd1 = min(max(d1, 0), S - 1);
            int cy0 = min(max(y0, 0), S - 1), cy1 = min(max(y1, 0), S - 1);
            int cx0 = min(max(x0, 0), S - 1);
            int cx1 = min(max(x1, 0), S - 1);
            // byte offsets: element index * DIM rows * 2 bytes = idx * 768
            int c0b = cx0 * (DIM * 2), c1b = cx1 * (DIM * 2);
            int ib[4];
            ib[0] = (st + cd0 * S * S + cy0 * S) * (DIM * 2);
            ib[1] = (st + cd0 * S * S + cy1 * S) * (DIM * 2);
            ib[2] = (st + cd1 * S * S + cy0 * S) * (DIM * 2);
            ib[3] = (st + cd1 * S * S + cy1 * S) * (DIM * 2);
            float wdy[4];
            wdy[0] = wD0 * wY0; wdy[1] = wD0 * wY1;
            wdy[2] = wD1 * wY0; wdy[3] = wD1 * wY1;
            #pragma unroll
            for (int cg = 0; cg < 4; cg++) {
                float4 ent;
                ent.x = wdy[cg] * wX0;
                ent.y = wdy[cg] * wX1;
                ent.z = __int_as_float(ib[cg] + c0b);
                ent.w = __int_as_float(ib[cg] + c1b);
                s_pt[wslot][pp][cg] = ent;
            }
        }
    }
    __syncwarp();

    // ---- phase 2: per point: 1 LDS.128 + 2 LDG.128 ----
    const int cg  = lane >> 3;             // 0..3 = (d,y) corner combo
    const int ch8 = (lane & 7) * 8;        // 8 channels per lane
    const char* vbb = (const char*)(value + (size_t)b * NTOK * DIM + h * HDIM + ch8);

    float a0 = 0.f, a1 = 0.f, a2 = 0.f, a3 = 0.f;
    float a4 = 0.f, a5 = 0.f, a6 = 0.f, a7 = 0.f;
    #pragma unroll
    for (int p = 0; p < 12; p++) {
        float4 ent = s_pt[wslot][p][cg];
        {
            uint4 raw = *(const uint4*)(vbb + __float_as_int(ent.z));
            float w = ent.x;
            float2 va = __bfloat1622float2(*(const __nv_bfloat162*)&raw.x);
            float2 vb2 = __bfloat1622float2(*(const __nv_bfloat162*)&raw.y);
            float2 vc = __bfloat1622float2(*(const __nv_bfloat162*)&raw.z);
            float2 vd = __bfloat1622float2(*(const __nv_bfloat162*)&raw.w);
            a0 += w * va.x;  a1 += w * va.y;
            a2 += w * vb2.x; a3 += w * vb2.y;
            a4 += w * vc.x;  a5 += w * vc.y;
            a6 += w * vd.x;  a7 += w * vd.y;
        }
        {
            uint4 raw = *(const uint4*)(vbb + __float_as_int(ent.w));
            float w = ent.y;
            float2 va = __bfloat1622float2(*(const __nv_bfloat162*)&raw.x);
            float2 vb2 = __bfloat1622float2(*(const __nv_bfloat162*)&raw.y);
            float2 vc = __bfloat1622float2(*(const __nv_bfloat162*)&raw.z);
            float2 vd = __bfloat1622float2(*(const __nv_bfloat162*)&raw.w);
            a0 += w * va.x;  a1 += w * va.y;
            a2 += w * vb2.x; a3 += w * vb2.y;
            a4 += w * vc.x;  a5 += w * vc.y;
            a6 += w * vd.x;  a7 += w * vd.y;
        }
    }
    // reduce across the 4 corner groups: lanes l, l+8, l+16, l+24 share channels
    #pragma unroll
    for (int o = 16; o >= 8; o >>= 1) {
        a0 += __shfl_down_sync(FULL, a0, o);
        a1 += __shfl_down_sync(FULL, a1, o);
        a2 += __shfl_down_sync(FULL, a2, o);
        a3 += __shfl_down_sync(FULL, a3, o);
        a4 += __shfl_down_sync(FULL, a4, o);
        a5 += __shfl_down_sync(FULL, a5, o);
        a6 += __shfl_down_sync(FULL, a6, o);
        a7 += __shfl_down_sync(FULL, a7, o);
    }
    if (lane < 8) {
        uint4 pkt;
        pkt.x = pack_bf16x2(a0, a1);
        pkt.y = pack_bf16x2(a2, a3);
        pkt.z = pack_bf16x2(a4, a5);
        pkt.w = pack_bf16x2(a6, a7);
        *(uint4*)(out + (size_t)bq * DIM + h * HDIM + ch8) = pkt;
    }
}

// ---------------- depthwise 3x3x3 conv + GELU: 48 voxels/block, 8ch/thread ----
__global__ void __launch_bounds__(576) dwconv_gelu_kernel(
        const bf16* __restrict__ x, const float* __restrict__ w,
        const float* __restrict__ bias, bf16* __restrict__ y)
{
    __shared__ float sw[27 * HID];
    int tid = threadIdx.x;                 // 576
    for (int i = tid; i < 27 * HID; i += 576) sw[i] = w[i];
    __syncthreads();

    int c8  = (tid % 12) * 8;
    int vox = tid / 12;
    int vlin = blockIdx.x * 48 + vox;
    int b = vlin / NTOK, v = vlin % NTOK;

    int S, base;
    if (v < NHIGH)        { S = 24; base = 0; }
    else if (v < NMIDEND) { S = 12; base = NHIGH; }
    else                  { S = 6;  base = NMIDEND; }
    int loc = v - base;
    int d = loc / (S * S), yy = (loc / S) % S, xx = loc % S;

    const bf16* xb = x + ((size_t)b * NTOK + base) * HID + c8;
    float4 bv0 = *(const float4*)&bias[c8];
    float4 bv1 = *(const float4*)&bias[c8 + 4];
    float a0 = bv0.x, a1 = bv0.y, a2 = bv0.z, a3 = bv0.w;
    float a4 = bv1.x, a5 = bv1.y, a6 = bv1.z, a7 = bv1.w;
    #pragma unroll
    for (int kd = 0; kd < 3; kd++) {
        int di = d + kd - 1;
        if (di < 0 || di >= S) continue;
        #pragma unroll
        for (int kh = 0; kh < 3; kh++) {
            int yi = yy + kh - 1;
            if (yi < 0 || yi >= S) continue;
            #pragma unroll
            for (int kw = 0; kw < 3; kw++) {
                int xi = xx + kw - 1;
                if (xi < 0 || xi >= S) continue;
                uint4 raw = *(const uint4*)(xb + (size_t)((di * S + yi) * S + xi) * HID);
                float2 va = __bfloat1622float2(*(const __nv_bfloat162*)&raw.x);
                float2 vb2 = __bfloat1622float2(*(const __nv_bfloat162*)&raw.y);
                float2 vc = __bfloat1622float2(*(const __nv_bfloat162*)&raw.z);
                float2 vd = __bfloat1622float2(*(const __nv_bfloat162*)&raw.w);
                const float* wp = &sw[((kd * 3 + kh) * 3 + kw) * HID + c8];
                float4 wv0 = *(const float4*)wp;
                float4 wv1 = *(const float4*)(wp + 4);
                a0 += wv0.x * va.x;  a1 += wv0.y * va.y;
                a2 += wv0.z * vb2.x; a3 += wv0.w * vb2.y;
                a4 += wv1.x * vc.x;  a5 += wv1.y * vc.y;
                a6 += wv1.z * vd.x;  a7 += wv1.w * vd.y;
            }
        }
    }
    const float ISQ2 = 0.70710678118654752f;
    float g0 = 0.5f * a0 * (1.f + erff(a0 * ISQ2));
    float g1 = 0.5f * a1 * (1.f + erff(a1 * ISQ2));
    float g2 = 0.5f * a2 * (1.f + erff(a2 * ISQ2));
    float g3 = 0.5f * a3 * (1.f + erff(a3 * ISQ2));
    float g4 = 0.5f * a4 * (1.f + erff(a4 * ISQ2));
    float g5 = 0.5f * a5 * (1.f + erff(a5 * ISQ2));
    float g6 = 0.5f * a6 * (1.f + erff(a6 * ISQ2));
    float g7 = 0.5f * a7 * (1.f + erff(a7 * ISQ2));
    uint4 pkt;
    pkt.x = pack_bf16x2(g0, g1);
    pkt.y = pack_bf16x2(g2, g3);
    pkt.z = pack_bf16x2(g4, g5);
    pkt.w = pack_bf16x2(g6, g7);
    *(uint4*)(y + ((size_t)b * NTOK + v) * HID + c8) = pkt;
}

// ---------------- launch ----------------
static void* sym_addr(const void* sym) {
    void* p = nullptr;
    cudaGetSymbolAddress(&p, sym);
    return p;
}

extern "C" void kernel_launch(void* const* d_in, const int* in_sizes, int n_in,
                              void* d_out, int out_size)
{
    const float* query = (const float*)d_in[0];
    const float* feat  = (const float*)d_in[2];
    int wb = n_in - 24;
    const float* qnorm_w    = (const float*)d_in[wb + 0];
    const float* qnorm_b    = (const float*)d_in[wb + 1];
    const float* fnorm_w    = (const float*)d_in[wb + 2];
    const float* fnorm_b    = (const float*)d_in[wb + 3];
    const float* ext_qnorm_w= (const float*)d_in[wb + 4];
    const float* ext_qnorm_b= (const float*)d_in[wb + 5];
    const float* ext_fnorm_w= (const float*)d_in[wb + 6];
    const float* ext_fnorm_b= (const float*)d_in[wb + 7];
    const float* ffn_norm_w = (const float*)d_in[wb + 8];
    const float* ffn_norm_b = (const float*)d_in[wb + 9];
    const float* off_w      = (const float*)d_in[wb + 10];
    const float* off_b      = (const float*)d_in[wb + 11];
    const float* aw_w       = (const float*)d_in[wb + 12];
    const float* aw_b       = (const float*)d_in[wb + 13];
    const float* val_w      = (const float*)d_in[wb + 14];
    const float* val_b      = (const float*)d_in[wb + 15];
    const float* out_w      = (const float*)d_in[wb + 16];
    const float* out_b      = (const float*)d_in[wb + 17];
    const float* fc1_w      = (const float*)d_in[wb + 18];
    const float* fc1_b      = (const float*)d_in[wb + 19];
    const float* dw_w       = (const float*)d_in[wb + 20];
    const float* dw_b       = (const float*)d_in[wb + 21];
    const float* fc2_w      = (const float*)d_in[wb + 22];
    const float* fc2_b      = (const float*)d_in[wb + 23];

    float* qn    = (float*)sym_addr(g_qn);
    float* out1  = (float*)sym_addr(g_out1);
    float* offaw = (float*)sym_addr(g_offaw);
    float* bias288 = (float*)sym_addr(g_bias288);
    bf16* aqb    = (bf16*)sym_addr(g_aq_b);
    bf16* afb    = (bf16*)sym_addr(g_af_b);
    bf16* valb   = (bf16*)sym_addr(g_val_b);
    bf16* doutb  = (bf16*)sym_addr(g_dout_b);
    bf16* xfb    = (bf16*)sym_addr(g_xf_b);
    bf16* xgb    = (bf16*)sym_addr(g_xg_b);
    bf16* wbf    = (bf16*)sym_addr(g_wb);
    float* outp  = (float*)d_out;

    cudaFuncSetAttribute(gemm_bf16_kernel<false, true>,  cudaFuncAttributeMaxDynamicSharedMemorySize, GEMM_SMEM);
    cudaFuncSetAttribute(gemm_bf16_kernel<false, false>, cudaFuncAttributeMaxDynamicSharedMemorySize, GEMM_SMEM);
    cudaFuncSetAttribute(gemm_bf16_kernel<true,  false>, cudaFuncAttributeMaxDynamicSharedMemorySize, GEMM_SMEM);
    cudaFuncSetAttribute(gemm_dual_kernel, cudaFuncAttributeMaxDynamicSharedMemorySize, GEMM_SMEM);

    const int M = MROWS;
    int gy = (M + 127) / 128;
    int grow = (M + 7) / 8;

    // 0) weights -> bf16 (+ interleave off/aw, + combined bias build)
    cvt_weights_kernel<<<468, 256>>>(val_w, off_w, aw_w, out_w, fc1_w, fc2_w,
                                     off_b, aw_b, wbf, bias288);
    // 1) q build + LN chain (warp per row)
    prep_kernel<<<grow, 256>>>(query, feat, qnorm_w, qnorm_b, fnorm_w, fnorm_b,
                               ext_qnorm_w, ext_qnorm_b, ext_fnorm_w, ext_fnorm_b,
                               qn, aqb, afb);
    // 2+3) fused: value = af @ val_w + val_b (bf16) AND offaw = aq @ [off|aw]_w + bias (fp32)
    gemm_dual_kernel<<<dim3(7, gy), 256, GEMM_SMEM>>>(
        afb, wbf + WOFF_VAL, val_b, valb, 384,
        aqb, wbf + WOFF_OFFAW, bias288, offaw, 288,
        M, 384, 4);
    // 4) deformable sampling (softmax fused)
    {
        int warps = MROWS * HEADS;
        int blocks = (warps + 7) / 8;
        deform_kernel<<<blocks, 256>>>(offaw, valb, doutb);
    }
    // 5) out1 = qn + dout @ out_w + out_b (fp32)
    gemm_bf16_kernel<true, false><<<dim3(4, gy), 256, GEMM_SMEM>>>(doutb, wbf + WOFF_OUT, out_b, qn, out1, M, 384, 384);
    // 6) t = LN(out1, ffn_norm) -> bf16
    ln_kernel<<<grow, 256>>>(out1, ffn_norm_w, ffn_norm_b, aqb);
    // 7) x = t @ fc1_w + fc1_b  (bf16 out)
    gemm_bf16_kernel<false, true><<<dim3(1, gy), 256, GEMM_SMEM>>>(aqb, wbf + WOFF_FC1, fc1_b, nullptr, xfb, M, 96, 384);
    // 8) depthwise conv + GELU (bf16 out, 48 voxels/block)
    dwconv_gelu_kernel<<<MROWS / 48, 576>>>(xfb, dw_w, dw_b, xgb);
    // 9) out = out1 + xg @ fc2_w + fc2_b (fp32)
    gemm_bf16_kernel<true, false><<<dim3(4, gy), 256, GEMM_SMEM>>>(xgb, wbf + WOFF_FC2, fc2_b, out1, outp, M, 384, 96);
}

// round 15
// speedup vs baseline: 3.9347x; 1.0397x over previous
#include <cstdint>
#include <cstddef>
#include <cuda_runtime.h>
#include <cuda_bf16.h>
#include <mma.h>
#include <math.h>

using namespace nvcuda;
typedef __nv_bfloat16 bf16;

// ---------------- problem constants ----------------
#define DIM     384
#define HEADS   6
#define HDIM    64
#define HID     96
#define BB      2
#define NMID    1728
#define NTOK    15768
#define NHIGH   13824
#define NMIDEND 15552
#define MROWS   (BB*NTOK)         // 31536

// weight arena offsets (bf16 elements), [K,N] layout (off+aw interleaved to N=288)
#define WOFF_VAL   0
#define WOFF_OFFAW 147456
#define WOFF_OUT   258048
#define WOFF_FC1   405504
#define WOFF_FC2   442368
#define WTOTAL     479232

// ---------------- scratch (device globals) ----------------
__device__ float g_qn   [(size_t)MROWS*DIM];
__device__ float g_out1 [(size_t)MROWS*DIM];
__device__ float g_offaw[(size_t)MROWS*288];
__device__ float g_bias288[288];
__device__ bf16  g_aq_b [(size_t)MROWS*DIM];
__device__ bf16  g_af_b [(size_t)MROWS*DIM];
__device__ bf16  g_val_b[(size_t)MROWS*DIM];
__device__ bf16  g_dout_b[(size_t)MROWS*DIM];
__device__ bf16  g_xf_b [(size_t)MROWS*HID];
__device__ bf16  g_xg_b [(size_t)MROWS*HID];
__device__ bf16  g_wb   [WTOTAL];

// ---------------- helpers ----------------
__device__ __forceinline__ float2 warp_sum2(float a, float b) {
    #pragma unroll
    for (int o = 16; o > 0; o >>= 1) {
        a += __shfl_xor_sync(0xffffffffu, a, o);
        b += __shfl_xor_sync(0xffffffffu, b, o);
    }
    return make_float2(a, b);
}
__device__ __forceinline__ uint32_t pack_bf16x2(float a, float b) {
    __nv_bfloat162 p = __floats2bfloat162_rn(a, b);
    return *reinterpret_cast<uint32_t*>(&p);
}
// packed f32x2 helpers (sm_100-family base PTX)
__device__ __forceinline__ unsigned long long pack2_from_bf16x2(uint32_t raw) {
    uint32_t lo = raw << 16;
    uint32_t hi = raw & 0xffff0000u;
    unsigned long long v;
    asm("mov.b64 %0, {%1, %2};" : "=l"(v) : "r"(lo), "r"(hi));
    return v;
}
__device__ __forceinline__ unsigned long long dup_f32x2(float w) {
    uint32_t wb_ = __float_as_uint(w);
    unsigned long long v;
    asm("mov.b64 %0, {%1, %2};" : "=l"(v) : "r"(wb_), "r"(wb_));
    return v;
}
__device__ __forceinline__ void fma_f32x2(unsigned long long& acc,
                                          unsigned long long a, unsigned long long b) {
    asm("fma.rn.f32x2 %0, %1, %2, %0;" : "+l"(acc) : "l"(a), "l"(b));
}
__device__ __forceinline__ float2 unpack_f32x2(unsigned long long v) {
    float x, y;
    asm("mov.b64 {%0, %1}, %2;" : "=f"(x), "=f"(y) : "l"(v));
    return make_float2(x, y);
}

// ---------------- K1: build q (+feat), fused LN chain + weight convert ----------
__global__ void __launch_bounds__(256) prep_kernel(
        const float* __restrict__ query, const float* __restrict__ feat,
        const float* __restrict__ qw, const float* __restrict__ qb,
        const float* __restrict__ fw, const float* __restrict__ fb,
        const float* __restrict__ eqw, const float* __restrict__ eqb,
        const float* __restrict__ efw, const float* __restrict__ efb,
        float* __restrict__ qn_o, bf16* __restrict__ aq_o, bf16* __restrict__ af_o,
        const float* __restrict__ vw, const float* __restrict__ ow,
        const float* __restrict__ aww, const float* __restrict__ outw,
        const float* __restrict__ f1w, const float* __restrict__ f2w,
        const float* __restrict__ offb, const float* __restrict__ awb,
        bf16* __restrict__ wdst, float* __restrict__ bias288)
{
    // weight convert tail (grid-stride over whole grid; <=1 iter/thread)
    {
        int gid = blockIdx.x * 256 + threadIdx.x;
        if (gid < 288) bias288[gid] = (gid < 216) ? offb[gid] : awb[gid - 216];
        int stride = gridDim.x * 256;
        for (int i = gid; i < WTOTAL; i += stride) {
            float v;
            if      (i < WOFF_OFFAW) v = vw[i];
            else if (i < WOFF_OUT) {
                int rel = i - WOFF_OFFAW;
                int k = rel / 288, j = rel % 288;
                v = (j < 216) ? ow[k * 216 + j] : aww[k * 72 + (j - 216)];
            }
            else if (i < WOFF_FC1) v = outw[i - WOFF_OUT];
            else if (i < WOFF_FC2) v = f1w[i - WOFF_FC1];
            else                   v = f2w[i - WOFF_FC2];
            wdst[i] = __float2bfloat16(v);
        }
    }

    int row = blockIdx.x * 8 + (threadIdx.x >> 5);
    if (row >= MROWS) return;
    int lane = threadIdx.x & 31;
    int b = row / NTOK, t = row % NTOK;

    float x[12];
    float s = 0.f, ss = 0.f;
    const bool addf = (t >= NHIGH && t < NMIDEND);
    const float* qrow = query + (size_t)row * DIM;
    const float* frow = addf ? feat + ((size_t)b * NMID + (t - NHIGH)) * DIM : nullptr;
    #pragma unroll
    for (int i = 0; i < 3; i++) {
        int c = (lane + i * 32) * 4;
        float4 v = *(const float4*)&qrow[c];
        if (addf) {
            float4 f = *(const float4*)&frow[c];
            v.x += f.x; v.y += f.y; v.z += f.z; v.w += f.w;
        }
        x[i*4+0] = v.x; x[i*4+1] = v.y; x[i*4+2] = v.z; x[i*4+3] = v.w;
        s += v.x + v.y + v.z + v.w;
        ss += v.x*v.x + v.y*v.y + v.z*v.z + v.w*v.w;
    }
    float2 r = warp_sum2(s, ss);
    float m  = r.x * (1.f / DIM);
    float rs = rsqrtf(r.y * (1.f / DIM) - m * m + 1e-6f);

    float qv[12], fv[12];
    float s1 = 0.f, ss1 = 0.f, s2 = 0.f, ss2 = 0.f;
    #pragma unroll
    for (int i = 0; i < 3; i++) {
        int c = (lane + i * 32) * 4;
        float4 qwv = *(const float4*)&qw[c];
        float4 qbv = *(const float4*)&qb[c];
        float4 fwv = *(const float4*)&fw[c];
        float4 fbv = *(const float4*)&fb[c];
        float4 o;
        #pragma unroll
        for (int j = 0; j < 4; j++) {
            float xn = (x[i*4+j] - m) * rs;
            float qq = xn * ((&qwv.x)[j]) + ((&qbv.x)[j]);
            float ff = xn * ((&fwv.x)[j]) + ((&fbv.x)[j]);
            qv[i*4+j] = qq; fv[i*4+j] = ff;
            (&o.x)[j] = qq;
            s1 += qq; ss1 += qq*qq;
            s2 += ff; ss2 += ff*ff;
        }
        *(float4*)&qn_o[(size_t)row * DIM + c] = o;
    }
    float2 r1 = warp_sum2(s1, ss1);
    float m1  = r1.x * (1.f / DIM);
    float rs1 = rsqrtf(r1.y * (1.f / DIM) - m1 * m1 + 1e-6f);
    float2 r2 = warp_sum2(s2, ss2);
    float m2  = r2.x * (1.f / DIM);
    float rs2 = rsqrtf(r2.y * (1.f / DIM) - m2 * m2 + 1e-6f);
    #pragma unroll
    for (int i = 0; i < 3; i++) {
        int c = (lane + i * 32) * 4;
        float4 ewv = *(const float4*)&eqw[c];
        float4 ebv = *(const float4*)&eqb[c];
        float4 fwv = *(const float4*)&efw[c];
        float4 fbv = *(const float4*)&efb[c];
        float aqv[4], afv[4];
        #pragma unroll
        for (int j = 0; j < 4; j++) {
            aqv[j] = (qv[i*4+j] - m1) * rs1 * ((&ewv.x)[j]) + ((&ebv.x)[j]);
            afv[j] = (fv[i*4+j] - m2) * rs2 * ((&fwv.x)[j]) + ((&fbv.x)[j]);
        }
        uint2 pa, pf;
        pa.x = pack_bf16x2(aqv[0], aqv[1]); pa.y = pack_bf16x2(aqv[2], aqv[3]);
        pf.x = pack_bf16x2(afv[0], afv[1]); pf.y = pack_bf16x2(afv[2], afv[3]);
        *(uint2*)&aq_o[(size_t)row * DIM + c] = pa;
        *(uint2*)&af_o[(size_t)row * DIM + c] = pf;
    }
}

// ---------------- generic LN (fp32 in -> bf16 out) — warp per row, float4 -----
__global__ void __launch_bounds__(256) ln_kernel(
        const float* __restrict__ xin, const float* __restrict__ w,
        const float* __restrict__ bws, bf16* __restrict__ yo)
{
    int row = blockIdx.x * 8 + (threadIdx.x >> 5);
    if (row >= MROWS) return;
    int lane = threadIdx.x & 31;
    float x[12]; float s = 0.f, ss = 0.f;
    const float* xr = xin + (size_t)row * DIM;
    #pragma unroll
    for (int i = 0; i < 3; i++) {
        int c = (lane + i * 32) * 4;
        float4 v = *(const float4*)&xr[c];
        x[i*4+0] = v.x; x[i*4+1] = v.y; x[i*4+2] = v.z; x[i*4+3] = v.w;
        s += v.x + v.y + v.z + v.w;
        ss += v.x*v.x + v.y*v.y + v.z*v.z + v.w*v.w;
    }
    float2 r = warp_sum2(s, ss);
    float m  = r.x * (1.f / DIM);
    float rs = rsqrtf(r.y * (1.f / DIM) - m * m + 1e-6f);
    #pragma unroll
    for (int i = 0; i < 3; i++) {
        int c = (lane + i * 32) * 4;
        float4 wv = *(const float4*)&w[c];
        float4 bv = *(const float4*)&bws[c];
        float y0 = (x[i*4+0] - m) * rs * wv.x + bv.x;
        float y1 = (x[i*4+1] - m) * rs * wv.y + bv.y;
        float y2 = (x[i*4+2] - m) * rs * wv.z + bv.z;
        float y3 = (x[i*4+3] - m) * rs * wv.w + bv.w;
        uint2 p;
        p.x = pack_bf16x2(y0, y1); p.y = pack_bf16x2(y2, y3);
        *(uint2*)&yo[(size_t)row * DIM + c] = p;
    }
}

// ---------------- bf16 wmma GEMM core, 128x96 tile, 8 warps (32x48 each) ------
template<bool RESID>
__device__ __forceinline__ void gemm_core(
        const bf16* __restrict__ A, const bf16* __restrict__ W,
        const float* __restrict__ bias, const float* __restrict__ resid,
        void* __restrict__ Cout, int M, int N, int K,
        int row0, int col0, bool outbf, char* sraw)
{
    constexpr int BM = 128, BK = 32;
    constexpr int AP = 40, BP = 104, CP = 100;
    bf16* As = (bf16*)sraw;
    bf16* Bs = (bf16*)(sraw + 2 * BM * AP * (int)sizeof(bf16));
    float* Cs = (float*)sraw;

    int tid = threadIdx.x;
    int wid = tid >> 5, wm = wid & 3, wn = wid >> 2;

    const int arow = tid >> 2, acq = (tid & 3) * 8;
    const int br0 = tid / 12,  bc0 = (tid % 12) * 8;
    const int idx2 = tid + 256;
    const int br1 = idx2 / 12, bc1 = (idx2 % 12) * 8;
    const bool haveB1 = (tid < 128);
    const uint4 z4 = make_uint4(0, 0, 0, 0);

    uint4 ra0, ra1, rb0, rb1;
    #define LDG_TILE(K0) do { \
        int r0_ = row0 + arow, r1_ = row0 + arow + 64; \
        ra0 = (r0_ < M) ? *(const uint4*)&A[(size_t)r0_ * K + (K0) + acq] : z4; \
        ra1 = (r1_ < M) ? *(const uint4*)&A[(size_t)r1_ * K + (K0) + acq] : z4; \
        rb0 = *(const uint4*)&W[(size_t)((K0) + br0) * N + col0 + bc0]; \
        if (haveB1) rb1 = *(const uint4*)&W[(size_t)((K0) + br1) * N + col0 + bc1]; \
    } while (0)
    #define STS_TILE(BUF) do { \
        *(uint4*)&As[(BUF) * BM * AP + arow * AP + acq]        = ra0; \
        *(uint4*)&As[(BUF) * BM * AP + (arow + 64) * AP + acq] = ra1; \
        *(uint4*)&Bs[(BUF) * BK * BP + br0 * BP + bc0]         = rb0; \
        if (haveB1) *(uint4*)&Bs[(BUF) * BK * BP + br1 * BP + bc1] = rb1; \
    } while (0)

    wmma::fragment<wmma::accumulator, 16, 16, 16, float> acc[2][3];
    #pragma unroll
    for (int i = 0; i < 2; i++)
        #pragma unroll
        for (int j = 0; j < 3; j++)
            wmma::fill_fragment(acc[i][j], 0.f);

    const int nk = K / BK;
    LDG_TILE(0);
    STS_TILE(0);
    __syncthreads();

    for (int t = 0; t < nk; t++) {
        if (t + 1 < nk) LDG_TILE((t + 1) * BK);
        const bf16* Ab = As + (t & 1) * BM * AP;
        const bf16* Bb = Bs + (t & 1) * BK * BP;
        #pragma unroll
        for (int ks = 0; ks < 2; ks++) {
            wmma::fragment<wmma::matrix_a, 16, 16, 16, bf16, wmma::row_major> fa[2];
            wmma::fragment<wmma::matrix_b, 16, 16, 16, bf16, wmma::row_major> fb[3];
            #pragma unroll
            for (int i = 0; i < 2; i++)
                wmma::load_matrix_sync(fa[i], &Ab[(wm * 32 + i * 16) * AP + ks * 16], AP);
            #pragma unroll
            for (int j = 0; j < 3; j++)
                wmma::load_matrix_sync(fb[j], &Bb[(ks * 16) * BP + wn * 48 + j * 16], BP);
            #pragma unroll
            for (int i = 0; i < 2; i++)
                #pragma unroll
                for (int j = 0; j < 3; j++)
                    wmma::mma_sync(acc[i][j], fa[i], fb[j], acc[i][j]);
        }
        if (t + 1 < nk) STS_TILE((t + 1) & 1);
        __syncthreads();
    }

    #pragma unroll
    for (int i = 0; i < 2; i++)
        #pragma unroll
        for (int j = 0; j < 3; j++)
            wmma::store_matrix_sync(&Cs[(wm * 32 + i * 16) * CP + wn * 48 + j * 16],
                                    acc[i][j], CP, wmma::mem_row_major);
    __syncthreads();
    #pragma unroll
    for (int it = 0; it < 12; it++) {
        int idx = tid + it * 256;
        int r = idx / 24, cq = (idx % 24) * 4;
        int gr = row0 + r, gc = col0 + cq;
        if (gr < M) {
            float4 v = *(const float4*)&Cs[r * CP + cq];
            float4 bv = *(const float4*)&bias[gc];
            v.x += bv.x; v.y += bv.y; v.z += bv.z; v.w += bv.w;
            if (RESID) {
                float4 rv = *(const float4*)&resid[(size_t)gr * N + gc];
                v.x += rv.x; v.y += rv.y; v.z += rv.z; v.w += rv.w;
            }
            if (outbf) {
                uint2 p;
                p.x = pack_bf16x2(v.x, v.y);
                p.y = pack_bf16x2(v.z, v.w);
                *(uint2*)((bf16*)Cout + (size_t)gr * N + gc) = p;
            } else {
                *(float4*)((float*)Cout + (size_t)gr * N + gc) = v;
            }
        }
    }
    #undef LDG_TILE
    #undef STS_TILE
}
#define GEMM_SMEM 51200

template<bool RESID, bool OUTBF>
__global__ void __launch_bounds__(256, 2) gemm_bf16_kernel(
        const bf16* __restrict__ A, const bf16* __restrict__ W,
        const float* __restrict__ bias, const float* __restrict__ resid,
        void* __restrict__ Cout, int M, int N, int K)
{
    extern __shared__ __align__(16) char sraw[];
    gemm_core<RESID>(A, W, bias, resid, Cout, M, N, K,
                     blockIdx.y * 128, blockIdx.x * 96, OUTBF, sraw);
}

// dual-problem GEMM: blockIdx.x < split -> problem 0 (bf16 out), else problem 1 (fp32 out)
__global__ void __launch_bounds__(256, 2) gemm_dual_kernel(
        const bf16* __restrict__ A0, const bf16* __restrict__ W0,
        const float* __restrict__ b0, void* __restrict__ C0, int N0,
        const bf16* __restrict__ A1, const bf16* __restrict__ W1,
        const float* __restrict__ b1, void* __restrict__ C1, int N1,
        int M, int K, int split)
{
    extern __shared__ __align__(16) char sraw[];
    if ((int)blockIdx.x < split)
        gemm_core<false>(A0, W0, b0, nullptr, C0, M, N0, K,
                         blockIdx.y * 128, blockIdx.x * 96, true, sraw);
    else
        gemm_core<false>(A1, W1, b1, nullptr, C1, M, N1, K,
                         blockIdx.y * 128, (blockIdx.x - split) * 96, false, sraw);
}

// ---------------- deformable sampling v8: smem tables + packed f32x2 FMA ------
__global__ void __launch_bounds__(256) deform_kernel(
        const float* __restrict__ offaw,
        const bf16* __restrict__ value, bf16* __restrict__ out)
{
    const unsigned FULL = 0xffffffffu;
    __shared__ __align__(16) float4 s_pt[8][12][4];   // 6 KB
    int wslot = threadIdx.x >> 5;
    int gw   = (blockIdx.x * blockDim.x + threadIdx.x) >> 5;
    int lane = threadIdx.x & 31;
    if (gw >= MROWS * HEADS) return;
    int h  = gw % HEADS;
    int bq = gw / HEADS;
    int q  = bq % NTOK;
    int b  = bq / NTOK;

    float rd, rx, ry;
    {
        int S, loc;
        if (q < NHIGH)        { S = 24; loc = q; }
        else if (q < NMIDEND) { S = 12; loc = q - NHIGH; }
        else                  { S = 6;  loc = q - NMIDEND; }
        int d = loc / (S * S), y = (loc / S) % S, x = loc % S;
        float inv = 1.f / (float)S;
        rd = (d + 0.5f) * inv; ry = (y + 0.5f) * inv; rx = (x + 0.5f) * inv;
    }

    // ---- phase 1: lane pp handles point pp; softmax fused; build smem table ----
    {
        int pp = (lane < 12) ? lane : 0;
        float logit = offaw[(size_t)bq * 288 + 216 + h * 12 + pp];
        float lm = (lane < 12) ? logit : -1e30f;
        #pragma unroll
        for (int o = 16; o > 0; o >>= 1) lm = fmaxf(lm, __shfl_xor_sync(FULL, lm, o));
        float e = expf(logit - lm);
        float es = (lane < 12) ? e : 0.f;
        #pragma unroll
        for (int o = 16; o > 0; o >>= 1) es += __shfl_xor_sync(FULL, es, o);
        float a = e / es;

        if (lane < 12) {
            int l = pp >> 2;
            int S  = (l == 0) ? 24 : ((l == 1) ? 12 : 6);
            int st = (l == 0) ? 0  : ((l == 1) ? NHIGH : NMIDEND);
            const float* o = offaw + (size_t)bq * 288 + h * 36 + pp * 3;
            float pd = rd * S + o[0] - 0.5f;
            float px = rx * S + o[1] - 0.5f;
            float py = ry * S + o[2] - 0.5f;
            float fd = floorf(pd), fx = floorf(px), fy = floorf(py);
            int d0 = (int)fd, x0 = (int)fx, y0 = (int)fy;
            int d1 = d0 + 1, x1 = x0 + 1, y1 = y0 + 1;
            float wd1 = pd - fd, wx1 = px - fx, wy1 = py - fy;
            float wD0 = a * (1.f - wd1) * ((d0 >= 0 && d0 < S) ? 1.f : 0.f);
            float wD1 = a * wd1        * ((d1 >= 0 && d1 < S) ? 1.f : 0.f);
            float wY0 = (1.f - wy1) * ((y0 >= 0 && y0 < S) ? 1.f : 0.f);
            float wY1 = wy1         * ((y1 >= 0 && y1 < S) ? 1.f : 0.f);
            float wX0 = (1.f - wx1) * ((x0 >= 0 && x0 < S) ? 1.f : 0.f);
            float wX1 = wx1         * ((x1 >= 0 && x1 < S) ? 1.f : 0.f);
            int cd0 = min(max(d0, 0), S - 1), cd1 = min(max(d1, 0), S - 1);
            int cy0 = min(max(y0, 0), S - 1), cy1 = min(max(y1, 0), S - 1);
            int cx0 = min(max(x0, 0), S - 1);
            int cx1 = min(max(x1, 0), S - 1);
            int c0b = cx0 * (DIM * 2), c1b = cx1 * (DIM * 2);
            int ib[4];
            ib[0] = (st + cd0 * S * S + cy0 * S) * (DIM * 2);
            ib[1] = (st + cd0 * S * S + cy1 * S) * (DIM * 2);
            ib[2] = (st + cd1 * S * S + cy0 * S) * (DIM * 2);
            ib[3] = (st + cd1 * S * S + cy1 * S) * (DIM * 2);
            float wdy[4];
            wdy[0] = wD0 * wY0; wdy[1] = wD0 * wY1;
            wdy[2] = wD1 * wY0; wdy[3] = wD1 * wY1;
            #pragma unroll
            for (int cg = 0; cg < 4; cg++) {
                float4 ent;
                ent.x = wdy[cg] * wX0;
                ent.y = wdy[cg] * wX1;
                ent.z = __int_as_float(ib[cg] + c0b);
                ent.w = __int_as_float(ib[cg] + c1b);
                s_pt[wslot][pp][cg] = ent;
            }
        }
    }
    __syncwarp();

    // ---- phase 2: per point: 1 LDS.128 + 2 LDG.128, packed f32x2 FMA ----
    const int cg  = lane >> 3;
    const int ch8 = (lane & 7) * 8;
    const char* vbb = (const char*)(value + (size_t)b * NTOK * DIM + h * HDIM + ch8);

    unsigned long long a01 = 0ull, a23 = 0ull, a45 = 0ull, a67 = 0ull;
    #pragma unroll
    for (int p = 0; p < 12; p++) {
        float4 ent = s_pt[wslot][p][cg];
        {
            uint4 raw = *(const uint4*)(vbb + __float_as_int(ent.z));
            unsigned long long w2 = dup_f32x2(ent.x);
            fma_f32x2(a01, pack2_from_bf16x2(raw.x), w2);
            fma_f32x2(a23, pack2_from_bf16x2(raw.y), w2);
            fma_f32x2(a45, pack2_from_bf16x2(raw.z), w2);
            fma_f32x2(a67, pack2_from_bf16x2(raw.w), w2);
        }
        {
            uint4 raw = *(const uint4*)(vbb + __float_as_int(ent.w));
            unsigned long long w2 = dup_f32x2(ent.y);
            fma_f32x2(a01, pack2_from_bf16x2(raw.x), w2);
            fma_f32x2(a23, pack2_from_bf16x2(raw.y), w2);
            fma_f32x2(a45, pack2_from_bf16x2(raw.z), w2);
            fma_f32x2(a67, pack2_from_bf16x2(raw.w), w2);
        }
    }
    float2 p01 = unpack_f32x2(a01);
    float2 p23 = unpack_f32x2(a23);
    float2 p45 = unpack_f32x2(a45);
    float2 p67 = unpack_f32x2(a67);
    float a0 = p01.x, a1 = p01.y, a2 = p23.x, a3 = p23.y;
    float a4 = p45.x, a5 = p45.y, a6 = p67.x, a7 = p67.y;
    #pragma unroll
    for (int o = 16; o >= 8; o >>= 1) {
        a0 += __shfl_down_sync(FULL, a0, o);
        a1 += __shfl_down_sync(FULL, a1, o);
        a2 += __shfl_down_sync(FULL, a2, o);
        a3 += __shfl_down_sync(FULL, a3, o);
        a4 += __shfl_down_sync(FULL, a4, o);
        a5 += __shfl_down_sync(FULL, a5, o);
        a6 += __shfl_down_sync(FULL, a6, o);
        a7 += __shfl_down_sync(FULL, a7, o);
    }
    if (lane < 8) {
        uint4 pkt;
        pkt.x = pack_bf16x2(a0, a1);
        pkt.y = pack_bf16x2(a2, a3);
        pkt.z = pack_bf16x2(a4, a5);
        pkt.w = pack_bf16x2(a6, a7);
        *(uint4*)(out + (size_t)bq * DIM + h * HDIM + ch8) = pkt;
    }
}

// ---------------- depthwise 3x3x3 conv + GELU: 48 voxels/block, 8ch/thread ----
__global__ void __launch_bounds__(576) dwconv_gelu_kernel(
        const bf16* __restrict__ x, const float* __restrict__ w,
        const float* __restrict__ bias, bf16* __restrict__ y)
{
    __shared__ float sw[27 * HID];
    int tid = threadIdx.x;                 // 576
    for (int i = tid; i < 27 * HID; i += 576) sw[i] = w[i];
    __syncthreads();

    int c8  = (tid % 12) * 8;
    int vox = tid / 12;
    int vlin = blockIdx.x * 48 + vox;
    int b = vlin / NTOK, v = vlin % NTOK;

    int S, base;
    if (v < NHIGH)        { S = 24; base = 0; }
    else if (v < NMIDEND) { S = 12; base = NHIGH; }
    else                  { S = 6;  base = NMIDEND; }
    int loc = v - base;
    int d = loc / (S * S), yy = (loc / S) % S, xx = loc % S;

    const bf16* xb = x + ((size_t)b * NTOK + base) * HID + c8;
    float4 bv0 = *(const float4*)&bias[c8];
    float4 bv1 = *(const float4*)&bias[c8 + 4];
    float a0 = bv0.x, a1 = bv0.y, a2 = bv0.z, a3 = bv0.w;
    float a4 = bv1.x, a5 = bv1.y, a6 = bv1.z, a7 = bv1.w;
    #pragma unroll
    for (int kd = 0; kd < 3; kd++) {
        int di = d + kd - 1;
        if (di < 0 || di >= S) continue;
        #pragma unroll
        for (int kh = 0; kh < 3; kh++) {
            int yi = yy + kh - 1;
            if (yi < 0 || yi >= S) continue;
            #pragma unroll
            for (int kw = 0; kw < 3; kw++) {
                int xi = xx + kw - 1;
                if (xi < 0 || xi >= S) continue;
                uint4 raw = *(const uint4*)(xb + (size_t)((di * S + yi) * S + xi) * HID);
                float2 va = __bfloat1622float2(*(const __nv_bfloat162*)&raw.x);
                float2 vb2 = __bfloat1622float2(*(const __nv_bfloat162*)&raw.y);
                float2 vc = __bfloat1622float2(*(const __nv_bfloat162*)&raw.z);
                float2 vd = __bfloat1622float2(*(const __nv_bfloat162*)&raw.w);
                const float* wp = &sw[((kd * 3 + kh) * 3 + kw) * HID + c8];
                float4 wv0 = *(const float4*)wp;
                float4 wv1 = *(const float4*)(wp + 4);
                a0 += wv0.x * va.x;  a1 += wv0.y * va.y;
                a2 += wv0.z * vb2.x; a3 += wv0.w * vb2.y;
                a4 += wv1.x * vc.x;  a5 += wv1.y * vc.y;
                a6 += wv1.z * vd.x;  a7 += wv1.w * vd.y;
            }
        }
    }
    const float ISQ2 = 0.70710678118654752f;
    float g0 = 0.5f * a0 * (1.f + erff(a0 * ISQ2));
    float g1 = 0.5f * a1 * (1.f + erff(a1 * ISQ2));
    float g2 = 0.5f * a2 * (1.f + erff(a2 * ISQ2));
    float g3 = 0.5f * a3 * (1.f + erff(a3 * ISQ2));
    float g4 = 0.5f * a4 * (1.f + erff(a4 * ISQ2));
    float g5 = 0.5f * a5 * (1.f + erff(a5 * ISQ2));
    float g6 = 0.5f * a6 * (1.f + erff(a6 * ISQ2));
    float g7 = 0.5f * a7 * (1.f + erff(a7 * ISQ2));
    uint4 pkt;
    pkt.x = pack_bf16x2(g0, g1);
    pkt.y = pack_bf16x2(g2, g3);
    pkt.z = pack_bf16x2(g4, g5);
    pkt.w = pack_bf16x2(g6, g7);
    *(uint4*)(y + ((size_t)b * NTOK + v) * HID + c8) = pkt;
}

// ---------------- launch ----------------
static void* sym_addr(const void* sym) {
    void* p = nullptr;
    cudaGetSymbolAddress(&p, sym);
    return p;
}

extern "C" void kernel_launch(void* const* d_in, const int* in_sizes, int n_in,
                              void* d_out, int out_size)
{
    const float* query = (const float*)d_in[0];
    const float* feat  = (const float*)d_in[2];
    int wb = n_in - 24;
    const float* qnorm_w    = (const float*)d_in[wb + 0];
    const float* qnorm_b    = (const float*)d_in[wb + 1];
    const float* fnorm_w    = (const float*)d_in[wb + 2];
    const float* fnorm_b    = (const float*)d_in[wb + 3];
    const float* ext_qnorm_w= (const float*)d_in[wb + 4];
    const float* ext_qnorm_b= (const float*)d_in[wb + 5];
    const float* ext_fnorm_w= (const float*)d_in[wb + 6];
    const float* ext_fnorm_b= (const float*)d_in[wb + 7];
    const float* ffn_norm_w = (const float*)d_in[wb + 8];
    const float* ffn_norm_b = (const float*)d_in[wb + 9];
    const float* off_w      = (const float*)d_in[wb + 10];
    const float* off_b      = (const float*)d_in[wb + 11];
    const float* aw_w       = (const float*)d_in[wb + 12];
    const float* aw_b       = (const float*)d_in[wb + 13];
    const float* val_w      = (const float*)d_in[wb + 14];
    const float* val_b      = (const float*)d_in[wb + 15];
    const float* out_w      = (const float*)d_in[wb + 16];
    const float* out_b      = (const float*)d_in[wb + 17];
    const float* fc1_w      = (const float*)d_in[wb + 18];
    const float* fc1_b      = (const float*)d_in[wb + 19];
    const float* dw_w       = (const float*)d_in[wb + 20];
    const float* dw_b       = (const float*)d_in[wb + 21];
    const float* fc2_w      = (const float*)d_in[wb + 22];
    const float* fc2_b      = (const float*)d_in[wb + 23];

    float* qn    = (float*)sym_addr(g_qn);
    float* out1  = (float*)sym_addr(g_out1);
    float* offaw = (float*)sym_addr(g_offaw);
    float* bias288 = (float*)sym_addr(g_bias288);
    bf16* aqb    = (bf16*)sym_addr(g_aq_b);
    bf16* afb    = (bf16*)sym_addr(g_af_b);
    bf16* valb   = (bf16*)sym_addr(g_val_b);
    bf16* doutb  = (bf16*)sym_addr(g_dout_b);
    bf16* xfb    = (bf16*)sym_addr(g_xf_b);
    bf16* xgb    = (bf16*)sym_addr(g_xg_b);
    bf16* wbf    = (bf16*)sym_addr(g_wb);
    float* outp  = (float*)d_out;

    cudaFuncSetAttribute(gemm_bf16_kernel<false, true>,  cudaFuncAttributeMaxDynamicSharedMemorySize, GEMM_SMEM);
    cudaFuncSetAttribute(gemm_bf16_kernel<false, false>, cudaFuncAttributeMaxDynamicSharedMemorySize, GEMM_SMEM);
    cudaFuncSetAttribute(gemm_bf16_kernel<true,  false>, cudaFuncAttributeMaxDynamicSharedMemorySize, GEMM_SMEM);
    cudaFuncSetAttribute(gemm_dual_kernel, cudaFuncAttributeMaxDynamicSharedMemorySize, GEMM_SMEM);

    const int M = MROWS;
    int gy = (M + 127) / 128;
    int grow = (M + 7) / 8;

    // 1) q build + LN chain (warp per row) + fused weight convert
    prep_kernel<<<grow, 256>>>(query, feat, qnorm_w, qnorm_b, fnorm_w, fnorm_b,
                               ext_qnorm_w, ext_qnorm_b, ext_fnorm_w, ext_fnorm_b,
                               qn, aqb, afb,
                               val_w, off_w, aw_w, out_w, fc1_w, fc2_w,
                               off_b, aw_b, wbf, bias288);
    // 2+3) fused: value = af @ val_w + val_b (bf16) AND offaw = aq @ [off|aw]_w + bias (fp32)
    gemm_dual_kernel<<<dim3(7, gy), 256, GEMM_SMEM>>>(
        afb, wbf + WOFF_VAL, val_b, valb, 384,
        aqb, wbf + WOFF_OFFAW, bias288, offaw, 288,
        M, 384, 4);
    // 4) deformable sampling (softmax fused)
    {
        int warps = MROWS * HEADS;
        int blocks = (warps + 7) / 8;
        deform_kernel<<<blocks, 256>>>(offaw, valb, doutb);
    }
    // 5) out1 = qn + dout @ out_w + out_b (fp32)
    gemm_bf16_kernel<true, false><<<dim3(4, gy), 256, GEMM_SMEM>>>(doutb, wbf + WOFF_OUT, out_b, qn, out1, M, 384, 384);
    // 6) t = LN(out1, ffn_norm) -> bf16
    ln_kernel<<<grow, 256>>>(out1, ffn_norm_w, ffn_norm_b, aqb);
    // 7) x = t @ fc1_w + fc1_b  (bf16 out)
    gemm_bf16_kernel<false, true><<<dim3(1, gy), 256, GEMM_SMEM>>>(aqb, wbf + WOFF_FC1, fc1_b, nullptr, xfb, M, 96, 384);
    // 8) depthwise conv + GELU (bf16 out, 48 voxels/block)
    dwconv_gelu_kernel<<<MROWS / 48, 576>>>(xfb, dw_w, dw_b, xgb);
    // 9) out = out1 + xg @ fc2_w + fc2_b (fp32)
    gemm_bf16_kernel<true, false><<<dim3(4, gy), 256, GEMM_SMEM>>>(xgb, wbf + WOFF_FC2, fc2_b, out1, outp, M, 384, 96);
}